// round 9
// baseline (speedup 1.0000x reference)
#include <cuda_runtime.h>
#include <math.h>
#include <float.h>

// Problem constants
#define NN    6144
#define FEATN 512
#define HIDN  256
#define KMN   50
#define KNNN  20
#define THRF  0.1f
// spatial: exp(-d2 / (2*50^2)) = exp(-d2/5000)
#define INV2SD2 (1.0f/5000.0f)
#define CAPC  128

// ---------------- device scratch (static; no allocation allowed) ----------------
__device__ float g_fn[NN * FEATN];                 // normalized features
__device__ float g_adj[(size_t)NN * NN];           // dense RAW scores (pre-sigmoid)
__device__ float g_xw1[NN * HIDN];                 // X @ W1
__device__ float g_acc[NN * HIDN];                 // GCN1 accumulator -> h
__device__ float g_t1[NN * KMN];                   // h @ W2
__device__ float g_sacc[NN * KMN];                 // GCN2 accumulator
__device__ float g_t2[NN * KMN];                   // adj @ S
__device__ float g_deg[NN];
__device__ float g_dinv[NN];
__device__ int   g_idx[NN * KNNN];
__device__ float g_val[NN * KNNN];                 // sigmoid(adj) of selected top-20
__device__ float g_Ac[KMN * KMN];
__device__ float g_loss;
__device__ float g_E;

// ---------------- 1. normalize rows of features ----------------
__global__ __launch_bounds__(128) void k_prep(const float* __restrict__ X) {
    int row = blockIdx.x, t = threadIdx.x;
    const float* xr = X + row * FEATN;
    float ss = 0.f;
    for (int f = t; f < FEATN; f += 128) { float v = xr[f]; ss += v * v; }
    for (int o = 16; o > 0; o >>= 1) ss += __shfl_down_sync(0xffffffffu, ss, o);
    __shared__ float red[4];
    __shared__ float sinv;
    if ((t & 31) == 0) red[t >> 5] = ss;
    __syncthreads();
    if (t == 0) {
        float s = red[0] + red[1] + red[2] + red[3];
        sinv = 1.0f / fmaxf(sqrtf(s), 1e-12f);
    }
    __syncthreads();
    float inv = sinv;
    for (int f = t; f < FEATN; f += 128) g_fn[row * FEATN + f] = xr[f] * inv;
}

// ---------------- 2. XW1 = X @ W1  (64x64x16 tile, 4x4 micro) ----------------
__global__ __launch_bounds__(256) void k_xw1(const float* __restrict__ X,
                                             const float* __restrict__ W1) {
    __shared__ float As[16][64];
    __shared__ float Bs[16][64];
    int tid = threadIdx.x;
    int bi = blockIdx.y * 64, bj = blockIdx.x * 64;
    int tx = tid & 15, ty = tid >> 4;
    int ar_ = tid >> 2, ac_ = (tid & 3) << 2;
    int br_ = tid >> 4, bc_ = (tid & 15) << 2;
    float acc[4][4];
#pragma unroll
    for (int m = 0; m < 4; m++)
#pragma unroll
        for (int n = 0; n < 4; n++) acc[m][n] = 0.f;

    for (int k0 = 0; k0 < FEATN; k0 += 16) {
        float4 a = *(const float4*)(X + (bi + ar_) * FEATN + k0 + ac_);
        As[ac_ + 0][ar_] = a.x; As[ac_ + 1][ar_] = a.y;
        As[ac_ + 2][ar_] = a.z; As[ac_ + 3][ar_] = a.w;
        float4 b = *(const float4*)(W1 + (k0 + br_) * HIDN + bj + bc_);
        *(float4*)&Bs[br_][bc_] = b;
        __syncthreads();
#pragma unroll
        for (int k = 0; k < 16; k++) {
            float av[4], bv[4];
#pragma unroll
            for (int m = 0; m < 4; m++) av[m] = As[k][ty * 4 + m];
#pragma unroll
            for (int n = 0; n < 4; n++) bv[n] = Bs[k][tx * 4 + n];
#pragma unroll
            for (int m = 0; m < 4; m++)
#pragma unroll
                for (int n = 0; n < 4; n++) acc[m][n] += av[m] * bv[n];
        }
        __syncthreads();
    }
#pragma unroll
    for (int m = 0; m < 4; m++)
#pragma unroll
        for (int n = 0; n < 4; n++)
            g_xw1[(bi + ty * 4 + m) * HIDN + bj + tx * 4 + n] = acc[m][n];
}

// ---------------- 3. sim GEMM + spatial epilogue (store RAW score) ----------------
// raw = (lam*sim + (1-lam)*exp(-d2/5000)) * temperature   (sigmoid deferred)
__global__ __launch_bounds__(256) void k_sim(const float* __restrict__ pos,
                                             const float* __restrict__ plam,
                                             const float* __restrict__ ptemp) {
    __shared__ float As[8][128];
    __shared__ float Bs[8][128];
    int tid = threadIdx.x;
    int bi = blockIdx.y * 128;
    int bj = blockIdx.x * 128;
    int lr = tid >> 1;
    int lc = (tid & 1) << 2;
    int tx = tid & 15, ty = tid >> 4;

    float acc[8][8];
#pragma unroll
    for (int m = 0; m < 8; m++)
#pragma unroll
        for (int n = 0; n < 8; n++) acc[m][n] = 0.f;

    const float* Abase = g_fn + (bi + lr) * FEATN + lc;
    const float* Bbase = g_fn + (bj + lr) * FEATN + lc;

    for (int k0 = 0; k0 < FEATN; k0 += 8) {
        float4 a = *(const float4*)(Abase + k0);
        float4 b = *(const float4*)(Bbase + k0);
        As[lc + 0][lr] = a.x; As[lc + 1][lr] = a.y;
        As[lc + 2][lr] = a.z; As[lc + 3][lr] = a.w;
        Bs[lc + 0][lr] = b.x; Bs[lc + 1][lr] = b.y;
        Bs[lc + 2][lr] = b.z; Bs[lc + 3][lr] = b.w;
        __syncthreads();
#pragma unroll
        for (int k = 0; k < 8; k++) {
            float ar[8], br[8];
#pragma unroll
            for (int m = 0; m < 8; m++) ar[m] = As[k][ty * 8 + m];
#pragma unroll
            for (int n = 0; n < 8; n++) br[n] = Bs[k][tx * 8 + n];
#pragma unroll
            for (int m = 0; m < 8; m++)
#pragma unroll
                for (int n = 0; n < 8; n++) acc[m][n] += ar[m] * br[n];
        }
        __syncthreads();
    }

    float lam = 1.0f / (1.0f + expf(-plam[0]));
    float T = ptemp[0];
    float oml = 1.0f - lam;

    float pix[8], piy[8], p2i[8], pjx[8], pjy[8], p2j[8];
#pragma unroll
    for (int m = 0; m < 8; m++) {
        int r = bi + ty * 8 + m;
        pix[m] = pos[2 * r]; piy[m] = pos[2 * r + 1];
        p2i[m] = pix[m] * pix[m] + piy[m] * piy[m];
    }
#pragma unroll
    for (int n = 0; n < 8; n++) {
        int c = bj + tx * 8 + n;
        pjx[n] = pos[2 * c]; pjy[n] = pos[2 * c + 1];
        p2j[n] = pjx[n] * pjx[n] + pjy[n] * pjy[n];
    }
#pragma unroll
    for (int m = 0; m < 8; m++) {
        size_t rowoff = (size_t)(bi + ty * 8 + m) * NN + bj + tx * 8;
#pragma unroll
        for (int n = 0; n < 8; n++) {
            float d2 = fmaxf(p2i[m] + p2j[n] -
                             2.0f * (pix[m] * pjx[n] + piy[m] * pjy[n]), 0.0f);
            float sp = __expf(-d2 * INV2SD2);
            g_adj[rowoff + n] = (lam * acc[m][n] + oml * sp) * T;
        }
    }
}

// ---------------- 4. row-wise exact top-20 via register binary-search select -----
// keys: monotone u32 mapping of float (value desc, tie -> smaller index wins)
__global__ __launch_bounds__(128) void k_topk() {
    int row = blockIdx.x, t = threadIdx.x;
    const float* r = g_adj + (size_t)row * NN;

    unsigned key[48];
#pragma unroll
    for (int k = 0; k < 48; k++) {
        unsigned b = __float_as_uint(r[t + k * 128]);
        key[k] = (b & 0x80000000u) ? ~b : (b | 0x80000000u);
    }

    __shared__ int scnt[4];
    __shared__ unsigned smm[8];

    // per-row min/max of keys to seed the search range
    unsigned kmin = key[0], kmax = key[0];
#pragma unroll
    for (int k = 1; k < 48; k++) {
        kmin = min(kmin, key[k]);
        kmax = max(kmax, key[k]);
    }
    for (int o = 16; o > 0; o >>= 1) {
        kmin = min(kmin, __shfl_down_sync(0xffffffffu, kmin, o));
        kmax = max(kmax, __shfl_down_sync(0xffffffffu, kmax, o));
    }
    if ((t & 31) == 0) { smm[t >> 5] = kmin; smm[4 + (t >> 5)] = kmax; }
    __syncthreads();
    unsigned lo = min(min(smm[0], smm[1]), min(smm[2], smm[3]));
    unsigned hi = max(max(smm[4], smm[5]), max(smm[6], smm[7]));
    if (hi != 0xffffffffu) hi += 1;   // exclusive upper bound
    __syncthreads();

    // binary search: invariant count(key >= lo) >= 20
    for (int it = 0; it < 34; it++) {
        if (hi - lo <= 1) break;
        unsigned mid = lo + ((hi - lo) >> 1);
        int c = 0;
#pragma unroll
        for (int k = 0; k < 48; k++) c += (key[k] >= mid) ? 1 : 0;
        for (int o = 16; o > 0; o >>= 1) c += __shfl_down_sync(0xffffffffu, c, o);
        if ((t & 31) == 0) scnt[t >> 5] = c;
        __syncthreads();
        int tot = scnt[0] + scnt[1] + scnt[2] + scnt[3];
        __syncthreads();
        if (tot >= 20) {
            lo = mid;
            if (tot <= 96) break;     // small enough candidate set
        } else {
            hi = mid;
        }
    }

    // gather candidates >= lo (packed key|~idx for exact tie ordering)
    __shared__ unsigned long long cand[CAPC];
    __shared__ int cnum;
    cand[t] = 0ull;
    if (t == 0) cnum = 0;
    __syncthreads();
#pragma unroll
    for (int k = 0; k < 48; k++) {
        if (key[k] >= lo) {
            int p = atomicAdd(&cnum, 1);
            if (p < CAPC)
                cand[p] = ((unsigned long long)key[k] << 32) |
                          (unsigned)(~(t + k * 128));
        }
    }
    __syncthreads();

    // warp 0: 20 rounds of argmax over candidates
    if (t < 32) {
        for (int it = 0; it < KNNN; it++) {
            unsigned long long best = 0ull;
            int bslot = 0;
#pragma unroll
            for (int s = 0; s < CAPC / 32; s++) {
                unsigned long long c = cand[t + s * 32];
                if (c > best) { best = c; bslot = t + s * 32; }
            }
#pragma unroll
            for (int o = 16; o > 0; o >>= 1) {
                unsigned long long b2 = __shfl_down_sync(0xffffffffu, best, o);
                int s2 = __shfl_down_sync(0xffffffffu, bslot, o);
                if (b2 > best) { best = b2; bslot = s2; }
            }
            bslot = __shfl_sync(0xffffffffu, bslot, 0);
            if (t == 0) {
                unsigned kk = (unsigned)(best >> 32);
                unsigned fb = (kk & 0x80000000u) ? (kk & 0x7fffffffu) : ~kk;
                float raw = __uint_as_float(fb);
                g_val[row * KNNN + it] = 1.0f / (1.0f + expf(-raw));
                g_idx[row * KNNN + it] = (int)(~(unsigned)(best & 0xffffffffu));
                cand[bslot] = 0ull;
            }
            __syncwarp();
        }
    }
}

// ---------------- 5. degrees (column sums of M = A_bin + I) ----------------
__global__ void k_deg_init() {
    int i = blockIdx.x * 256 + threadIdx.x;
    if (i < NN) g_deg[i] = 1.0f;
}
__global__ void k_deg_scatter() {
    int e = blockIdx.x * 256 + threadIdx.x;
    if (e < NN * KNNN) {
        if (g_val[e] > THRF) atomicAdd(&g_deg[g_idx[e]], 1.0f);
    }
}
__global__ void k_dinv() {
    int i = blockIdx.x * 256 + threadIdx.x;
    if (i < NN) g_dinv[i] = 1.0f / sqrtf(g_deg[i]);
}

// ---------------- 6. GCN layer 1: h = relu(Mn^T (XW1) + b1) ----------------
__global__ void k_acc_init() {
    int idx = blockIdx.x * 256 + threadIdx.x;
    int i = idx >> 8;
    g_acc[idx] = g_dinv[i] * g_xw1[idx];
}
__global__ __launch_bounds__(HIDN) void k_scatter1() {
    int i = blockIdx.x, f = threadIdx.x;
    __shared__ int   sj[KNNN];
    __shared__ float sw[KNNN];
    if (f < KNNN) { sj[f] = g_idx[i * KNNN + f]; sw[f] = g_val[i * KNNN + f]; }
    __syncthreads();
    float z = g_dinv[i] * g_xw1[i * HIDN + f];
#pragma unroll
    for (int k = 0; k < KNNN; k++) {
        if (sw[k] > THRF) atomicAdd(&g_acc[sj[k] * HIDN + f], z);
    }
}
__global__ void k_relu(const float* __restrict__ b1) {
    int idx = blockIdx.x * 256 + threadIdx.x;
    int i = idx >> 8, f = idx & 255;
    g_acc[idx] = fmaxf(g_dinv[i] * g_acc[idx] + b1[f], 0.0f);
}

// ---------------- 7. t1 = h @ W2 ----------------
__global__ __launch_bounds__(64) void k_hw2(const float* __restrict__ W2) {
    int i = blockIdx.x, t = threadIdx.x;
    __shared__ float sh[HIDN];
    for (int k = t; k < HIDN; k += 64) sh[k] = g_acc[i * HIDN + k];
    __syncthreads();
    if (t < KMN) {
        float s = 0.f;
#pragma unroll 8
        for (int k = 0; k < HIDN; k++) s += sh[k] * W2[k * KMN + t];
        g_t1[i * KMN + t] = s;
    }
}

// ---------------- 8. GCN layer 2 + softmax -> S ----------------
__global__ __launch_bounds__(64) void k_sacc_init() {
    int i = blockIdx.x, t = threadIdx.x;
    if (t < KMN) g_sacc[i * KMN + t] = g_dinv[i] * g_t1[i * KMN + t];
}
__global__ __launch_bounds__(64) void k_scatter2() {
    int i = blockIdx.x, t = threadIdx.x;
    __shared__ int   sj[KNNN];
    __shared__ float sw[KNNN];
    if (t < KNNN) { sj[t] = g_idx[i * KNNN + t]; sw[t] = g_val[i * KNNN + t]; }
    __syncthreads();
    if (t < KMN) {
        float z = g_dinv[i] * g_t1[i * KMN + t];
#pragma unroll
        for (int k = 0; k < KNNN; k++) {
            if (sw[k] > THRF) atomicAdd(&g_sacc[sj[k] * KMN + t], z);
        }
    }
}
__global__ __launch_bounds__(64) void k_softmax(const float* __restrict__ b2,
                                                float* __restrict__ S) {
    int i = blockIdx.x, t = threadIdx.x;
    __shared__ float red[64];
    float v = (t < KMN) ? g_dinv[i] * g_sacc[i * KMN + t] + b2[t] : -FLT_MAX;
    red[t] = v;
#pragma unroll
    for (int o = 32; o > 0; o >>= 1) {
        __syncthreads();
        if (t < o) red[t] = fmaxf(red[t], red[t + o]);
    }
    __syncthreads();
    float mx = red[0];
    __syncthreads();
    float e = (t < KMN) ? expf(v - mx) : 0.f;
    red[t] = e;
#pragma unroll
    for (int o = 32; o > 0; o >>= 1) {
        __syncthreads();
        if (t < o) red[t] += red[t + o];
    }
    __syncthreads();
    float inv = 1.0f / red[0];
    if (t < KMN) S[i * KMN + t] = e * inv;
}

// ---------------- 9. t2 = adj @ S (sparse, masked adj values) -----
__global__ __launch_bounds__(64) void k_adjS(const float* __restrict__ S) {
    int i = blockIdx.x, t = threadIdx.x;
    __shared__ int   sj[KNNN];
    __shared__ float sw[KNNN];
    if (t < KNNN) { sj[t] = g_idx[i * KNNN + t]; sw[t] = g_val[i * KNNN + t]; }
    __syncthreads();
    if (t < KMN) {
        float a = 0.f;
#pragma unroll
        for (int k = 0; k < KNNN; k++) a += sw[k] * S[sj[k] * KMN + t];
        g_t2[i * KMN + t] = a;
    }
}

// ---------------- 10. A_coarse = S^T @ t2 (partial per 128-row block) -------
__global__ __launch_bounds__(256) void k_Ac(const float* __restrict__ S) {
    int t = threadIdx.x;
    int r0 = blockIdx.x * 128;
    __shared__ float sS[KMN], sT[KMN];
    float acc[10];
    int c1[10], c2[10]; bool ok[10];
#pragma unroll
    for (int p = 0; p < 10; p++) {
        int e = t + p * 256;
        ok[p] = (e < KMN * KMN);
        c1[p] = ok[p] ? e / KMN : 0;
        c2[p] = ok[p] ? e % KMN : 0;
        acc[p] = 0.f;
    }
    for (int r = 0; r < 128; r++) {
        int i = r0 + r;
        if (t < KMN) sS[t] = S[i * KMN + t];
        else if (t >= 64 && t < 64 + KMN) sT[t - 64] = g_t2[i * KMN + t - 64];
        __syncthreads();
#pragma unroll
        for (int p = 0; p < 10; p++)
            if (ok[p]) acc[p] += sS[c1[p]] * sT[c2[p]];
        __syncthreads();
    }
#pragma unroll
    for (int p = 0; p < 10; p++)
        if (ok[p]) atomicAdd(&g_Ac[t + p * 256], acc[p]);
}

// ---------------- 11. X_t = S^T @ X (partials, 128-row x 128-feat blocks) ---
__global__ __launch_bounds__(256) void k_Xt(const float* __restrict__ X,
                                            const float* __restrict__ S,
                                            float* __restrict__ outXt) {
    int t = threadIdx.x;
    int fc = blockIdx.x * 128;
    int r0 = blockIdx.y * 128;
    int f = t & 127, ch = t >> 7;
    __shared__ float sS[KMN];
    __shared__ float sX[128];
    float acc[25];
#pragma unroll
    for (int c = 0; c < 25; c++) acc[c] = 0.f;
    for (int r = 0; r < 128; r++) {
        int i = r0 + r;
        if (t < KMN) sS[t] = S[i * KMN + t];
        if (t >= 128) sX[t - 128] = X[i * FEATN + fc + t - 128];
        __syncthreads();
        float xv = sX[f];
#pragma unroll
        for (int c = 0; c < 25; c++) acc[c] += sS[ch * 25 + c] * xv;
        __syncthreads();
    }
#pragma unroll
    for (int c = 0; c < 25; c++)
        atomicAdd(&outXt[(ch * 25 + c) * FEATN + fc + f], acc[c]);
}

// ---------------- 12. spatial loss: sum over bin edges (S_i.S_j)*d2 ---------
__global__ __launch_bounds__(256) void k_loss(const float* __restrict__ S,
                                              const float* __restrict__ pos) {
    int warp = (blockIdx.x * 256 + threadIdx.x) >> 5;
    int lane = threadIdx.x & 31;
    if (warp >= NN) return;
    int i = warp;
    float s0 = (lane < KMN) ? S[i * KMN + lane] : 0.f;
    bool has2 = (lane + 32 < KMN);
    float s1 = has2 ? S[i * KMN + lane + 32] : 0.f;
    float xi = pos[2 * i], yi = pos[2 * i + 1];
    float p2i = xi * xi + yi * yi;
    float lsum = 0.f; int cnt = 0;
#pragma unroll
    for (int k = 0; k < KNNN; k++) {
        float v = g_val[i * KNNN + k];
        if (v > THRF) {
            int j = g_idx[i * KNNN + k];
            float xj = pos[2 * j], yj = pos[2 * j + 1];
            float d2 = fmaxf(p2i + xj * xj + yj * yj -
                             2.0f * (xi * xj + yi * yj), 0.0f);
            float dp = s0 * ((lane < KMN) ? S[j * KMN + lane] : 0.f);
            if (has2) dp += s1 * S[j * KMN + lane + 32];
            lsum += d2 * dp;
            cnt++;
        }
    }
#pragma unroll
    for (int o = 16; o > 0; o >>= 1) lsum += __shfl_down_sync(0xffffffffu, lsum, o);
    if (lane == 0) {
        atomicAdd(&g_loss, lsum);
        atomicAdd(&g_E, (float)cnt);
    }
}

// ---------------- zero/init + finalize ----------------
__global__ void k_zero(float* __restrict__ outXt) {
    int idx = blockIdx.x * 256 + threadIdx.x;
    if (idx < KMN * FEATN) outXt[idx] = 0.f;
    if (idx < KMN * KMN) g_Ac[idx] = 0.f;
    if (idx == 0) { g_loss = 0.f; g_E = 0.f; }
}
__global__ void k_final(const float* __restrict__ psw,
                        const float* __restrict__ plam,
                        float* __restrict__ out) {
    int idx = blockIdx.x * 256 + threadIdx.x;
    const int offA = NN * KMN + KMN * FEATN;
    if (idx < KMN * KMN) {
        float a = g_Ac[idx];
        out[offA + idx] = (a > THRF) ? a : 0.f;
    }
    if (idx == 0) {
        out[offA + KMN * KMN] = psw[0] * g_loss / g_E;
        out[offA + KMN * KMN + 1] = 1.0f / (1.0f + expf(-plam[0]));
    }
}

// ---------------- launcher ----------------
extern "C" void kernel_launch(void* const* d_in, const int* in_sizes, int n_in,
                              void* d_out, int out_size) {
    const float* X    = (const float*)d_in[0];
    const float* pos  = (const float*)d_in[1];
    const float* lamw = (const float*)d_in[2];
    const float* temp = (const float*)d_in[3];
    const float* sw   = (const float*)d_in[4];
    const float* W1   = (const float*)d_in[5];
    const float* b1   = (const float*)d_in[6];
    const float* W2   = (const float*)d_in[7];
    const float* b2   = (const float*)d_in[8];
    float* out  = (float*)d_out;
    float* S    = out;              // [N, K]
    float* oXt  = out + NN * KMN;   // [K, FEAT]

    k_prep<<<NN, 128>>>(X);
    k_xw1<<<dim3(HIDN / 64, NN / 64), 256>>>(X, W1);
    k_sim<<<dim3(NN / 128, NN / 128), 256>>>(pos, lamw, temp);
    k_topk<<<NN, 128>>>();
    k_zero<<<(KMN * FEATN + 255) / 256, 256>>>(oXt);
    k_deg_init<<<NN / 256, 256>>>();
    k_deg_scatter<<<(NN * KNNN + 255) / 256, 256>>>();
    k_dinv<<<NN / 256, 256>>>();
    k_acc_init<<<(NN * HIDN) / 256, 256>>>();
    k_scatter1<<<NN, HIDN>>>();
    k_relu<<<(NN * HIDN) / 256, 256>>>(b1);
    k_hw2<<<NN, 64>>>(W2);
    k_sacc_init<<<NN, 64>>>();
    k_scatter2<<<NN, 64>>>();
    k_softmax<<<NN, 64>>>(b2, S);
    k_adjS<<<NN, 64>>>(S);
    k_Ac<<<NN / 128, 256>>>(S);
    k_Xt<<<dim3(FEATN / 128, NN / 128), 256>>>(X, S, oXt);
    k_loss<<<NN / 8, 256>>>(S, pos);
    k_final<<<(KMN * KMN + 255) / 256, 256>>>(sw, lamw, out);
}

// round 12
// speedup vs baseline: 1.5298x; 1.5298x over previous
#include <cuda_runtime.h>
#include <cuda_bf16.h>
#include <math.h>
#include <float.h>
#include <stdint.h>

// Problem constants
#define NN    6144
#define FEATN 512
#define HIDN  256
#define KMN   50
#define KNNN  20
#define THRF  0.1f
#define INV2SD2 (1.0f/5000.0f)
#define CAPC  128
#define SSTR  72   // smem row stride in bf16 (144B) -> conflict-free frag loads

// ---------------- device scratch ----------------
__device__ __nv_bfloat16 g_fhi[NN * FEATN];
__device__ __nv_bfloat16 g_flo[NN * FEATN];
__device__ float g_adj[(size_t)NN * NN];           // raw scores (pre-sigmoid)
__device__ float g_xw1[NN * HIDN];
__device__ float g_acc[NN * HIDN];
__device__ float g_t1[NN * KMN];
__device__ float g_sacc[NN * KMN];
__device__ float g_t2[NN * KMN];
__device__ float g_deg[NN];
__device__ float g_dinv[NN];
__device__ int   g_idx[NN * KNNN];
__device__ float g_val[NN * KNNN];
__device__ float g_Ac[KMN * KMN];
__device__ float g_loss;
__device__ float g_E;

// ---------------- mma.sync helper (baseline PTX, valid on compute_103) -----
__device__ __forceinline__ void mma16816(float* d, const uint32_t* a,
                                         const uint32_t* b) {
    asm volatile(
        "mma.sync.aligned.m16n8k16.row.col.f32.bf16.bf16.f32 "
        "{%0,%1,%2,%3}, {%4,%5,%6,%7}, {%8,%9}, {%0,%1,%2,%3};"
        : "+f"(d[0]), "+f"(d[1]), "+f"(d[2]), "+f"(d[3])
        : "r"(a[0]), "r"(a[1]), "r"(a[2]), "r"(a[3]), "r"(b[0]), "r"(b[1]));
}

// ---------------- 1. normalize rows + bf16 hi/lo split ----------------
__global__ __launch_bounds__(128) void k_prep(const float* __restrict__ X) {
    int row = blockIdx.x, t = threadIdx.x;
    const float* xr = X + row * FEATN;
    float ss = 0.f;
    for (int f = t; f < FEATN; f += 128) { float v = xr[f]; ss += v * v; }
    for (int o = 16; o > 0; o >>= 1) ss += __shfl_down_sync(0xffffffffu, ss, o);
    __shared__ float red[4];
    __shared__ float sinv;
    if ((t & 31) == 0) red[t >> 5] = ss;
    __syncthreads();
    if (t == 0) {
        float s = red[0] + red[1] + red[2] + red[3];
        sinv = 1.0f / fmaxf(sqrtf(s), 1e-12f);
    }
    __syncthreads();
    float inv = sinv;
    for (int f = t; f < FEATN; f += 128) {
        float v = xr[f] * inv;
        __nv_bfloat16 h = __float2bfloat16(v);
        g_fhi[row * FEATN + f] = h;
        g_flo[row * FEATN + f] = __float2bfloat16(v - __bfloat162float(h));
    }
}

// ---------------- 2. XW1 = X @ W1 ----------------
__global__ __launch_bounds__(256) void k_xw1(const float* __restrict__ X,
                                             const float* __restrict__ W1) {
    __shared__ float As[16][64];
    __shared__ float Bs[16][64];
    int tid = threadIdx.x;
    int bi = blockIdx.y * 64, bj = blockIdx.x * 64;
    int tx = tid & 15, ty = tid >> 4;
    int ar_ = tid >> 2, ac_ = (tid & 3) << 2;
    int br_ = tid >> 4, bc_ = (tid & 15) << 2;
    float acc[4][4];
#pragma unroll
    for (int m = 0; m < 4; m++)
#pragma unroll
        for (int n = 0; n < 4; n++) acc[m][n] = 0.f;

    for (int k0 = 0; k0 < FEATN; k0 += 16) {
        float4 a = *(const float4*)(X + (bi + ar_) * FEATN + k0 + ac_);
        As[ac_ + 0][ar_] = a.x; As[ac_ + 1][ar_] = a.y;
        As[ac_ + 2][ar_] = a.z; As[ac_ + 3][ar_] = a.w;
        float4 b = *(const float4*)(W1 + (k0 + br_) * HIDN + bj + bc_);
        *(float4*)&Bs[br_][bc_] = b;
        __syncthreads();
#pragma unroll
        for (int k = 0; k < 16; k++) {
            float av[4], bv[4];
#pragma unroll
            for (int m = 0; m < 4; m++) av[m] = As[k][ty * 4 + m];
#pragma unroll
            for (int n = 0; n < 4; n++) bv[n] = Bs[k][tx * 4 + n];
#pragma unroll
            for (int m = 0; m < 4; m++)
#pragma unroll
                for (int n = 0; n < 4; n++) acc[m][n] += av[m] * bv[n];
        }
        __syncthreads();
    }
#pragma unroll
    for (int m = 0; m < 4; m++)
#pragma unroll
        for (int n = 0; n < 4; n++)
            g_xw1[(bi + ty * 4 + m) * HIDN + bj + tx * 4 + n] = acc[m][n];
}

// ---------------- 3. sim via bf16 mma.sync hi/lo split + fused epilogue ----
// D = hiA.hiB^T + loA.hiB^T + hiA.loB^T   (fp32 accum)
// raw = lam*T*D + (1-lam)*T*exp(-d2/5000) -> g_adj
__global__ __launch_bounds__(256) void k_sim_mma(const float* __restrict__ pos,
                                                 const float* __restrict__ plam,
                                                 const float* __restrict__ ptemp) {
    __shared__ __nv_bfloat16 sA[128 * SSTR];
    __shared__ __nv_bfloat16 sB[128 * SSTR];
    __shared__ float cpx[128], cpy[128], rpx[128], rpy[128];

    int t = threadIdx.x, w = t >> 5, lane = t & 31;
    int bi = blockIdx.y * 128, bj = blockIdx.x * 128;
    int wm = w & 3, wn = w >> 2;          // 4 (M) x 2 (N) warp grid

    if (t < 128) {
        cpx[t] = pos[2 * (bj + t)];
        cpy[t] = pos[2 * (bj + t) + 1];
    } else {
        int u = t - 128;
        rpx[u] = pos[2 * (bi + u)];
        rpy[u] = pos[2 * (bi + u) + 1];
    }

    float acc[2][8][4];
#pragma unroll
    for (int mi = 0; mi < 2; mi++)
#pragma unroll
        for (int ni = 0; ni < 8; ni++)
#pragma unroll
            for (int r = 0; r < 4; r++) acc[mi][ni][r] = 0.f;

    int lrow = t >> 1;
    int lch = (t & 1) * 4;     // 16B chunks [lch, lch+4)

    const __nv_bfloat16* Aseg[3] = { g_fhi, g_flo, g_fhi };
    const __nv_bfloat16* Bseg[3] = { g_fhi, g_fhi, g_flo };

#pragma unroll 1
    for (int seg = 0; seg < 3; seg++) {
        const __nv_bfloat16* Ag = Aseg[seg] + (size_t)(bi + lrow) * FEATN;
        const __nv_bfloat16* Bg = Bseg[seg] + (size_t)(bj + lrow) * FEATN;
#pragma unroll 1
        for (int kc = 0; kc < FEATN; kc += 64) {
            __syncthreads();
#pragma unroll
            for (int j = 0; j < 4; j++) {
                int ch = lch + j;
                *(uint4*)&sA[lrow * SSTR + ch * 8] = *(const uint4*)(Ag + kc + ch * 8);
                *(uint4*)&sB[lrow * SSTR + ch * 8] = *(const uint4*)(Bg + kc + ch * 8);
            }
            __syncthreads();
#pragma unroll
            for (int k16 = 0; k16 < 4; k16++) {
                int kb = k16 * 16 + (lane & 3) * 2;
                uint32_t bfr[8][2];
#pragma unroll
                for (int ni = 0; ni < 8; ni++) {
                    int n = wn * 64 + ni * 8 + (lane >> 2);
                    bfr[ni][0] = *(const uint32_t*)&sB[n * SSTR + kb];
                    bfr[ni][1] = *(const uint32_t*)&sB[n * SSTR + kb + 8];
                }
#pragma unroll
                for (int mi = 0; mi < 2; mi++) {
                    int r = wm * 32 + mi * 16 + (lane >> 2);
                    uint32_t afr[4];
                    afr[0] = *(const uint32_t*)&sA[r * SSTR + kb];
                    afr[1] = *(const uint32_t*)&sA[(r + 8) * SSTR + kb];
                    afr[2] = *(const uint32_t*)&sA[r * SSTR + kb + 8];
                    afr[3] = *(const uint32_t*)&sA[(r + 8) * SSTR + kb + 8];
#pragma unroll
                    for (int ni = 0; ni < 8; ni++)
                        mma16816(acc[mi][ni], afr, bfr[ni]);
                }
            }
        }
    }

    // epilogue: spatial + scale, write raw scores
    float lam = 1.0f / (1.0f + expf(-plam[0]));
    float T = ptemp[0];
    float aC = lam * T, bC = (1.0f - lam) * T;
#pragma unroll
    for (int mi = 0; mi < 2; mi++) {
#pragma unroll
        for (int rr = 0; rr < 2; rr++) {
            int r = wm * 32 + mi * 16 + rr * 8 + (lane >> 2);
            float xi = rpx[r], yi = rpy[r];
            float p2i = xi * xi + yi * yi;
            size_t gro = (size_t)(bi + r) * NN + bj;
#pragma unroll
            for (int ni = 0; ni < 8; ni++) {
                int c = wn * 64 + ni * 8 + (lane & 3) * 2;
                float xj0 = cpx[c], yj0 = cpy[c];
                float xj1 = cpx[c + 1], yj1 = cpy[c + 1];
                float d20 = fmaxf(p2i + xj0 * xj0 + yj0 * yj0 -
                                  2.0f * (xi * xj0 + yi * yj0), 0.0f);
                float d21 = fmaxf(p2i + xj1 * xj1 + yj1 * yj1 -
                                  2.0f * (xi * xj1 + yi * yj1), 0.0f);
                float2 o;
                o.x = aC * acc[mi][ni][rr * 2 + 0] + bC * __expf(-d20 * INV2SD2);
                o.y = aC * acc[mi][ni][rr * 2 + 1] + bC * __expf(-d21 * INV2SD2);
                *(float2*)&g_adj[gro + c] = o;
            }
        }
    }
}

// ---------------- 4. row-wise exact top-20 (binary-search select) -----
__global__ __launch_bounds__(128) void k_topk() {
    int row = blockIdx.x, t = threadIdx.x;
    const float* r = g_adj + (size_t)row * NN;

    unsigned key[48];
#pragma unroll
    for (int k = 0; k < 48; k++) {
        unsigned b = __float_as_uint(r[t + k * 128]);
        key[k] = (b & 0x80000000u) ? ~b : (b | 0x80000000u);
    }

    __shared__ int scnt[4];
    __shared__ unsigned smm[8];

    unsigned kmin = key[0], kmax = key[0];
#pragma unroll
    for (int k = 1; k < 48; k++) {
        kmin = min(kmin, key[k]);
        kmax = max(kmax, key[k]);
    }
    for (int o = 16; o > 0; o >>= 1) {
        kmin = min(kmin, __shfl_down_sync(0xffffffffu, kmin, o));
        kmax = max(kmax, __shfl_down_sync(0xffffffffu, kmax, o));
    }
    if ((t & 31) == 0) { smm[t >> 5] = kmin; smm[4 + (t >> 5)] = kmax; }
    __syncthreads();
    unsigned lo = min(min(smm[0], smm[1]), min(smm[2], smm[3]));
    unsigned hi = max(max(smm[4], smm[5]), max(smm[6], smm[7]));
    if (hi != 0xffffffffu) hi += 1;
    __syncthreads();

    for (int it = 0; it < 34; it++) {
        if (hi - lo <= 1) break;
        unsigned mid = lo + ((hi - lo) >> 1);
        int c = 0;
#pragma unroll
        for (int k = 0; k < 48; k++) c += (key[k] >= mid) ? 1 : 0;
        for (int o = 16; o > 0; o >>= 1) c += __shfl_down_sync(0xffffffffu, c, o);
        if ((t & 31) == 0) scnt[t >> 5] = c;
        __syncthreads();
        int tot = scnt[0] + scnt[1] + scnt[2] + scnt[3];
        __syncthreads();
        if (tot >= 20) {
            lo = mid;
            if (tot <= 96) break;
        } else {
            hi = mid;
        }
    }

    __shared__ unsigned long long cand[CAPC];
    __shared__ int cnum;
    cand[t] = 0ull;
    if (t == 0) cnum = 0;
    __syncthreads();
#pragma unroll
    for (int k = 0; k < 48; k++) {
        if (key[k] >= lo) {
            int p = atomicAdd(&cnum, 1);
            if (p < CAPC)
                cand[p] = ((unsigned long long)key[k] << 32) |
                          (unsigned)(~(t + k * 128));
        }
    }
    __syncthreads();

    if (t < 32) {
        for (int it = 0; it < KNNN; it++) {
            unsigned long long best = 0ull;
            int bslot = 0;
#pragma unroll
            for (int s = 0; s < CAPC / 32; s++) {
                unsigned long long c = cand[t + s * 32];
                if (c > best) { best = c; bslot = t + s * 32; }
            }
#pragma unroll
            for (int o = 16; o > 0; o >>= 1) {
                unsigned long long b2 = __shfl_down_sync(0xffffffffu, best, o);
                int s2 = __shfl_down_sync(0xffffffffu, bslot, o);
                if (b2 > best) { best = b2; bslot = s2; }
            }
            bslot = __shfl_sync(0xffffffffu, bslot, 0);
            if (t == 0) {
                unsigned kk = (unsigned)(best >> 32);
                unsigned fb = (kk & 0x80000000u) ? (kk & 0x7fffffffu) : ~kk;
                float raw = __uint_as_float(fb);
                g_val[row * KNNN + it] = 1.0f / (1.0f + expf(-raw));
                g_idx[row * KNNN + it] = (int)(~(unsigned)(best & 0xffffffffu));
                cand[bslot] = 0ull;
            }
            __syncwarp();
        }
    }
}

// ---------------- 5. degrees ----------------
__global__ void k_deg_init() {
    int i = blockIdx.x * 256 + threadIdx.x;
    if (i < NN) g_deg[i] = 1.0f;
}
__global__ void k_deg_scatter() {
    int e = blockIdx.x * 256 + threadIdx.x;
    if (e < NN * KNNN) {
        if (g_val[e] > THRF) atomicAdd(&g_deg[g_idx[e]], 1.0f);
    }
}
__global__ void k_dinv() {
    int i = blockIdx.x * 256 + threadIdx.x;
    if (i < NN) g_dinv[i] = 1.0f / sqrtf(g_deg[i]);
}

// ---------------- 6. GCN layer 1 ----------------
__global__ void k_acc_init() {
    int idx = blockIdx.x * 256 + threadIdx.x;
    int i = idx >> 8;
    g_acc[idx] = g_dinv[i] * g_xw1[idx];
}
__global__ __launch_bounds__(HIDN) void k_scatter1() {
    int i = blockIdx.x, f = threadIdx.x;
    __shared__ int   sj[KNNN];
    __shared__ float sw[KNNN];
    if (f < KNNN) { sj[f] = g_idx[i * KNNN + f]; sw[f] = g_val[i * KNNN + f]; }
    __syncthreads();
    float z = g_dinv[i] * g_xw1[i * HIDN + f];
#pragma unroll
    for (int k = 0; k < KNNN; k++) {
        if (sw[k] > THRF) atomicAdd(&g_acc[sj[k] * HIDN + f], z);
    }
}
__global__ void k_relu(const float* __restrict__ b1) {
    int idx = blockIdx.x * 256 + threadIdx.x;
    int i = idx >> 8, f = idx & 255;
    g_acc[idx] = fmaxf(g_dinv[i] * g_acc[idx] + b1[f], 0.0f);
}

// ---------------- 7. t1 = h @ W2 ----------------
__global__ __launch_bounds__(64) void k_hw2(const float* __restrict__ W2) {
    int i = blockIdx.x, t = threadIdx.x;
    __shared__ float sh[HIDN];
    for (int k = t; k < HIDN; k += 64) sh[k] = g_acc[i * HIDN + k];
    __syncthreads();
    if (t < KMN) {
        float s = 0.f;
#pragma unroll 8
        for (int k = 0; k < HIDN; k++) s += sh[k] * W2[k * KMN + t];
        g_t1[i * KMN + t] = s;
    }
}

// ---------------- 8. GCN layer 2 + softmax ----------------
__global__ __launch_bounds__(64) void k_sacc_init() {
    int i = blockIdx.x, t = threadIdx.x;
    if (t < KMN) g_sacc[i * KMN + t] = g_dinv[i] * g_t1[i * KMN + t];
}
__global__ __launch_bounds__(64) void k_scatter2() {
    int i = blockIdx.x, t = threadIdx.x;
    __shared__ int   sj[KNNN];
    __shared__ float sw[KNNN];
    if (t < KNNN) { sj[t] = g_idx[i * KNNN + t]; sw[t] = g_val[i * KNNN + t]; }
    __syncthreads();
    if (t < KMN) {
        float z = g_dinv[i] * g_t1[i * KMN + t];
#pragma unroll
        for (int k = 0; k < KNNN; k++) {
            if (sw[k] > THRF) atomicAdd(&g_sacc[sj[k] * KMN + t], z);
        }
    }
}
__global__ __launch_bounds__(64) void k_softmax(const float* __restrict__ b2,
                                                float* __restrict__ S) {
    int i = blockIdx.x, t = threadIdx.x;
    __shared__ float red[64];
    float v = (t < KMN) ? g_dinv[i] * g_sacc[i * KMN + t] + b2[t] : -FLT_MAX;
    red[t] = v;
#pragma unroll
    for (int o = 32; o > 0; o >>= 1) {
        __syncthreads();
        if (t < o) red[t] = fmaxf(red[t], red[t + o]);
    }
    __syncthreads();
    float mx = red[0];
    __syncthreads();
    float e = (t < KMN) ? expf(v - mx) : 0.f;
    red[t] = e;
#pragma unroll
    for (int o = 32; o > 0; o >>= 1) {
        __syncthreads();
        if (t < o) red[t] += red[t + o];
    }
    __syncthreads();
    float inv = 1.0f / red[0];
    if (t < KMN) S[i * KMN + t] = e * inv;
}

// ---------------- 9. t2 = adj @ S ----------------
__global__ __launch_bounds__(64) void k_adjS(const float* __restrict__ S) {
    int i = blockIdx.x, t = threadIdx.x;
    __shared__ int   sj[KNNN];
    __shared__ float sw[KNNN];
    if (t < KNNN) { sj[t] = g_idx[i * KNNN + t]; sw[t] = g_val[i * KNNN + t]; }
    __syncthreads();
    if (t < KMN) {
        float a = 0.f;
#pragma unroll
        for (int k = 0; k < KNNN; k++) a += sw[k] * S[sj[k] * KMN + t];
        g_t2[i * KMN + t] = a;
    }
}

// ---------------- 10. A_coarse = S^T @ t2 ----------------
__global__ __launch_bounds__(256) void k_Ac(const float* __restrict__ S) {
    int t = threadIdx.x;
    int r0 = blockIdx.x * 128;
    __shared__ float sS[KMN], sT[KMN];
    float acc[10];
    int c1[10], c2[10]; bool ok[10];
#pragma unroll
    for (int p = 0; p < 10; p++) {
        int e = t + p * 256;
        ok[p] = (e < KMN * KMN);
        c1[p] = ok[p] ? e / KMN : 0;
        c2[p] = ok[p] ? e % KMN : 0;
        acc[p] = 0.f;
    }
    for (int r = 0; r < 128; r++) {
        int i = r0 + r;
        if (t < KMN) sS[t] = S[i * KMN + t];
        else if (t >= 64 && t < 64 + KMN) sT[t - 64] = g_t2[i * KMN + t - 64];
        __syncthreads();
#pragma unroll
        for (int p = 0; p < 10; p++)
            if (ok[p]) acc[p] += sS[c1[p]] * sT[c2[p]];
        __syncthreads();
    }
#pragma unroll
    for (int p = 0; p < 10; p++)
        if (ok[p]) atomicAdd(&g_Ac[t + p * 256], acc[p]);
}

// ---------------- 11. X_t = S^T @ X ----------------
__global__ __launch_bounds__(256) void k_Xt(const float* __restrict__ X,
                                            const float* __restrict__ S,
                                            float* __restrict__ outXt) {
    int t = threadIdx.x;
    int fc = blockIdx.x * 128;
    int r0 = blockIdx.y * 128;
    int f = t & 127, ch = t >> 7;
    __shared__ float sS[KMN];
    __shared__ float sX[128];
    float acc[25];
#pragma unroll
    for (int c = 0; c < 25; c++) acc[c] = 0.f;
    for (int r = 0; r < 128; r++) {
        int i = r0 + r;
        if (t < KMN) sS[t] = S[i * KMN + t];
        if (t >= 128) sX[t - 128] = X[i * FEATN + fc + t - 128];
        __syncthreads();
        float xv = sX[f];
#pragma unroll
        for (int c = 0; c < 25; c++) acc[c] += sS[ch * 25 + c] * xv;
        __syncthreads();
    }
#pragma unroll
    for (int c = 0; c < 25; c++)
        atomicAdd(&outXt[(ch * 25 + c) * FEATN + fc + f], acc[c]);
}

// ---------------- 12. spatial loss ----------------
__global__ __launch_bounds__(256) void k_loss(const float* __restrict__ S,
                                              const float* __restrict__ pos) {
    int warp = (blockIdx.x * 256 + threadIdx.x) >> 5;
    int lane = threadIdx.x & 31;
    if (warp >= NN) return;
    int i = warp;
    float s0 = (lane < KMN) ? S[i * KMN + lane] : 0.f;
    bool has2 = (lane + 32 < KMN);
    float s1 = has2 ? S[i * KMN + lane + 32] : 0.f;
    float xi = pos[2 * i], yi = pos[2 * i + 1];
    float p2i = xi * xi + yi * yi;
    float lsum = 0.f; int cnt = 0;
#pragma unroll
    for (int k = 0; k < KNNN; k++) {
        float v = g_val[i * KNNN + k];
        if (v > THRF) {
            int j = g_idx[i * KNNN + k];
            float xj = pos[2 * j], yj = pos[2 * j + 1];
            float d2 = fmaxf(p2i + xj * xj + yj * yj -
                             2.0f * (xi * xj + yi * yj), 0.0f);
            float dp = s0 * ((lane < KMN) ? S[j * KMN + lane] : 0.f);
            if (has2) dp += s1 * S[j * KMN + lane + 32];
            lsum += d2 * dp;
            cnt++;
        }
    }
#pragma unroll
    for (int o = 16; o > 0; o >>= 1) lsum += __shfl_down_sync(0xffffffffu, lsum, o);
    if (lane == 0) {
        atomicAdd(&g_loss, lsum);
        atomicAdd(&g_E, (float)cnt);
    }
}

// ---------------- zero/init + finalize ----------------
__global__ void k_zero(float* __restrict__ outXt) {
    int idx = blockIdx.x * 256 + threadIdx.x;
    if (idx < KMN * FEATN) outXt[idx] = 0.f;
    if (idx < KMN * KMN) g_Ac[idx] = 0.f;
    if (idx == 0) { g_loss = 0.f; g_E = 0.f; }
}
__global__ void k_final(const float* __restrict__ psw,
                        const float* __restrict__ plam,
                        float* __restrict__ out) {
    int idx = blockIdx.x * 256 + threadIdx.x;
    const int offA = NN * KMN + KMN * FEATN;
    if (idx < KMN * KMN) {
        float a = g_Ac[idx];
        out[offA + idx] = (a > THRF) ? a : 0.f;
    }
    if (idx == 0) {
        out[offA + KMN * KMN] = psw[0] * g_loss / g_E;
        out[offA + KMN * KMN + 1] = 1.0f / (1.0f + expf(-plam[0]));
    }
}

// ---------------- launcher ----------------
extern "C" void kernel_launch(void* const* d_in, const int* in_sizes, int n_in,
                              void* d_out, int out_size) {
    const float* X    = (const float*)d_in[0];
    const float* pos  = (const float*)d_in[1];
    const float* lamw = (const float*)d_in[2];
    const float* temp = (const float*)d_in[3];
    const float* sw   = (const float*)d_in[4];
    const float* W1   = (const float*)d_in[5];
    const float* b1   = (const float*)d_in[6];
    const float* W2   = (const float*)d_in[7];
    const float* b2   = (const float*)d_in[8];
    float* out  = (float*)d_out;
    float* S    = out;              // [N, K]
    float* oXt  = out + NN * KMN;   // [K, FEAT]

    k_prep<<<NN, 128>>>(X);
    k_xw1<<<dim3(HIDN / 64, NN / 64), 256>>>(X, W1);
    k_sim_mma<<<dim3(NN / 128, NN / 128), 256>>>(pos, lamw, temp);
    k_topk<<<NN, 128>>>();
    k_zero<<<(KMN * FEATN + 255) / 256, 256>>>(oXt);
    k_deg_init<<<NN / 256, 256>>>();
    k_deg_scatter<<<(NN * KNNN + 255) / 256, 256>>>();
    k_dinv<<<NN / 256, 256>>>();
    k_acc_init<<<(NN * HIDN) / 256, 256>>>();
    k_scatter1<<<NN, HIDN>>>();
    k_relu<<<(NN * HIDN) / 256, 256>>>(b1);
    k_hw2<<<NN, 64>>>(W2);
    k_sacc_init<<<NN, 64>>>();
    k_scatter2<<<NN, 64>>>();
    k_softmax<<<NN, 64>>>(b2, S);
    k_adjS<<<NN, 64>>>(S);
    k_Ac<<<NN / 128, 256>>>(S);
    k_Xt<<<dim3(FEATN / 128, NN / 128), 256>>>(X, S, oXt);
    k_loss<<<NN / 8, 256>>>(S, pos);
    k_final<<<(KMN * KMN + 255) / 256, 256>>>(sw, lamw, out);
}

// round 13
// speedup vs baseline: 2.1919x; 1.4328x over previous
#include <cuda_runtime.h>
#include <cuda_bf16.h>
#include <math.h>
#include <float.h>
#include <stdint.h>

// Problem constants
#define NN    6144
#define FEATN 512
#define HIDN  256
#define KMN   50
#define KNNN  20
#define THRF  0.1f
#define INV2SD2 (1.0f/5000.0f)
#define CAPC  128
#define SSTR  72        // smem row stride in bf16 (144B) -> conflict-free
#define TILEB (128*SSTR*2)            // 18432 B per tile
#define BUFB  (4*TILEB)               // 73728 B per buffer (Ahi,Alo,Bhi,Blo)

// ---------------- device scratch ----------------
__device__ __nv_bfloat16 g_fhi[NN * FEATN];
__device__ __nv_bfloat16 g_flo[NN * FEATN];
__device__ float g_adj[(size_t)NN * NN];           // raw scores (pre-sigmoid)
__device__ float g_xw1[NN * HIDN];
__device__ float g_acc[NN * HIDN];
__device__ float g_t1[NN * KMN];
__device__ float g_sacc[NN * KMN];
__device__ float g_t2[NN * KMN];
__device__ float g_deg[NN];
__device__ float g_dinv[NN];
__device__ int   g_idx[NN * KNNN];
__device__ float g_val[NN * KNNN];
__device__ float g_Ac[KMN * KMN];
__device__ float g_loss;
__device__ float g_E;

// ---------------- PTX helpers (all baseline ISA, valid on compute_103) -----
__device__ __forceinline__ void mma16816(float* d, const uint32_t* a,
                                         const uint32_t* b) {
    asm volatile(
        "mma.sync.aligned.m16n8k16.row.col.f32.bf16.bf16.f32 "
        "{%0,%1,%2,%3}, {%4,%5,%6,%7}, {%8,%9}, {%0,%1,%2,%3};"
        : "+f"(d[0]), "+f"(d[1]), "+f"(d[2]), "+f"(d[3])
        : "r"(a[0]), "r"(a[1]), "r"(a[2]), "r"(a[3]), "r"(b[0]), "r"(b[1]));
}
__device__ __forceinline__ uint32_t smem_u32(const void* p) {
    uint32_t a;
    asm("{ .reg .u64 t; cvta.to.shared.u64 t, %1; cvt.u32.u64 %0, t; }"
        : "=r"(a) : "l"(p));
    return a;
}
#define LDMX4(r, addr) asm volatile( \
    "ldmatrix.sync.aligned.m8n8.x4.shared.b16 {%0,%1,%2,%3}, [%4];" \
    : "=r"((r)[0]), "=r"((r)[1]), "=r"((r)[2]), "=r"((r)[3]) : "r"(addr))
#define CP16(saddr, gptr) asm volatile( \
    "cp.async.cg.shared.global [%0], [%1], 16;" :: "r"(saddr), "l"(gptr))
#define CP_COMMIT() asm volatile("cp.async.commit_group;" ::: "memory")

// ---------------- 1. normalize rows + bf16 hi/lo split ----------------
__global__ __launch_bounds__(128) void k_prep(const float* __restrict__ X) {
    int row = blockIdx.x, t = threadIdx.x;
    const float* xr = X + row * FEATN;
    float ss = 0.f;
    for (int f = t; f < FEATN; f += 128) { float v = xr[f]; ss += v * v; }
    for (int o = 16; o > 0; o >>= 1) ss += __shfl_down_sync(0xffffffffu, ss, o);
    __shared__ float red[4];
    __shared__ float sinv;
    if ((t & 31) == 0) red[t >> 5] = ss;
    __syncthreads();
    if (t == 0) {
        float s = red[0] + red[1] + red[2] + red[3];
        sinv = 1.0f / fmaxf(sqrtf(s), 1e-12f);
    }
    __syncthreads();
    float inv = sinv;
    for (int f = t; f < FEATN; f += 128) {
        float v = xr[f] * inv;
        __nv_bfloat16 h = __float2bfloat16(v);
        g_fhi[row * FEATN + f] = h;
        g_flo[row * FEATN + f] = __float2bfloat16(v - __bfloat162float(h));
    }
}

// ---------------- 2. XW1 = X @ W1 ----------------
__global__ __launch_bounds__(256) void k_xw1(const float* __restrict__ X,
                                             const float* __restrict__ W1) {
    __shared__ float As[16][64];
    __shared__ float Bs[16][64];
    int tid = threadIdx.x;
    int bi = blockIdx.y * 64, bj = blockIdx.x * 64;
    int tx = tid & 15, ty = tid >> 4;
    int ar_ = tid >> 2, ac_ = (tid & 3) << 2;
    int br_ = tid >> 4, bc_ = (tid & 15) << 2;
    float acc[4][4];
#pragma unroll
    for (int m = 0; m < 4; m++)
#pragma unroll
        for (int n = 0; n < 4; n++) acc[m][n] = 0.f;

    for (int k0 = 0; k0 < FEATN; k0 += 16) {
        float4 a = *(const float4*)(X + (bi + ar_) * FEATN + k0 + ac_);
        As[ac_ + 0][ar_] = a.x; As[ac_ + 1][ar_] = a.y;
        As[ac_ + 2][ar_] = a.z; As[ac_ + 3][ar_] = a.w;
        float4 b = *(const float4*)(W1 + (k0 + br_) * HIDN + bj + bc_);
        *(float4*)&Bs[br_][bc_] = b;
        __syncthreads();
#pragma unroll
        for (int k = 0; k < 16; k++) {
            float av[4], bv[4];
#pragma unroll
            for (int m = 0; m < 4; m++) av[m] = As[k][ty * 4 + m];
#pragma unroll
            for (int n = 0; n < 4; n++) bv[n] = Bs[k][tx * 4 + n];
#pragma unroll
            for (int m = 0; m < 4; m++)
#pragma unroll
                for (int n = 0; n < 4; n++) acc[m][n] += av[m] * bv[n];
        }
        __syncthreads();
    }
#pragma unroll
    for (int m = 0; m < 4; m++)
#pragma unroll
        for (int n = 0; n < 4; n++)
            g_xw1[(bi + ty * 4 + m) * HIDN + bj + tx * 4 + n] = acc[m][n];
}

// ---------------- 3. sim: bf16 hi/lo mma + cp.async pipeline + symmetry ----
// D = hiA.hiB^T + loA.hiB^T + hiA.loB^T ; raw = lam*T*D + (1-lam)*T*exp(-d2/5000)
// Upper-triangle tiles only; mirror written via smem transpose stage.
__global__ __launch_bounds__(256) void k_sim_mma(const float* __restrict__ pos,
                                                 const float* __restrict__ plam,
                                                 const float* __restrict__ ptemp) {
    if (blockIdx.y > blockIdx.x) return;    // symmetry: compute bj >= bi only
    extern __shared__ char dyn[];
    __shared__ float cpx[128], cpy[128], rpx[128], rpy[128];

    int t = threadIdx.x, w = t >> 5, lane = t & 31;
    int bi = blockIdx.y * 128, bj = blockIdx.x * 128;
    bool offdiag = (blockIdx.x != blockIdx.y);
    int wm = w & 3, wn = w >> 2;            // 4(M) x 2(N) warp grid

    if (t < 128) {
        cpx[t] = pos[2 * (bj + t)];
        cpy[t] = pos[2 * (bj + t) + 1];
    } else {
        int u = t - 128;
        rpx[u] = pos[2 * (bi + u)];
        rpy[u] = pos[2 * (bi + u) + 1];
    }

    float acc[2][8][4];
#pragma unroll
    for (int mi = 0; mi < 2; mi++)
#pragma unroll
        for (int ni = 0; ni < 8; ni++)
#pragma unroll
            for (int r = 0; r < 4; r++) acc[mi][ni][r] = 0.f;

    uint32_t dynb = smem_u32(dyn);
    int lrow = t >> 1;
    int lch = (t & 1) * 4;                  // 16B chunks [lch, lch+4)

    const __nv_bfloat16* Ah0 = g_fhi + (size_t)(bi + lrow) * FEATN;
    const __nv_bfloat16* Al0 = g_flo + (size_t)(bi + lrow) * FEATN;
    const __nv_bfloat16* Bh0 = g_fhi + (size_t)(bj + lrow) * FEATN;
    const __nv_bfloat16* Bl0 = g_flo + (size_t)(bj + lrow) * FEATN;

    auto issue = [&](int c, int buf) {
        int kc = c * 64;
        uint32_t sb = dynb + buf * BUFB + lrow * (SSTR * 2);
#pragma unroll
        for (int j = 0; j < 4; j++) {
            int ch = lch + j;
            uint32_t off = sb + ch * 16;
            CP16(off,             Ah0 + kc + ch * 8);
            CP16(off + TILEB,     Al0 + kc + ch * 8);
            CP16(off + 2 * TILEB, Bh0 + kc + ch * 8);
            CP16(off + 3 * TILEB, Bl0 + kc + ch * 8);
        }
        CP_COMMIT();
    };

    issue(0, 0);
#pragma unroll 1
    for (int c = 0; c < 8; c++) {
        if (c < 7) {
            issue(c + 1, (c + 1) & 1);
            asm volatile("cp.async.wait_group 1;" ::: "memory");
        } else {
            asm volatile("cp.async.wait_group 0;" ::: "memory");
        }
        __syncthreads();
        uint32_t tb = dynb + (c & 1) * BUFB;
        int m = lane >> 3, r8 = lane & 7;
#pragma unroll
        for (int k16 = 0; k16 < 4; k16++) {
            int kb = k16 * 16;
            uint32_t ah[2][4], al[2][4], bf[8][2];
            // A fragments (hi & lo): matrices rows R+(m&1)*8+r8, col kb+(m>>1)*8
#pragma unroll
            for (int mi = 0; mi < 2; mi++) {
                int R = wm * 32 + mi * 16;
                uint32_t aoff = ((R + (m & 1) * 8 + r8) * SSTR + kb + (m >> 1) * 8) * 2;
                LDMX4(ah[mi], tb + aoff);
                LDMX4(al[mi], tb + TILEB + aoff);
            }
            // B-hi fragments: 4 x ldmatrix.x4 covering ni pairs
#pragma unroll
            for (int p = 0; p < 4; p++) {
                int n0 = wn * 64 + p * 16;
                uint32_t boff = ((n0 + (m >> 1) * 8 + r8) * SSTR + kb + (m & 1) * 8) * 2;
                LDMX4(&bf[2 * p][0], tb + 2 * TILEB + boff);
            }
#pragma unroll
            for (int mi = 0; mi < 2; mi++)
#pragma unroll
                for (int ni = 0; ni < 8; ni++) {
                    mma16816(acc[mi][ni], ah[mi], bf[ni]);   // hi.hi
                    mma16816(acc[mi][ni], al[mi], bf[ni]);   // lo.hi
                }
            // B-lo fragments (reuse regs)
#pragma unroll
            for (int p = 0; p < 4; p++) {
                int n0 = wn * 64 + p * 16;
                uint32_t boff = ((n0 + (m >> 1) * 8 + r8) * SSTR + kb + (m & 1) * 8) * 2;
                LDMX4(&bf[2 * p][0], tb + 3 * TILEB + boff);
            }
#pragma unroll
            for (int mi = 0; mi < 2; mi++)
#pragma unroll
                for (int ni = 0; ni < 8; ni++)
                    mma16816(acc[mi][ni], ah[mi], bf[ni]);   // hi.lo
        }
        __syncthreads();
    }

    // epilogue: raw scores; direct write + (off-diag) transpose stage
    float lam = 1.0f / (1.0f + expf(-plam[0]));
    float T = ptemp[0];
    float aC = lam * T, bC = (1.0f - lam) * T;
    float* stage = (float*)dyn;             // 128 x (stride 132) floats
#pragma unroll
    for (int mi = 0; mi < 2; mi++) {
#pragma unroll
        for (int rr = 0; rr < 2; rr++) {
            int r = wm * 32 + mi * 16 + rr * 8 + (lane >> 2);
            float xi = rpx[r], yi = rpy[r];
            float p2i = xi * xi + yi * yi;
            size_t gro = (size_t)(bi + r) * NN + bj;
#pragma unroll
            for (int ni = 0; ni < 8; ni++) {
                int c = wn * 64 + ni * 8 + (lane & 3) * 2;
                float xj0 = cpx[c], yj0 = cpy[c];
                float xj1 = cpx[c + 1], yj1 = cpy[c + 1];
                float d20 = fmaxf(p2i + xj0 * xj0 + yj0 * yj0 -
                                  2.0f * (xi * xj0 + yi * yj0), 0.0f);
                float d21 = fmaxf(p2i + xj1 * xj1 + yj1 * yj1 -
                                  2.0f * (xi * xj1 + yi * yj1), 0.0f);
                float2 o;
                o.x = aC * acc[mi][ni][rr * 2 + 0] + bC * __expf(-d20 * INV2SD2);
                o.y = aC * acc[mi][ni][rr * 2 + 1] + bC * __expf(-d21 * INV2SD2);
                *(float2*)&g_adj[gro + c] = o;
                if (offdiag) {
                    stage[c * 132 + r] = o.x;
                    stage[(c + 1) * 132 + r] = o.y;
                }
            }
        }
    }
    if (offdiag) {
        __syncthreads();
#pragma unroll
        for (int j = 0; j < 16; j++) {
            int idx4 = t + j * 256;
            int cc = idx4 >> 5, r4 = (idx4 & 31) * 4;
            float4 v = *(float4*)&stage[cc * 132 + r4];
            *(float4*)&g_adj[(size_t)(bj + cc) * NN + bi + r4] = v;
        }
    }
}

// ---------------- 4. row-wise exact top-20 (binary-search select) -----
__global__ __launch_bounds__(128) void k_topk() {
    int row = blockIdx.x, t = threadIdx.x;
    const float* r = g_adj + (size_t)row * NN;

    unsigned key[48];
#pragma unroll
    for (int k = 0; k < 48; k++) {
        unsigned b = __float_as_uint(r[t + k * 128]);
        key[k] = (b & 0x80000000u) ? ~b : (b | 0x80000000u);
    }

    __shared__ int scnt[4];
    __shared__ unsigned smm[8];

    unsigned kmin = key[0], kmax = key[0];
#pragma unroll
    for (int k = 1; k < 48; k++) {
        kmin = min(kmin, key[k]);
        kmax = max(kmax, key[k]);
    }
    for (int o = 16; o > 0; o >>= 1) {
        kmin = min(kmin, __shfl_down_sync(0xffffffffu, kmin, o));
        kmax = max(kmax, __shfl_down_sync(0xffffffffu, kmax, o));
    }
    if ((t & 31) == 0) { smm[t >> 5] = kmin; smm[4 + (t >> 5)] = kmax; }
    __syncthreads();
    unsigned lo = min(min(smm[0], smm[1]), min(smm[2], smm[3]));
    unsigned hi = max(max(smm[4], smm[5]), max(smm[6], smm[7]));
    if (hi != 0xffffffffu) hi += 1;
    __syncthreads();

    for (int it = 0; it < 34; it++) {
        if (hi - lo <= 1) break;
        unsigned mid = lo + ((hi - lo) >> 1);
        int c = 0;
#pragma unroll
        for (int k = 0; k < 48; k++) c += (key[k] >= mid) ? 1 : 0;
        for (int o = 16; o > 0; o >>= 1) c += __shfl_down_sync(0xffffffffu, c, o);
        if ((t & 31) == 0) scnt[t >> 5] = c;
        __syncthreads();
        int tot = scnt[0] + scnt[1] + scnt[2] + scnt[3];
        __syncthreads();
        if (tot >= 20) {
            lo = mid;
            if (tot <= 96) break;
        } else {
            hi = mid;
        }
    }

    __shared__ unsigned long long cand[CAPC];
    __shared__ int cnum;
    cand[t] = 0ull;
    if (t == 0) cnum = 0;
    __syncthreads();
#pragma unroll
    for (int k = 0; k < 48; k++) {
        if (key[k] >= lo) {
            int p = atomicAdd(&cnum, 1);
            if (p < CAPC)
                cand[p] = ((unsigned long long)key[k] << 32) |
                          (unsigned)(~(t + k * 128));
        }
    }
    __syncthreads();

    if (t < 32) {
        for (int it = 0; it < KNNN; it++) {
            unsigned long long best = 0ull;
            int bslot = 0;
#pragma unroll
            for (int s = 0; s < CAPC / 32; s++) {
                unsigned long long c = cand[t + s * 32];
                if (c > best) { best = c; bslot = t + s * 32; }
            }
#pragma unroll
            for (int o = 16; o > 0; o >>= 1) {
                unsigned long long b2 = __shfl_down_sync(0xffffffffu, best, o);
                int s2 = __shfl_down_sync(0xffffffffu, bslot, o);
                if (b2 > best) { best = b2; bslot = s2; }
            }
            bslot = __shfl_sync(0xffffffffu, bslot, 0);
            if (t == 0) {
                unsigned kk = (unsigned)(best >> 32);
                unsigned fb = (kk & 0x80000000u) ? (kk & 0x7fffffffu) : ~kk;
                float raw = __uint_as_float(fb);
                g_val[row * KNNN + it] = 1.0f / (1.0f + expf(-raw));
                g_idx[row * KNNN + it] = (int)(~(unsigned)(best & 0xffffffffu));
                cand[bslot] = 0ull;
            }
            __syncwarp();
        }
    }
}

// ---------------- 5. degrees ----------------
__global__ void k_deg_init() {
    int i = blockIdx.x * 256 + threadIdx.x;
    if (i < NN) g_deg[i] = 1.0f;
}
__global__ void k_deg_scatter() {
    int e = blockIdx.x * 256 + threadIdx.x;
    if (e < NN * KNNN) {
        if (g_val[e] > THRF) atomicAdd(&g_deg[g_idx[e]], 1.0f);
    }
}
__global__ void k_dinv() {
    int i = blockIdx.x * 256 + threadIdx.x;
    if (i < NN) g_dinv[i] = 1.0f / sqrtf(g_deg[i]);
}

// ---------------- 6. GCN layer 1 ----------------
__global__ void k_acc_init() {
    int idx = blockIdx.x * 256 + threadIdx.x;
    int i = idx >> 8;
    g_acc[idx] = g_dinv[i] * g_xw1[idx];
}
__global__ __launch_bounds__(HIDN) void k_scatter1() {
    int i = blockIdx.x, f = threadIdx.x;
    __shared__ int   sj[KNNN];
    __shared__ float sw[KNNN];
    if (f < KNNN) { sj[f] = g_idx[i * KNNN + f]; sw[f] = g_val[i * KNNN + f]; }
    __syncthreads();
    float z = g_dinv[i] * g_xw1[i * HIDN + f];
#pragma unroll
    for (int k = 0; k < KNNN; k++) {
        if (sw[k] > THRF) atomicAdd(&g_acc[sj[k] * HIDN + f], z);
    }
}
__global__ void k_relu(const float* __restrict__ b1) {
    int idx = blockIdx.x * 256 + threadIdx.x;
    int i = idx >> 8, f = idx & 255;
    g_acc[idx] = fmaxf(g_dinv[i] * g_acc[idx] + b1[f], 0.0f);
}

// ---------------- 7. t1 = h @ W2 ----------------
__global__ __launch_bounds__(64) void k_hw2(const float* __restrict__ W2) {
    int i = blockIdx.x, t = threadIdx.x;
    __shared__ float sh[HIDN];
    for (int k = t; k < HIDN; k += 64) sh[k] = g_acc[i * HIDN + k];
    __syncthreads();
    if (t < KMN) {
        float s = 0.f;
#pragma unroll 8
        for (int k = 0; k < HIDN; k++) s += sh[k] * W2[k * KMN + t];
        g_t1[i * KMN + t] = s;
    }
}

// ---------------- 8. GCN layer 2 + softmax ----------------
__global__ __launch_bounds__(64) void k_sacc_init() {
    int i = blockIdx.x, t = threadIdx.x;
    if (t < KMN) g_sacc[i * KMN + t] = g_dinv[i] * g_t1[i * KMN + t];
}
__global__ __launch_bounds__(64) void k_scatter2() {
    int i = blockIdx.x, t = threadIdx.x;
    __shared__ int   sj[KNNN];
    __shared__ float sw[KNNN];
    if (t < KNNN) { sj[t] = g_idx[i * KNNN + t]; sw[t] = g_val[i * KNNN + t]; }
    __syncthreads();
    if (t < KMN) {
        float z = g_dinv[i] * g_t1[i * KMN + t];
#pragma unroll
        for (int k = 0; k < KNNN; k++) {
            if (sw[k] > THRF) atomicAdd(&g_sacc[sj[k] * KMN + t], z);
        }
    }
}
__global__ __launch_bounds__(64) void k_softmax(const float* __restrict__ b2,
                                                float* __restrict__ S) {
    int i = blockIdx.x, t = threadIdx.x;
    __shared__ float red[64];
    float v = (t < KMN) ? g_dinv[i] * g_sacc[i * KMN + t] + b2[t] : -FLT_MAX;
    red[t] = v;
#pragma unroll
    for (int o = 32; o > 0; o >>= 1) {
        __syncthreads();
        if (t < o) red[t] = fmaxf(red[t], red[t + o]);
    }
    __syncthreads();
    float mx = red[0];
    __syncthreads();
    float e = (t < KMN) ? expf(v - mx) : 0.f;
    red[t] = e;
#pragma unroll
    for (int o = 32; o > 0; o >>= 1) {
        __syncthreads();
        if (t < o) red[t] += red[t + o];
    }
    __syncthreads();
    float inv = 1.0f / red[0];
    if (t < KMN) S[i * KMN + t] = e * inv;
}

// ---------------- 9. t2 = adj @ S ----------------
__global__ __launch_bounds__(64) void k_adjS(const float* __restrict__ S) {
    int i = blockIdx.x, t = threadIdx.x;
    __shared__ int   sj[KNNN];
    __shared__ float sw[KNNN];
    if (t < KNNN) { sj[t] = g_idx[i * KNNN + t]; sw[t] = g_val[i * KNNN + t]; }
    __syncthreads();
    if (t < KMN) {
        float a = 0.f;
#pragma unroll
        for (int k = 0; k < KNNN; k++) a += sw[k] * S[sj[k] * KMN + t];
        g_t2[i * KMN + t] = a;
    }
}

// ---------------- 10. A_coarse = S^T @ t2 ----------------
__global__ __launch_bounds__(256) void k_Ac(const float* __restrict__ S) {
    int t = threadIdx.x;
    int r0 = blockIdx.x * 128;
    __shared__ float sS[KMN], sT[KMN];
    float acc[10];
    int c1[10], c2[10]; bool ok[10];
#pragma unroll
    for (int p = 0; p < 10; p++) {
        int e = t + p * 256;
        ok[p] = (e < KMN * KMN);
        c1[p] = ok[p] ? e / KMN : 0;
        c2[p] = ok[p] ? e % KMN : 0;
        acc[p] = 0.f;
    }
    for (int r = 0; r < 128; r++) {
        int i = r0 + r;
        if (t < KMN) sS[t] = S[i * KMN + t];
        else if (t >= 64 && t < 64 + KMN) sT[t - 64] = g_t2[i * KMN + t - 64];
        __syncthreads();
#pragma unroll
        for (int p = 0; p < 10; p++)
            if (ok[p]) acc[p] += sS[c1[p]] * sT[c2[p]];
        __syncthreads();
    }
#pragma unroll
    for (int p = 0; p < 10; p++)
        if (ok[p]) atomicAdd(&g_Ac[t + p * 256], acc[p]);
}

// ---------------- 11. X_t = S^T @ X ----------------
__global__ __launch_bounds__(256) void k_Xt(const float* __restrict__ X,
                                            const float* __restrict__ S,
                                            float* __restrict__ outXt) {
    int t = threadIdx.x;
    int fc = blockIdx.x * 128;
    int r0 = blockIdx.y * 128;
    int f = t & 127, ch = t >> 7;
    __shared__ float sS[KMN];
    __shared__ float sX[128];
    float acc[25];
#pragma unroll
    for (int c = 0; c < 25; c++) acc[c] = 0.f;
    for (int r = 0; r < 128; r++) {
        int i = r0 + r;
        if (t < KMN) sS[t] = S[i * KMN + t];
        if (t >= 128) sX[t - 128] = X[i * FEATN + fc + t - 128];
        __syncthreads();
        float xv = sX[f];
#pragma unroll
        for (int c = 0; c < 25; c++) acc[c] += sS[ch * 25 + c] * xv;
        __syncthreads();
    }
#pragma unroll
    for (int c = 0; c < 25; c++)
        atomicAdd(&outXt[(ch * 25 + c) * FEATN + fc + f], acc[c]);
}

// ---------------- 12. spatial loss ----------------
__global__ __launch_bounds__(256) void k_loss(const float* __restrict__ S,
                                              const float* __restrict__ pos) {
    int warp = (blockIdx.x * 256 + threadIdx.x) >> 5;
    int lane = threadIdx.x & 31;
    if (warp >= NN) return;
    int i = warp;
    float s0 = (lane < KMN) ? S[i * KMN + lane] : 0.f;
    bool has2 = (lane + 32 < KMN);
    float s1 = has2 ? S[i * KMN + lane + 32] : 0.f;
    float xi = pos[2 * i], yi = pos[2 * i + 1];
    float p2i = xi * xi + yi * yi;
    float lsum = 0.f; int cnt = 0;
#pragma unroll
    for (int k = 0; k < KNNN; k++) {
        float v = g_val[i * KNNN + k];
        if (v > THRF) {
            int j = g_idx[i * KNNN + k];
            float xj = pos[2 * j], yj = pos[2 * j + 1];
            float d2 = fmaxf(p2i + xj * xj + yj * yj -
                             2.0f * (xi * xj + yi * yj), 0.0f);
            float dp = s0 * ((lane < KMN) ? S[j * KMN + lane] : 0.f);
            if (has2) dp += s1 * S[j * KMN + lane + 32];
            lsum += d2 * dp;
            cnt++;
        }
    }
#pragma unroll
    for (int o = 16; o > 0; o >>= 1) lsum += __shfl_down_sync(0xffffffffu, lsum, o);
    if (lane == 0) {
        atomicAdd(&g_loss, lsum);
        atomicAdd(&g_E, (float)cnt);
    }
}

// ---------------- zero/init + finalize ----------------
__global__ void k_zero(float* __restrict__ outXt) {
    int idx = blockIdx.x * 256 + threadIdx.x;
    if (idx < KMN * FEATN) outXt[idx] = 0.f;
    if (idx < KMN * KMN) g_Ac[idx] = 0.f;
    if (idx == 0) { g_loss = 0.f; g_E = 0.f; }
}
__global__ void k_final(const float* __restrict__ psw,
                        const float* __restrict__ plam,
                        float* __restrict__ out) {
    int idx = blockIdx.x * 256 + threadIdx.x;
    const int offA = NN * KMN + KMN * FEATN;
    if (idx < KMN * KMN) {
        float a = g_Ac[idx];
        out[offA + idx] = (a > THRF) ? a : 0.f;
    }
    if (idx == 0) {
        out[offA + KMN * KMN] = psw[0] * g_loss / g_E;
        out[offA + KMN * KMN + 1] = 1.0f / (1.0f + expf(-plam[0]));
    }
}

// ---------------- launcher ----------------
extern "C" void kernel_launch(void* const* d_in, const int* in_sizes, int n_in,
                              void* d_out, int out_size) {
    const float* X    = (const float*)d_in[0];
    const float* pos  = (const float*)d_in[1];
    const float* lamw = (const float*)d_in[2];
    const float* temp = (const float*)d_in[3];
    const float* sw   = (const float*)d_in[4];
    const float* W1   = (const float*)d_in[5];
    const float* b1   = (const float*)d_in[6];
    const float* W2   = (const float*)d_in[7];
    const float* b2   = (const float*)d_in[8];
    float* out  = (float*)d_out;
    float* S    = out;              // [N, K]
    float* oXt  = out + NN * KMN;   // [K, FEAT]

    const int SMEM_DYN = 2 * BUFB;  // 147456 B (stage 128*132*4=67584 fits)
    static int s_attr_done = 0;
    if (!s_attr_done) {
        cudaFuncSetAttribute(k_sim_mma, cudaFuncAttributeMaxDynamicSharedMemorySize,
                             SMEM_DYN);
        s_attr_done = 1;
    }

    k_prep<<<NN, 128>>>(X);
    k_xw1<<<dim3(HIDN / 64, NN / 64), 256>>>(X, W1);
    k_sim_mma<<<dim3(NN / 128, NN / 128), 256, SMEM_DYN>>>(pos, lamw, temp);
    k_topk<<<NN, 128>>>();
    k_zero<<<(KMN * FEATN + 255) / 256, 256>>>(oXt);
    k_deg_init<<<NN / 256, 256>>>();
    k_deg_scatter<<<(NN * KNNN + 255) / 256, 256>>>();
    k_dinv<<<NN / 256, 256>>>();
    k_acc_init<<<(NN * HIDN) / 256, 256>>>();
    k_scatter1<<<NN, HIDN>>>();
    k_relu<<<(NN * HIDN) / 256, 256>>>(b1);
    k_hw2<<<NN, 64>>>(W2);
    k_sacc_init<<<NN, 64>>>();
    k_scatter2<<<NN, 64>>>();
    k_softmax<<<NN, 64>>>(b2, S);
    k_adjS<<<NN, 64>>>(S);
    k_Ac<<<NN / 128, 256>>>(S);
    k_Xt<<<dim3(FEATN / 128, NN / 128), 256>>>(X, S, oXt);
    k_loss<<<NN / 8, 256>>>(S, pos);
    k_final<<<(KMN * KMN + 255) / 256, 256>>>(sw, lamw, out);
}

// round 14
// speedup vs baseline: 2.5707x; 1.1728x over previous
#include <cuda_runtime.h>
#include <cuda_fp16.h>
#include <math.h>
#include <float.h>
#include <stdint.h>

// Problem constants
#define NN    6144
#define FEATN 512
#define HIDN  256
#define KMN   50
#define KNNN  20
#define THRF  0.1f
#define INV2SD2 (1.0f/5000.0f)
#define CAPC  128
#define SSTR  72        // smem row stride in fp16 (144B) -> conflict-free
#define TILEB (128*SSTR*2)            // 18432 B per tile
#define BUFB  (3*TILEB)               // 55296 B per buffer (Ahi,Alo,Bhi)

// ---------------- device scratch ----------------
__device__ __half g_fhi[NN * FEATN];
__device__ __half g_flo[NN * FEATN];
__device__ float g_adj[(size_t)NN * NN];           // raw scores (pre-sigmoid)
__device__ float g_xw1[NN * HIDN];
__device__ float g_acc[NN * HIDN];
__device__ float g_t1[NN * KMN];
__device__ float g_deg[NN];
__device__ float g_dinv[NN];
__device__ int   g_idx[NN * KNNN];
__device__ float g_val[NN * KNNN];
__device__ float g_Ac[KMN * KMN];
__device__ float g_loss;
__device__ float g_E;
// CSC (transpose adjacency) for gather-based GCN
__device__ int   g_coff[NN + 1];
__device__ int   g_ccnt[NN];
__device__ int   g_csrc[NN * KNNN];

// ---------------- PTX helpers (baseline ISA, valid on compute_103) -----
__device__ __forceinline__ void mma16816(float* d, const uint32_t* a,
                                         const uint32_t* b) {
    asm volatile(
        "mma.sync.aligned.m16n8k16.row.col.f32.f16.f16.f32 "
        "{%0,%1,%2,%3}, {%4,%5,%6,%7}, {%8,%9}, {%0,%1,%2,%3};"
        : "+f"(d[0]), "+f"(d[1]), "+f"(d[2]), "+f"(d[3])
        : "r"(a[0]), "r"(a[1]), "r"(a[2]), "r"(a[3]), "r"(b[0]), "r"(b[1]));
}
__device__ __forceinline__ uint32_t smem_u32(const void* p) {
    uint32_t a;
    asm("{ .reg .u64 t; cvta.to.shared.u64 t, %1; cvt.u32.u64 %0, t; }"
        : "=r"(a) : "l"(p));
    return a;
}
#define LDMX4(r, addr) asm volatile( \
    "ldmatrix.sync.aligned.m8n8.x4.shared.b16 {%0,%1,%2,%3}, [%4];" \
    : "=r"((r)[0]), "=r"((r)[1]), "=r"((r)[2]), "=r"((r)[3]) : "r"(addr))
#define CP16(saddr, gptr) asm volatile( \
    "cp.async.cg.shared.global [%0], [%1], 16;" :: "r"(saddr), "l"(gptr))
#define CP_COMMIT() asm volatile("cp.async.commit_group;" ::: "memory")

// ---------------- 1. normalize rows + fp16 hi/lo split ----------------
__global__ __launch_bounds__(128) void k_prep(const float* __restrict__ X) {
    int row = blockIdx.x, t = threadIdx.x;
    const float* xr = X + row * FEATN;
    float ss = 0.f;
    for (int f = t; f < FEATN; f += 128) { float v = xr[f]; ss += v * v; }
    for (int o = 16; o > 0; o >>= 1) ss += __shfl_down_sync(0xffffffffu, ss, o);
    __shared__ float red[4];
    __shared__ float sinv;
    if ((t & 31) == 0) red[t >> 5] = ss;
    __syncthreads();
    if (t == 0) {
        float s = red[0] + red[1] + red[2] + red[3];
        sinv = 1.0f / fmaxf(sqrtf(s), 1e-12f);
    }
    __syncthreads();
    float inv = sinv;
    for (int f = t; f < FEATN; f += 128) {
        float v = xr[f] * inv;
        __half h = __float2half_rn(v);
        g_fhi[row * FEATN + f] = h;
        g_flo[row * FEATN + f] = __float2half_rn(v - __half2float(h));
    }
}

// ---------------- 2. XW1 = X @ W1 ----------------
__global__ __launch_bounds__(256) void k_xw1(const float* __restrict__ X,
                                             const float* __restrict__ W1) {
    __shared__ float As[16][64];
    __shared__ float Bs[16][64];
    int tid = threadIdx.x;
    int bi = blockIdx.y * 64, bj = blockIdx.x * 64;
    int tx = tid & 15, ty = tid >> 4;
    int ar_ = tid >> 2, ac_ = (tid & 3) << 2;
    int br_ = tid >> 4, bc_ = (tid & 15) << 2;
    float acc[4][4];
#pragma unroll
    for (int m = 0; m < 4; m++)
#pragma unroll
        for (int n = 0; n < 4; n++) acc[m][n] = 0.f;

    for (int k0 = 0; k0 < FEATN; k0 += 16) {
        float4 a = *(const float4*)(X + (bi + ar_) * FEATN + k0 + ac_);
        As[ac_ + 0][ar_] = a.x; As[ac_ + 1][ar_] = a.y;
        As[ac_ + 2][ar_] = a.z; As[ac_ + 3][ar_] = a.w;
        float4 b = *(const float4*)(W1 + (k0 + br_) * HIDN + bj + bc_);
        *(float4*)&Bs[br_][bc_] = b;
        __syncthreads();
#pragma unroll
        for (int k = 0; k < 16; k++) {
            float av[4], bv[4];
#pragma unroll
            for (int m = 0; m < 4; m++) av[m] = As[k][ty * 4 + m];
#pragma unroll
            for (int n = 0; n < 4; n++) bv[n] = Bs[k][tx * 4 + n];
#pragma unroll
            for (int m = 0; m < 4; m++)
#pragma unroll
                for (int n = 0; n < 4; n++) acc[m][n] += av[m] * bv[n];
        }
        __syncthreads();
    }
#pragma unroll
    for (int m = 0; m < 4; m++)
#pragma unroll
        for (int n = 0; n < 4; n++)
            g_xw1[(bi + ty * 4 + m) * HIDN + bj + tx * 4 + n] = acc[m][n];
}

// ---------------- 3. sim: fp16 hi/lo mma (2 terms) + pipeline + symmetry ----
// D ~= hiA.hiB^T + loA.hiB^T   (err ~6e-6 << 1.1e-3 rank gap)
// raw = lam*T*D + (1-lam)*T*exp(-d2/5000); upper-triangle tiles, mirrored.
__global__ __launch_bounds__(256, 2) void k_sim_mma(const float* __restrict__ pos,
                                                    const float* __restrict__ plam,
                                                    const float* __restrict__ ptemp) {
    if (blockIdx.y > blockIdx.x) return;    // symmetry: compute bj >= bi only
    extern __shared__ char dyn[];
    __shared__ float cpx[128], cpy[128], rpx[128], rpy[128];

    int t = threadIdx.x, w = t >> 5, lane = t & 31;
    int bi = blockIdx.y * 128, bj = blockIdx.x * 128;
    bool offdiag = (blockIdx.x != blockIdx.y);
    int wm = w & 3, wn = w >> 2;            // 4(M) x 2(N) warp grid

    if (t < 128) {
        cpx[t] = pos[2 * (bj + t)];
        cpy[t] = pos[2 * (bj + t) + 1];
    } else {
        int u = t - 128;
        rpx[u] = pos[2 * (bi + u)];
        rpy[u] = pos[2 * (bi + u) + 1];
    }

    float acc[2][8][4];
#pragma unroll
    for (int mi = 0; mi < 2; mi++)
#pragma unroll
        for (int ni = 0; ni < 8; ni++)
#pragma unroll
            for (int r = 0; r < 4; r++) acc[mi][ni][r] = 0.f;

    uint32_t dynb = smem_u32(dyn);
    int lrow = t >> 1;
    int lch = (t & 1) * 4;                  // 16B chunks [lch, lch+4)

    const __half* Ah0 = g_fhi + (size_t)(bi + lrow) * FEATN;
    const __half* Al0 = g_flo + (size_t)(bi + lrow) * FEATN;
    const __half* Bh0 = g_fhi + (size_t)(bj + lrow) * FEATN;

    auto issue = [&](int c, int buf) {
        int kc = c * 64;
        uint32_t sb = dynb + buf * BUFB + lrow * (SSTR * 2);
#pragma unroll
        for (int j = 0; j < 4; j++) {
            int ch = lch + j;
            uint32_t off = sb + ch * 16;
            CP16(off,             Ah0 + kc + ch * 8);
            CP16(off + TILEB,     Al0 + kc + ch * 8);
            CP16(off + 2 * TILEB, Bh0 + kc + ch * 8);
        }
        CP_COMMIT();
    };

    issue(0, 0);
#pragma unroll 1
    for (int c = 0; c < 8; c++) {
        if (c < 7) {
            issue(c + 1, (c + 1) & 1);
            asm volatile("cp.async.wait_group 1;" ::: "memory");
        } else {
            asm volatile("cp.async.wait_group 0;" ::: "memory");
        }
        __syncthreads();
        uint32_t tb = dynb + (c & 1) * BUFB;
        int m = lane >> 3, r8 = lane & 7;
#pragma unroll
        for (int k16 = 0; k16 < 4; k16++) {
            int kb = k16 * 16;
            uint32_t ah[2][4], al[2][4], bf[8][2];
#pragma unroll
            for (int mi = 0; mi < 2; mi++) {
                int R = wm * 32 + mi * 16;
                uint32_t aoff = ((R + (m & 1) * 8 + r8) * SSTR + kb + (m >> 1) * 8) * 2;
                LDMX4(ah[mi], tb + aoff);
                LDMX4(al[mi], tb + TILEB + aoff);
            }
#pragma unroll
            for (int p = 0; p < 4; p++) {
                int n0 = wn * 64 + p * 16;
                uint32_t boff = ((n0 + (m >> 1) * 8 + r8) * SSTR + kb + (m & 1) * 8) * 2;
                LDMX4(&bf[2 * p][0], tb + 2 * TILEB + boff);
            }
#pragma unroll
            for (int mi = 0; mi < 2; mi++)
#pragma unroll
                for (int ni = 0; ni < 8; ni++) {
                    mma16816(acc[mi][ni], ah[mi], bf[ni]);   // hi.hi
                    mma16816(acc[mi][ni], al[mi], bf[ni]);   // lo.hi
                }
        }
        __syncthreads();
    }

    // epilogue: raw scores; direct write + (off-diag) transpose stage
    float lam = 1.0f / (1.0f + expf(-plam[0]));
    float T = ptemp[0];
    float aC = lam * T, bC = (1.0f - lam) * T;
    float* stage = (float*)dyn;             // 128 x (stride 132) floats
#pragma unroll
    for (int mi = 0; mi < 2; mi++) {
#pragma unroll
        for (int rr = 0; rr < 2; rr++) {
            int r = wm * 32 + mi * 16 + rr * 8 + (lane >> 2);
            float xi = rpx[r], yi = rpy[r];
            float p2i = xi * xi + yi * yi;
            size_t gro = (size_t)(bi + r) * NN + bj;
#pragma unroll
            for (int ni = 0; ni < 8; ni++) {
                int c = wn * 64 + ni * 8 + (lane & 3) * 2;
                float xj0 = cpx[c], yj0 = cpy[c];
                float xj1 = cpx[c + 1], yj1 = cpy[c + 1];
                float d20 = fmaxf(p2i + xj0 * xj0 + yj0 * yj0 -
                                  2.0f * (xi * xj0 + yi * yj0), 0.0f);
                float d21 = fmaxf(p2i + xj1 * xj1 + yj1 * yj1 -
                                  2.0f * (xi * xj1 + yi * yj1), 0.0f);
                float2 o;
                o.x = aC * acc[mi][ni][rr * 2 + 0] + bC * __expf(-d20 * INV2SD2);
                o.y = aC * acc[mi][ni][rr * 2 + 1] + bC * __expf(-d21 * INV2SD2);
                *(float2*)&g_adj[gro + c] = o;
                if (offdiag) {
                    stage[c * 132 + r] = o.x;
                    stage[(c + 1) * 132 + r] = o.y;
                }
            }
        }
    }
    if (offdiag) {
        __syncthreads();
#pragma unroll
        for (int j = 0; j < 16; j++) {
            int idx4 = t + j * 256;
            int cc = idx4 >> 5, r4 = (idx4 & 31) * 4;
            float4 v = *(float4*)&stage[cc * 132 + r4];
            *(float4*)&g_adj[(size_t)(bj + cc) * NN + bi + r4] = v;
        }
    }
}

// ---------------- 4. row-wise exact top-20 (float4 + binary search) -----
__global__ __launch_bounds__(128) void k_topk() {
    int row = blockIdx.x, t = threadIdx.x;
    const float4* r4 = (const float4*)(g_adj + (size_t)row * NN);

    unsigned key[48];
#pragma unroll
    for (int kk = 0; kk < 12; kk++) {
        float4 v = r4[t + kk * 128];
        float e[4] = { v.x, v.y, v.z, v.w };
#pragma unroll
        for (int q = 0; q < 4; q++) {
            unsigned b = __float_as_uint(e[q]);
            key[kk * 4 + q] = (b & 0x80000000u) ? ~b : (b | 0x80000000u);
        }
    }

    __shared__ int scnt[4];
    __shared__ unsigned smm[8];

    unsigned kmin = key[0], kmax = key[0];
#pragma unroll
    for (int k = 1; k < 48; k++) {
        kmin = min(kmin, key[k]);
        kmax = max(kmax, key[k]);
    }
    for (int o = 16; o > 0; o >>= 1) {
        kmin = min(kmin, __shfl_down_sync(0xffffffffu, kmin, o));
        kmax = max(kmax, __shfl_down_sync(0xffffffffu, kmax, o));
    }
    if ((t & 31) == 0) { smm[t >> 5] = kmin; smm[4 + (t >> 5)] = kmax; }
    __syncthreads();
    unsigned lo = min(min(smm[0], smm[1]), min(smm[2], smm[3]));
    unsigned hi = max(max(smm[4], smm[5]), max(smm[6], smm[7]));
    if (hi != 0xffffffffu) hi += 1;
    __syncthreads();

    for (int it = 0; it < 34; it++) {
        if (hi - lo <= 1) break;
        unsigned mid = lo + ((hi - lo) >> 1);
        int c = 0;
#pragma unroll
        for (int k = 0; k < 48; k++) c += (key[k] >= mid) ? 1 : 0;
        for (int o = 16; o > 0; o >>= 1) c += __shfl_down_sync(0xffffffffu, c, o);
        if ((t & 31) == 0) scnt[t >> 5] = c;
        __syncthreads();
        int tot = scnt[0] + scnt[1] + scnt[2] + scnt[3];
        __syncthreads();
        if (tot >= 20) {
            lo = mid;
            if (tot <= 96) break;
        } else {
            hi = mid;
        }
    }

    __shared__ unsigned long long cand[CAPC];
    __shared__ int cnum;
    cand[t] = 0ull;
    if (t == 0) cnum = 0;
    __syncthreads();
#pragma unroll
    for (int k = 0; k < 48; k++) {
        if (key[k] >= lo) {
            int gidx = ((t + (k >> 2) * 128) << 2) + (k & 3);
            int p = atomicAdd(&cnum, 1);
            if (p < CAPC)
                cand[p] = ((unsigned long long)key[k] << 32) | (unsigned)(~gidx);
        }
    }
    __syncthreads();

    if (t < 32) {
        for (int it = 0; it < KNNN; it++) {
            unsigned long long best = 0ull;
            int bslot = 0;
#pragma unroll
            for (int s = 0; s < CAPC / 32; s++) {
                unsigned long long c = cand[t + s * 32];
                if (c > best) { best = c; bslot = t + s * 32; }
            }
#pragma unroll
            for (int o = 16; o > 0; o >>= 1) {
                unsigned long long b2 = __shfl_down_sync(0xffffffffu, best, o);
                int s2 = __shfl_down_sync(0xffffffffu, bslot, o);
                if (b2 > best) { best = b2; bslot = s2; }
            }
            bslot = __shfl_sync(0xffffffffu, bslot, 0);
            if (t == 0) {
                unsigned kk = (unsigned)(best >> 32);
                unsigned fb = (kk & 0x80000000u) ? (kk & 0x7fffffffu) : ~kk;
                float raw = __uint_as_float(fb);
                g_val[row * KNNN + it] = 1.0f / (1.0f + expf(-raw));
                g_idx[row * KNNN + it] = (int)(~(unsigned)(best & 0xffffffffu));
                cand[bslot] = 0ull;
            }
            __syncwarp();
        }
    }
}

// ---------------- 5. degrees + CSC build ----------------
__global__ void k_deg_init() {
    int i = blockIdx.x * 256 + threadIdx.x;
    if (i < NN) { g_deg[i] = 1.0f; g_ccnt[i] = 0; }
}
__global__ void k_deg_scatter() {
    int e = blockIdx.x * 256 + threadIdx.x;
    if (e < NN * KNNN) {
        if (g_val[e] > THRF) atomicAdd(&g_deg[g_idx[e]], 1.0f);
    }
}
__global__ void k_dinv() {
    int i = blockIdx.x * 256 + threadIdx.x;
    if (i < NN) g_dinv[i] = 1.0f / sqrtf(g_deg[i]);
}
// exclusive scan of edge counts (deg-1) over 6144 targets; one block
__global__ __launch_bounds__(256) void k_scan() {
    __shared__ int part[256];
    int t = threadIdx.x;
    int base = t * 24;
    int loc[24];
    int s = 0;
#pragma unroll
    for (int u = 0; u < 24; u++) {
        loc[u] = s;
        s += (int)g_deg[base + u] - 1;
    }
    part[t] = s;
    __syncthreads();
    for (int o = 1; o < 256; o <<= 1) {
        int v = (t >= o) ? part[t - o] : 0;
        __syncthreads();
        part[t] += v;
        __syncthreads();
    }
    int pre = (t == 0) ? 0 : part[t - 1];
#pragma unroll
    for (int u = 0; u < 24; u++) g_coff[base + u] = pre + loc[u];
    if (t == 255) g_coff[NN] = part[255];
}
__global__ void k_fill() {
    int e = blockIdx.x * 256 + threadIdx.x;
    if (e < NN * KNNN && g_val[e] > THRF) {
        int j = g_idx[e];
        int p = atomicAdd(&g_ccnt[j], 1);
        g_csrc[g_coff[j] + p] = e / KNNN;
    }
}

// ---------------- 6. GCN layer 1 (gather) : h = relu(Mn^T Z + b1) ----------
__global__ __launch_bounds__(HIDN) void k_gather1(const float* __restrict__ b1) {
    int j = blockIdx.x, f = threadIdx.x;
    float dj = g_dinv[j];
    float s = dj * g_xw1[j * HIDN + f];
    int e0 = g_coff[j], e1 = g_coff[j + 1];
    for (int e = e0; e < e1; e++) {
        int i = g_csrc[e];
        s += g_dinv[i] * g_xw1[i * HIDN + f];
    }
    g_acc[j * HIDN + f] = fmaxf(dj * s + b1[f], 0.0f);
}

// ---------------- 7. t1 = h @ W2 ----------------
__global__ __launch_bounds__(64) void k_hw2(const float* __restrict__ W2) {
    int i = blockIdx.x, t = threadIdx.x;
    __shared__ float sh[HIDN];
    for (int k = t; k < HIDN; k += 64) sh[k] = g_acc[i * HIDN + k];
    __syncthreads();
    if (t < KMN) {
        float s = 0.f;
#pragma unroll 8
        for (int k = 0; k < HIDN; k++) s += sh[k] * W2[k * KMN + t];
        g_t1[i * KMN + t] = s;
    }
}

// ---------------- 8. GCN layer 2 (gather) + softmax -> S ----------------
__global__ __launch_bounds__(64) void k_g2soft(const float* __restrict__ b2,
                                               float* __restrict__ S) {
    int j = blockIdx.x, t = threadIdx.x;
    float dj = g_dinv[j];
    float s = (t < KMN) ? dj * g_t1[j * KMN + t] : 0.f;
    int e0 = g_coff[j], e1 = g_coff[j + 1];
    for (int e = e0; e < e1; e++) {
        int i = g_csrc[e];
        if (t < KMN) s += g_dinv[i] * g_t1[i * KMN + t];
    }
    float v = (t < KMN) ? dj * s + b2[t] : -FLT_MAX;
    __shared__ float red[64];
    red[t] = v;
#pragma unroll
    for (int o = 32; o > 0; o >>= 1) {
        __syncthreads();
        if (t < o) red[t] = fmaxf(red[t], red[t + o]);
    }
    __syncthreads();
    float mx = red[0];
    __syncthreads();
    float e2 = (t < KMN) ? expf(v - mx) : 0.f;
    red[t] = e2;
#pragma unroll
    for (int o = 32; o > 0; o >>= 1) {
        __syncthreads();
        if (t < o) red[t] += red[t + o];
    }
    __syncthreads();
    float inv = 1.0f / red[0];
    if (t < KMN) S[j * KMN + t] = e2 * inv;
}

// ---------------- 9. t2 = adj @ S (sparse) -> reuse g_t1 slot? keep own ----
__device__ float g_t2[NN * KMN];
__global__ __launch_bounds__(64) void k_adjS(const float* __restrict__ S) {
    int i = blockIdx.x, t = threadIdx.x;
    __shared__ int   sj[KNNN];
    __shared__ float sw[KNNN];
    if (t < KNNN) { sj[t] = g_idx[i * KNNN + t]; sw[t] = g_val[i * KNNN + t]; }
    __syncthreads();
    if (t < KMN) {
        float a = 0.f;
#pragma unroll
        for (int k = 0; k < KNNN; k++) a += sw[k] * S[sj[k] * KMN + t];
        g_t2[i * KMN + t] = a;
    }
}

// ---------------- 10. A_coarse = S^T @ t2 ----------------
__global__ __launch_bounds__(256) void k_Ac(const float* __restrict__ S) {
    int t = threadIdx.x;
    int r0 = blockIdx.x * 128;
    __shared__ float sS[KMN], sT[KMN];
    float acc[10];
    int c1[10], c2[10]; bool ok[10];
#pragma unroll
    for (int p = 0; p < 10; p++) {
        int e = t + p * 256;
        ok[p] = (e < KMN * KMN);
        c1[p] = ok[p] ? e / KMN : 0;
        c2[p] = ok[p] ? e % KMN : 0;
        acc[p] = 0.f;
    }
    for (int r = 0; r < 128; r++) {
        int i = r0 + r;
        if (t < KMN) sS[t] = S[i * KMN + t];
        else if (t >= 64 && t < 64 + KMN) sT[t - 64] = g_t2[i * KMN + t - 64];
        __syncthreads();
#pragma unroll
        for (int p = 0; p < 10; p++)
            if (ok[p]) acc[p] += sS[c1[p]] * sT[c2[p]];
        __syncthreads();
    }
#pragma unroll
    for (int p = 0; p < 10; p++)
        if (ok[p]) atomicAdd(&g_Ac[t + p * 256], acc[p]);
}

// ---------------- 11. X_t = S^T @ X ----------------
__global__ __launch_bounds__(256) void k_Xt(const float* __restrict__ X,
                                            const float* __restrict__ S,
                                            float* __restrict__ outXt) {
    int t = threadIdx.x;
    int fc = blockIdx.x * 128;
    int r0 = blockIdx.y * 128;
    int f = t & 127, ch = t >> 7;
    __shared__ float sS[KMN];
    __shared__ float sX[128];
    float acc[25];
#pragma unroll
    for (int c = 0; c < 25; c++) acc[c] = 0.f;
    for (int r = 0; r < 128; r++) {
        int i = r0 + r;
        if (t < KMN) sS[t] = S[i * KMN + t];
        if (t >= 128) sX[t - 128] = X[i * FEATN + fc + t - 128];
        __syncthreads();
        float xv = sX[f];
#pragma unroll
        for (int c = 0; c < 25; c++) acc[c] += sS[ch * 25 + c] * xv;
        __syncthreads();
    }
#pragma unroll
    for (int c = 0; c < 25; c++)
        atomicAdd(&outXt[(ch * 25 + c) * FEATN + fc + f], acc[c]);
}

// ---------------- 12. spatial loss ----------------
__global__ __launch_bounds__(256) void k_loss(const float* __restrict__ S,
                                              const float* __restrict__ pos) {
    int warp = (blockIdx.x * 256 + threadIdx.x) >> 5;
    int lane = threadIdx.x & 31;
    if (warp >= NN) return;
    int i = warp;
    float s0 = (lane < KMN) ? S[i * KMN + lane] : 0.f;
    bool has2 = (lane + 32 < KMN);
    float s1 = has2 ? S[i * KMN + lane + 32] : 0.f;
    float xi = pos[2 * i], yi = pos[2 * i + 1];
    float p2i = xi * xi + yi * yi;
    float lsum = 0.f; int cnt = 0;
#pragma unroll
    for (int k = 0; k < KNNN; k++) {
        float v = g_val[i * KNNN + k];
        if (v > THRF) {
            int j = g_idx[i * KNNN + k];
            float xj = pos[2 * j], yj = pos[2 * j + 1];
            float d2 = fmaxf(p2i + xj * xj + yj * yj -
                             2.0f * (xi * xj + yi * yj), 0.0f);
            float dp = s0 * ((lane < KMN) ? S[j * KMN + lane] : 0.f);
            if (has2) dp += s1 * S[j * KMN + lane + 32];
            lsum += d2 * dp;
            cnt++;
        }
    }
#pragma unroll
    for (int o = 16; o > 0; o >>= 1) lsum += __shfl_down_sync(0xffffffffu, lsum, o);
    if (lane == 0) {
        atomicAdd(&g_loss, lsum);
        atomicAdd(&g_E, (float)cnt);
    }
}

// ---------------- zero/init + finalize ----------------
__global__ void k_zero(float* __restrict__ outXt) {
    int idx = blockIdx.x * 256 + threadIdx.x;
    if (idx < KMN * FEATN) outXt[idx] = 0.f;
    if (idx < KMN * KMN) g_Ac[idx] = 0.f;
    if (idx == 0) { g_loss = 0.f; g_E = 0.f; }
}
__global__ void k_final(const float* __restrict__ psw,
                        const float* __restrict__ plam,
                        float* __restrict__ out) {
    int idx = blockIdx.x * 256 + threadIdx.x;
    const int offA = NN * KMN + KMN * FEATN;
    if (idx < KMN * KMN) {
        float a = g_Ac[idx];
        out[offA + idx] = (a > THRF) ? a : 0.f;
    }
    if (idx == 0) {
        out[offA + KMN * KMN] = psw[0] * g_loss / g_E;
        out[offA + KMN * KMN + 1] = 1.0f / (1.0f + expf(-plam[0]));
    }
}

// ---------------- launcher ----------------
extern "C" void kernel_launch(void* const* d_in, const int* in_sizes, int n_in,
                              void* d_out, int out_size) {
    const float* X    = (const float*)d_in[0];
    const float* pos  = (const float*)d_in[1];
    const float* lamw = (const float*)d_in[2];
    const float* temp = (const float*)d_in[3];
    const float* sw   = (const float*)d_in[4];
    const float* W1   = (const float*)d_in[5];
    const float* b1   = (const float*)d_in[6];
    const float* W2   = (const float*)d_in[7];
    const float* b2   = (const float*)d_in[8];
    float* out  = (float*)d_out;
    float* S    = out;              // [N, K]
    float* oXt  = out + NN * KMN;   // [K, FEAT]

    const int SMEM_DYN = 2 * BUFB;  // 110592 B (stage 128*132*4=67584 fits)
    static int s_attr_done = 0;
    if (!s_attr_done) {
        cudaFuncSetAttribute(k_sim_mma, cudaFuncAttributeMaxDynamicSharedMemorySize,
                             SMEM_DYN);
        s_attr_done = 1;
    }

    k_prep<<<NN, 128>>>(X);
    k_xw1<<<dim3(HIDN / 64, NN / 64), 256>>>(X, W1);
    k_sim_mma<<<dim3(NN / 128, NN / 128), 256, SMEM_DYN>>>(pos, lamw, temp);
    k_topk<<<NN, 128>>>();
    k_zero<<<(KMN * FEATN + 255) / 256, 256>>>(oXt);
    k_deg_init<<<NN / 256, 256>>>();
    k_deg_scatter<<<(NN * KNNN + 255) / 256, 256>>>();
    k_scan<<<1, 256>>>();
    k_dinv<<<NN / 256, 256>>>();
    k_fill<<<(NN * KNNN + 255) / 256, 256>>>();
    k_gather1<<<NN, HIDN>>>(b1);
    k_hw2<<<NN, 64>>>(W2);
    k_g2soft<<<NN, 64>>>(b2, S);
    k_adjS<<<NN, 64>>>(S);
    k_Ac<<<NN / 128, 256>>>(S);
    k_Xt<<<dim3(FEATN / 128, NN / 128), 256>>>(X, S, oXt);
    k_loss<<<NN / 8, 256>>>(S, pos);
    k_final<<<(KMN * KMN + 255) / 256, 256>>>(sw, lamw, out);
}

// round 15
// speedup vs baseline: 2.7323x; 1.0629x over previous
#include <cuda_runtime.h>
#include <cuda_fp16.h>
#include <math.h>
#include <float.h>
#include <stdint.h>

// Problem constants
#define NN    6144
#define FEATN 512
#define HIDN  256
#define KMN   50
#define KNNN  20
#define THRF  0.1f
#define INV2SD2 (1.0f/5000.0f)
#define CAPC  128
#define SSTR  72        // smem row stride in fp16 (144B) -> conflict-free
#define TILEB (128*SSTR*2)            // 18432 B per tile
#define BUFB  (3*TILEB)               // sim buffer (Ahi,Alo,Bhi)
#define BUF4  (4*TILEB)               // xw1 buffer (Ahi,Alo,Bhi,Blo)

// ---------------- device scratch ----------------
__device__ __half g_fhi[NN * FEATN];   // normalized features hi
__device__ __half g_flo[NN * FEATN];   // normalized features lo
__device__ __half g_xhi[NN * FEATN];   // raw X hi
__device__ __half g_xlo[NN * FEATN];   // raw X lo
__device__ __half g_w1hi[HIDN * FEATN];  // W1^T hi  [n][k]
__device__ __half g_w1lo[HIDN * FEATN];  // W1^T lo
__device__ float g_adj[(size_t)NN * NN];           // raw scores (pre-sigmoid)
__device__ float g_xw1[NN * HIDN];
__device__ float g_acc[NN * HIDN];
__device__ float g_t1[NN * KMN];
__device__ float g_t2[NN * KMN];
__device__ float g_deg[NN];
__device__ float g_dinv[NN];
__device__ int   g_idx[NN * KNNN];
__device__ float g_val[NN * KNNN];
__device__ float g_Ac[KMN * KMN];
__device__ float g_loss;
__device__ float g_E;
// CSC (transpose adjacency) for gather-based GCN
__device__ int   g_coff[NN + 1];
__device__ int   g_ccnt[NN];
__device__ int   g_csrc[NN * KNNN];

// ---------------- PTX helpers (baseline ISA, valid on compute_103) -----
__device__ __forceinline__ void mma16816(float* d, const uint32_t* a,
                                         const uint32_t* b) {
    asm volatile(
        "mma.sync.aligned.m16n8k16.row.col.f32.f16.f16.f32 "
        "{%0,%1,%2,%3}, {%4,%5,%6,%7}, {%8,%9}, {%0,%1,%2,%3};"
        : "+f"(d[0]), "+f"(d[1]), "+f"(d[2]), "+f"(d[3])
        : "r"(a[0]), "r"(a[1]), "r"(a[2]), "r"(a[3]), "r"(b[0]), "r"(b[1]));
}
__device__ __forceinline__ uint32_t smem_u32(const void* p) {
    uint32_t a;
    asm("{ .reg .u64 t; cvta.to.shared.u64 t, %1; cvt.u32.u64 %0, t; }"
        : "=r"(a) : "l"(p));
    return a;
}
#define LDMX4(r, addr) asm volatile( \
    "ldmatrix.sync.aligned.m8n8.x4.shared.b16 {%0,%1,%2,%3}, [%4];" \
    : "=r"((r)[0]), "=r"((r)[1]), "=r"((r)[2]), "=r"((r)[3]) : "r"(addr))
#define CP16(saddr, gptr) asm volatile( \
    "cp.async.cg.shared.global [%0], [%1], 16;" :: "r"(saddr), "l"(gptr))
#define CP_COMMIT() asm volatile("cp.async.commit_group;" ::: "memory")

// ---------------- 1. normalize rows + fp16 hi/lo splits (norm & raw) -------
__global__ __launch_bounds__(128) void k_prep(const float* __restrict__ X) {
    int row = blockIdx.x, t = threadIdx.x;
    const float* xr = X + row * FEATN;
    float ss = 0.f;
    for (int f = t; f < FEATN; f += 128) { float v = xr[f]; ss += v * v; }
    for (int o = 16; o > 0; o >>= 1) ss += __shfl_down_sync(0xffffffffu, ss, o);
    __shared__ float red[4];
    __shared__ float sinv;
    if ((t & 31) == 0) red[t >> 5] = ss;
    __syncthreads();
    if (t == 0) {
        float s = red[0] + red[1] + red[2] + red[3];
        sinv = 1.0f / fmaxf(sqrtf(s), 1e-12f);
    }
    __syncthreads();
    float inv = sinv;
    for (int f = t; f < FEATN; f += 128) {
        float xv = xr[f];
        __half xh = __float2half_rn(xv);
        g_xhi[row * FEATN + f] = xh;
        g_xlo[row * FEATN + f] = __float2half_rn(xv - __half2float(xh));
        float v = xv * inv;
        __half h = __float2half_rn(v);
        g_fhi[row * FEATN + f] = h;
        g_flo[row * FEATN + f] = __float2half_rn(v - __half2float(h));
    }
}

// ---------------- 1b. W1 transpose + fp16 hi/lo split ----------------
__global__ void k_w1t(const float* __restrict__ W1) {
    int idx = blockIdx.x * 256 + threadIdx.x;   // 512*256
    if (idx >= FEATN * HIDN) return;
    int k = idx >> 8, n = idx & 255;
    float v = W1[idx];                          // W1[k][n], coalesced read
    __half h = __float2half_rn(v);
    g_w1hi[n * FEATN + k] = h;
    g_w1lo[n * FEATN + k] = __float2half_rn(v - __half2float(h));
}

// ---------------- 2. XW1 = X @ W1 via fp16 hi/lo mma (3 terms) -------------
__global__ __launch_bounds__(256) void k_xw1_mma() {
    extern __shared__ char dyn[];
    int t = threadIdx.x, w = t >> 5, lane = t & 31;
    int bi = blockIdx.y * 128, bj = blockIdx.x * 128;
    int wm = w & 3, wn = w >> 2;

    float acc[2][8][4];
#pragma unroll
    for (int mi = 0; mi < 2; mi++)
#pragma unroll
        for (int ni = 0; ni < 8; ni++)
#pragma unroll
            for (int r = 0; r < 4; r++) acc[mi][ni][r] = 0.f;

    uint32_t dynb = smem_u32(dyn);
    int lrow = t >> 1;
    int lch = (t & 1) * 4;

    const __half* Ah0 = g_xhi + (size_t)(bi + lrow) * FEATN;
    const __half* Al0 = g_xlo + (size_t)(bi + lrow) * FEATN;
    const __half* Bh0 = g_w1hi + (size_t)(bj + lrow) * FEATN;
    const __half* Bl0 = g_w1lo + (size_t)(bj + lrow) * FEATN;

    auto issue = [&](int c, int buf) {
        int kc = c * 64;
        uint32_t sb = dynb + buf * BUF4 + lrow * (SSTR * 2);
#pragma unroll
        for (int j = 0; j < 4; j++) {
            int ch = lch + j;
            uint32_t off = sb + ch * 16;
            CP16(off,             Ah0 + kc + ch * 8);
            CP16(off + TILEB,     Al0 + kc + ch * 8);
            CP16(off + 2 * TILEB, Bh0 + kc + ch * 8);
            CP16(off + 3 * TILEB, Bl0 + kc + ch * 8);
        }
        CP_COMMIT();
    };

    issue(0, 0);
#pragma unroll 1
    for (int c = 0; c < 8; c++) {
        if (c < 7) {
            issue(c + 1, (c + 1) & 1);
            asm volatile("cp.async.wait_group 1;" ::: "memory");
        } else {
            asm volatile("cp.async.wait_group 0;" ::: "memory");
        }
        __syncthreads();
        uint32_t tb = dynb + (c & 1) * BUF4;
        int m = lane >> 3, r8 = lane & 7;
#pragma unroll
        for (int k16 = 0; k16 < 4; k16++) {
            int kb = k16 * 16;
            uint32_t ah[2][4], al[2][4], bf[8][2];
#pragma unroll
            for (int mi = 0; mi < 2; mi++) {
                int R = wm * 32 + mi * 16;
                uint32_t aoff = ((R + (m & 1) * 8 + r8) * SSTR + kb + (m >> 1) * 8) * 2;
                LDMX4(ah[mi], tb + aoff);
                LDMX4(al[mi], tb + TILEB + aoff);
            }
#pragma unroll
            for (int p = 0; p < 4; p++) {
                int n0 = wn * 64 + p * 16;
                uint32_t boff = ((n0 + (m >> 1) * 8 + r8) * SSTR + kb + (m & 1) * 8) * 2;
                LDMX4(&bf[2 * p][0], tb + 2 * TILEB + boff);
            }
#pragma unroll
            for (int mi = 0; mi < 2; mi++)
#pragma unroll
                for (int ni = 0; ni < 8; ni++) {
                    mma16816(acc[mi][ni], ah[mi], bf[ni]);   // hi.hi
                    mma16816(acc[mi][ni], al[mi], bf[ni]);   // lo.hi
                }
#pragma unroll
            for (int p = 0; p < 4; p++) {
                int n0 = wn * 64 + p * 16;
                uint32_t boff = ((n0 + (m >> 1) * 8 + r8) * SSTR + kb + (m & 1) * 8) * 2;
                LDMX4(&bf[2 * p][0], tb + 3 * TILEB + boff);
            }
#pragma unroll
            for (int mi = 0; mi < 2; mi++)
#pragma unroll
                for (int ni = 0; ni < 8; ni++)
                    mma16816(acc[mi][ni], ah[mi], bf[ni]);   // hi.lo
        }
        __syncthreads();
    }

#pragma unroll
    for (int mi = 0; mi < 2; mi++)
#pragma unroll
        for (int rr = 0; rr < 2; rr++) {
            int r = wm * 32 + mi * 16 + rr * 8 + (lane >> 2);
            int go = (bi + r) * HIDN + bj;
#pragma unroll
            for (int ni = 0; ni < 8; ni++) {
                int c = wn * 64 + ni * 8 + (lane & 3) * 2;
                float2 o;
                o.x = acc[mi][ni][rr * 2 + 0];
                o.y = acc[mi][ni][rr * 2 + 1];
                *(float2*)&g_xw1[go + c] = o;
            }
        }
}

// ---------------- 3. sim: fp16 hi/lo mma (2 terms) + pipeline + symmetry ----
__global__ __launch_bounds__(256, 2) void k_sim_mma(const float* __restrict__ pos,
                                                    const float* __restrict__ plam,
                                                    const float* __restrict__ ptemp) {
    if (blockIdx.y > blockIdx.x) return;    // symmetry: compute bj >= bi only
    extern __shared__ char dyn[];
    __shared__ float cpx[128], cpy[128], rpx[128], rpy[128];

    int t = threadIdx.x, w = t >> 5, lane = t & 31;
    int bi = blockIdx.y * 128, bj = blockIdx.x * 128;
    bool offdiag = (blockIdx.x != blockIdx.y);
    int wm = w & 3, wn = w >> 2;

    if (t < 128) {
        cpx[t] = pos[2 * (bj + t)];
        cpy[t] = pos[2 * (bj + t) + 1];
    } else {
        int u = t - 128;
        rpx[u] = pos[2 * (bi + u)];
        rpy[u] = pos[2 * (bi + u) + 1];
    }

    float acc[2][8][4];
#pragma unroll
    for (int mi = 0; mi < 2; mi++)
#pragma unroll
        for (int ni = 0; ni < 8; ni++)
#pragma unroll
            for (int r = 0; r < 4; r++) acc[mi][ni][r] = 0.f;

    uint32_t dynb = smem_u32(dyn);
    int lrow = t >> 1;
    int lch = (t & 1) * 4;

    const __half* Ah0 = g_fhi + (size_t)(bi + lrow) * FEATN;
    const __half* Al0 = g_flo + (size_t)(bi + lrow) * FEATN;
    const __half* Bh0 = g_fhi + (size_t)(bj + lrow) * FEATN;

    auto issue = [&](int c, int buf) {
        int kc = c * 64;
        uint32_t sb = dynb + buf * BUFB + lrow * (SSTR * 2);
#pragma unroll
        for (int j = 0; j < 4; j++) {
            int ch = lch + j;
            uint32_t off = sb + ch * 16;
            CP16(off,             Ah0 + kc + ch * 8);
            CP16(off + TILEB,     Al0 + kc + ch * 8);
            CP16(off + 2 * TILEB, Bh0 + kc + ch * 8);
        }
        CP_COMMIT();
    };

    issue(0, 0);
#pragma unroll 1
    for (int c = 0; c < 8; c++) {
        if (c < 7) {
            issue(c + 1, (c + 1) & 1);
            asm volatile("cp.async.wait_group 1;" ::: "memory");
        } else {
            asm volatile("cp.async.wait_group 0;" ::: "memory");
        }
        __syncthreads();
        uint32_t tb = dynb + (c & 1) * BUFB;
        int m = lane >> 3, r8 = lane & 7;
#pragma unroll
        for (int k16 = 0; k16 < 4; k16++) {
            int kb = k16 * 16;
            uint32_t ah[2][4], al[2][4], bf[8][2];
#pragma unroll
            for (int mi = 0; mi < 2; mi++) {
                int R = wm * 32 + mi * 16;
                uint32_t aoff = ((R + (m & 1) * 8 + r8) * SSTR + kb + (m >> 1) * 8) * 2;
                LDMX4(ah[mi], tb + aoff);
                LDMX4(al[mi], tb + TILEB + aoff);
            }
#pragma unroll
            for (int p = 0; p < 4; p++) {
                int n0 = wn * 64 + p * 16;
                uint32_t boff = ((n0 + (m >> 1) * 8 + r8) * SSTR + kb + (m & 1) * 8) * 2;
                LDMX4(&bf[2 * p][0], tb + 2 * TILEB + boff);
            }
#pragma unroll
            for (int mi = 0; mi < 2; mi++)
#pragma unroll
                for (int ni = 0; ni < 8; ni++) {
                    mma16816(acc[mi][ni], ah[mi], bf[ni]);   // hi.hi
                    mma16816(acc[mi][ni], al[mi], bf[ni]);   // lo.hi
                }
        }
        __syncthreads();
    }

    float lam = 1.0f / (1.0f + expf(-plam[0]));
    float T = ptemp[0];
    float aC = lam * T, bC = (1.0f - lam) * T;
    float* stage = (float*)dyn;             // 128 x (stride 132) floats
#pragma unroll
    for (int mi = 0; mi < 2; mi++) {
#pragma unroll
        for (int rr = 0; rr < 2; rr++) {
            int r = wm * 32 + mi * 16 + rr * 8 + (lane >> 2);
            float xi = rpx[r], yi = rpy[r];
            float p2i = xi * xi + yi * yi;
            size_t gro = (size_t)(bi + r) * NN + bj;
#pragma unroll
            for (int ni = 0; ni < 8; ni++) {
                int c = wn * 64 + ni * 8 + (lane & 3) * 2;
                float xj0 = cpx[c], yj0 = cpy[c];
                float xj1 = cpx[c + 1], yj1 = cpy[c + 1];
                float d20 = fmaxf(p2i + xj0 * xj0 + yj0 * yj0 -
                                  2.0f * (xi * xj0 + yi * yj0), 0.0f);
                float d21 = fmaxf(p2i + xj1 * xj1 + yj1 * yj1 -
                                  2.0f * (xi * xj1 + yi * yj1), 0.0f);
                float2 o;
                o.x = aC * acc[mi][ni][rr * 2 + 0] + bC * __expf(-d20 * INV2SD2);
                o.y = aC * acc[mi][ni][rr * 2 + 1] + bC * __expf(-d21 * INV2SD2);
                *(float2*)&g_adj[gro + c] = o;
                if (offdiag) {
                    stage[c * 132 + r] = o.x;
                    stage[(c + 1) * 132 + r] = o.y;
                }
            }
        }
    }
    if (offdiag) {
        __syncthreads();
#pragma unroll
        for (int j = 0; j < 16; j++) {
            int idx4 = t + j * 256;
            int cc = idx4 >> 5, r4 = (idx4 & 31) * 4;
            float4 v = *(float4*)&stage[cc * 132 + r4];
            *(float4*)&g_adj[(size_t)(bj + cc) * NN + bi + r4] = v;
        }
    }
}

// ---------------- 4. row-wise exact top-20 (float-domain binary search) ----
__global__ __launch_bounds__(128) void k_topk() {
    int row = blockIdx.x, t = threadIdx.x;
    const float4* r4 = (const float4*)(g_adj + (size_t)row * NN);

    float key[48];
#pragma unroll
    for (int kk = 0; kk < 12; kk++) {
        float4 v = r4[t + kk * 128];
        key[kk * 4 + 0] = v.x; key[kk * 4 + 1] = v.y;
        key[kk * 4 + 2] = v.z; key[kk * 4 + 3] = v.w;
    }

    __shared__ int scnt[4];
    __shared__ float smm[8];

    float kmin = key[0], kmax = key[0];
#pragma unroll
    for (int k = 1; k < 48; k++) {
        kmin = fminf(kmin, key[k]);
        kmax = fmaxf(kmax, key[k]);
    }
    for (int o = 16; o > 0; o >>= 1) {
        kmin = fminf(kmin, __shfl_down_sync(0xffffffffu, kmin, o));
        kmax = fmaxf(kmax, __shfl_down_sync(0xffffffffu, kmax, o));
    }
    if ((t & 31) == 0) { smm[t >> 5] = kmin; smm[4 + (t >> 5)] = kmax; }
    __syncthreads();
    float lo = fminf(fminf(smm[0], smm[1]), fminf(smm[2], smm[3]));
    float hi = fmaxf(fmaxf(smm[4], smm[5]), fmaxf(smm[6], smm[7]));
    __syncthreads();

    for (int it = 0; it < 40; it++) {
        float mid = 0.5f * (lo + hi);
        if (mid == lo || mid == hi) break;
        int c = 0;
#pragma unroll
        for (int k = 0; k < 48; k++) c += (key[k] >= mid) ? 1 : 0;
        for (int o = 16; o > 0; o >>= 1) c += __shfl_down_sync(0xffffffffu, c, o);
        if ((t & 31) == 0) scnt[t >> 5] = c;
        __syncthreads();
        int tot = scnt[0] + scnt[1] + scnt[2] + scnt[3];
        __syncthreads();
        if (tot >= 20) {
            lo = mid;
            if (tot <= 96) break;
        } else {
            hi = mid;
        }
    }

    __shared__ unsigned long long cand[CAPC];
    __shared__ int cnum;
    cand[t] = 0ull;
    if (t == 0) cnum = 0;
    __syncthreads();
#pragma unroll
    for (int k = 0; k < 48; k++) {
        if (key[k] >= lo) {
            unsigned b = __float_as_uint(key[k]);
            unsigned mk = (b & 0x80000000u) ? ~b : (b | 0x80000000u);
            int gidx = ((t + (k >> 2) * 128) << 2) + (k & 3);
            int p = atomicAdd(&cnum, 1);
            if (p < CAPC)
                cand[p] = ((unsigned long long)mk << 32) | (unsigned)(~gidx);
        }
    }
    __syncthreads();

    if (t < 32) {
        for (int it = 0; it < KNNN; it++) {
            unsigned long long best = 0ull;
            int bslot = 0;
#pragma unroll
            for (int s = 0; s < CAPC / 32; s++) {
                unsigned long long c = cand[t + s * 32];
                if (c > best) { best = c; bslot = t + s * 32; }
            }
#pragma unroll
            for (int o = 16; o > 0; o >>= 1) {
                unsigned long long b2 = __shfl_down_sync(0xffffffffu, best, o);
                int s2 = __shfl_down_sync(0xffffffffu, bslot, o);
                if (b2 > best) { best = b2; bslot = s2; }
            }
            bslot = __shfl_sync(0xffffffffu, bslot, 0);
            if (t == 0) {
                unsigned kk = (unsigned)(best >> 32);
                unsigned fb = (kk & 0x80000000u) ? (kk & 0x7fffffffu) : ~kk;
                float raw = __uint_as_float(fb);
                g_val[row * KNNN + it] = 1.0f / (1.0f + expf(-raw));
                g_idx[row * KNNN + it] = (int)(~(unsigned)(best & 0xffffffffu));
                cand[bslot] = 0ull;
            }
            __syncwarp();
        }
    }
}

// ---------------- 5. degrees + CSC build ----------------
__global__ void k_deg_scatter() {
    int e = blockIdx.x * 256 + threadIdx.x;
    if (e < NN * KNNN) {
        if (g_val[e] > THRF) atomicAdd(&g_deg[g_idx[e]], 1.0f);
    }
}
__global__ void k_dinv() {
    int i = blockIdx.x * 256 + threadIdx.x;
    if (i < NN) g_dinv[i] = 1.0f / sqrtf(g_deg[i]);
}
__global__ __launch_bounds__(256) void k_scan() {
    __shared__ int part[256];
    int t = threadIdx.x;
    int base = t * 24;
    int loc[24];
    int s = 0;
#pragma unroll
    for (int u = 0; u < 24; u++) {
        loc[u] = s;
        s += (int)g_deg[base + u] - 1;
    }
    part[t] = s;
    __syncthreads();
    for (int o = 1; o < 256; o <<= 1) {
        int v = (t >= o) ? part[t - o] : 0;
        __syncthreads();
        part[t] += v;
        __syncthreads();
    }
    int pre = (t == 0) ? 0 : part[t - 1];
#pragma unroll
    for (int u = 0; u < 24; u++) g_coff[base + u] = pre + loc[u];
    if (t == 255) g_coff[NN] = part[255];
}
__global__ void k_fill() {
    int e = blockIdx.x * 256 + threadIdx.x;
    if (e < NN * KNNN && g_val[e] > THRF) {
        int j = g_idx[e];
        int p = atomicAdd(&g_ccnt[j], 1);
        g_csrc[g_coff[j] + p] = e / KNNN;
    }
}

// ---------------- 6. GCN layer 1 (gather) ----------
__global__ __launch_bounds__(HIDN) void k_gather1(const float* __restrict__ b1) {
    int j = blockIdx.x, f = threadIdx.x;
    float dj = g_dinv[j];
    float s = dj * g_xw1[j * HIDN + f];
    int e0 = g_coff[j], e1 = g_coff[j + 1];
    for (int e = e0; e < e1; e++) {
        int i = g_csrc[e];
        s += g_dinv[i] * g_xw1[i * HIDN + f];
    }
    g_acc[j * HIDN + f] = fmaxf(dj * s + b1[f], 0.0f);
}

// ---------------- 7. t1 = h @ W2 ----------------
__global__ __launch_bounds__(64) void k_hw2(const float* __restrict__ W2) {
    int i = blockIdx.x, t = threadIdx.x;
    __shared__ float sh[HIDN];
    for (int k = t; k < HIDN; k += 64) sh[k] = g_acc[i * HIDN + k];
    __syncthreads();
    if (t < KMN) {
        float s = 0.f;
#pragma unroll 8
        for (int k = 0; k < HIDN; k++) s += sh[k] * W2[k * KMN + t];
        g_t1[i * KMN + t] = s;
    }
}

// ---------------- 8. GCN layer 2 (gather) + softmax -> S ----------------
__global__ __launch_bounds__(64) void k_g2soft(const float* __restrict__ b2,
                                               float* __restrict__ S) {
    int j = blockIdx.x, t = threadIdx.x;
    float dj = g_dinv[j];
    float s = (t < KMN) ? dj * g_t1[j * KMN + t] : 0.f;
    int e0 = g_coff[j], e1 = g_coff[j + 1];
    for (int e = e0; e < e1; e++) {
        int i = g_csrc[e];
        if (t < KMN) s += g_dinv[i] * g_t1[i * KMN + t];
    }
    float v = (t < KMN) ? dj * s + b2[t] : -FLT_MAX;
    __shared__ float red[64];
    red[t] = v;
#pragma unroll
    for (int o = 32; o > 0; o >>= 1) {
        __syncthreads();
        if (t < o) red[t] = fmaxf(red[t], red[t + o]);
    }
    __syncthreads();
    float mx = red[0];
    __syncthreads();
    float e2 = (t < KMN) ? expf(v - mx) : 0.f;
    red[t] = e2;
#pragma unroll
    for (int o = 32; o > 0; o >>= 1) {
        __syncthreads();
        if (t < o) red[t] += red[t + o];
    }
    __syncthreads();
    float inv = 1.0f / red[0];
    if (t < KMN) S[j * KMN + t] = e2 * inv;
}

// ---------------- 9. t2 = adj @ S (sparse) ----------------
__global__ __launch_bounds__(64) void k_adjS(const float* __restrict__ S) {
    int i = blockIdx.x, t = threadIdx.x;
    __shared__ int   sj[KNNN];
    __shared__ float sw[KNNN];
    if (t < KNNN) { sj[t] = g_idx[i * KNNN + t]; sw[t] = g_val[i * KNNN + t]; }
    __syncthreads();
    if (t < KMN) {
        float a = 0.f;
#pragma unroll
        for (int k = 0; k < KNNN; k++) a += sw[k] * S[sj[k] * KMN + t];
        g_t2[i * KMN + t] = a;
    }
}

// ---------------- 10. A_coarse = S^T @ t2 ----------------
__global__ __launch_bounds__(256) void k_Ac(const float* __restrict__ S) {
    int t = threadIdx.x;
    int r0 = blockIdx.x * 128;
    __shared__ float sS[KMN], sT[KMN];
    float acc[10];
    int c1[10], c2[10]; bool ok[10];
#pragma unroll
    for (int p = 0; p < 10; p++) {
        int e = t + p * 256;
        ok[p] = (e < KMN * KMN);
        c1[p] = ok[p] ? e / KMN : 0;
        c2[p] = ok[p] ? e % KMN : 0;
        acc[p] = 0.f;
    }
    for (int r = 0; r < 128; r++) {
        int i = r0 + r;
        if (t < KMN) sS[t] = S[i * KMN + t];
        else if (t >= 64 && t < 64 + KMN) sT[t - 64] = g_t2[i * KMN + t - 64];
        __syncthreads();
#pragma unroll
        for (int p = 0; p < 10; p++)
            if (ok[p]) acc[p] += sS[c1[p]] * sT[c2[p]];
        __syncthreads();
    }
#pragma unroll
    for (int p = 0; p < 10; p++)
        if (ok[p]) atomicAdd(&g_Ac[t + p * 256], acc[p]);
}

// ---------------- 11. X_t = S^T @ X ----------------
__global__ __launch_bounds__(256) void k_Xt(const float* __restrict__ X,
                                            const float* __restrict__ S,
                                            float* __restrict__ outXt) {
    int t = threadIdx.x;
    int fc = blockIdx.x * 128;
    int r0 = blockIdx.y * 128;
    int f = t & 127, ch = t >> 7;
    __shared__ float sS[KMN];
    __shared__ float sX[128];
    float acc[25];
#pragma unroll
    for (int c = 0; c < 25; c++) acc[c] = 0.f;
    for (int r = 0; r < 128; r++) {
        int i = r0 + r;
        if (t < KMN) sS[t] = S[i * KMN + t];
        if (t >= 128) sX[t - 128] = X[i * FEATN + fc + t - 128];
        __syncthreads();
        float xv = sX[f];
#pragma unroll
        for (int c = 0; c < 25; c++) acc[c] += sS[ch * 25 + c] * xv;
        __syncthreads();
    }
#pragma unroll
    for (int c = 0; c < 25; c++)
        atomicAdd(&outXt[(ch * 25 + c) * FEATN + fc + f], acc[c]);
}

// ---------------- 12. spatial loss ----------------
__global__ __launch_bounds__(256) void k_loss(const float* __restrict__ S,
                                              const float* __restrict__ pos) {
    int warp = (blockIdx.x * 256 + threadIdx.x) >> 5;
    int lane = threadIdx.x & 31;
    if (warp >= NN) return;
    int i = warp;
    float s0 = (lane < KMN) ? S[i * KMN + lane] : 0.f;
    bool has2 = (lane + 32 < KMN);
    float s1 = has2 ? S[i * KMN + lane + 32] : 0.f;
    float xi = pos[2 * i], yi = pos[2 * i + 1];
    float p2i = xi * xi + yi * yi;
    float lsum = 0.f; int cnt = 0;
#pragma unroll
    for (int k = 0; k < KNNN; k++) {
        float v = g_val[i * KNNN + k];
        if (v > THRF) {
            int j = g_idx[i * KNNN + k];
            float xj = pos[2 * j], yj = pos[2 * j + 1];
            float d2 = fmaxf(p2i + xj * xj + yj * yj -
                             2.0f * (xi * xj + yi * yj), 0.0f);
            float dp = s0 * ((lane < KMN) ? S[j * KMN + lane] : 0.f);
            if (has2) dp += s1 * S[j * KMN + lane + 32];
            lsum += d2 * dp;
            cnt++;
        }
    }
#pragma unroll
    for (int o = 16; o > 0; o >>= 1) lsum += __shfl_down_sync(0xffffffffu, lsum, o);
    if (lane == 0) {
        atomicAdd(&g_loss, lsum);
        atomicAdd(&g_E, (float)cnt);
    }
}

// ---------------- zero/init + finalize ----------------
__global__ void k_zero(float* __restrict__ outXt) {
    int idx = blockIdx.x * 256 + threadIdx.x;
    if (idx < KMN * FEATN) outXt[idx] = 0.f;
    if (idx < KMN * KMN) g_Ac[idx] = 0.f;
    if (idx < NN) { g_deg[idx] = 1.0f; g_ccnt[idx] = 0; }
    if (idx == 0) { g_loss = 0.f; g_E = 0.f; }
}
__global__ void k_final(const float* __restrict__ psw,
                        const float* __restrict__ plam,
                        float* __restrict__ out) {
    int idx = blockIdx.x * 256 + threadIdx.x;
    const int offA = NN * KMN + KMN * FEATN;
    if (idx < KMN * KMN) {
        float a = g_Ac[idx];
        out[offA + idx] = (a > THRF) ? a : 0.f;
    }
    if (idx == 0) {
        out[offA + KMN * KMN] = psw[0] * g_loss / g_E;
        out[offA + KMN * KMN + 1] = 1.0f / (1.0f + expf(-plam[0]));
    }
}

// ---------------- launcher ----------------
extern "C" void kernel_launch(void* const* d_in, const int* in_sizes, int n_in,
                              void* d_out, int out_size) {
    const float* X    = (const float*)d_in[0];
    const float* pos  = (const float*)d_in[1];
    const float* lamw = (const float*)d_in[2];
    const float* temp = (const float*)d_in[3];
    const float* sw   = (const float*)d_in[4];
    const float* W1   = (const float*)d_in[5];
    const float* b1   = (const float*)d_in[6];
    const float* W2   = (const float*)d_in[7];
    const float* b2   = (const float*)d_in[8];
    float* out  = (float*)d_out;
    float* S    = out;              // [N, K]
    float* oXt  = out + NN * KMN;   // [K, FEAT]

    const int SMEM_SIM = 2 * BUFB;   // 110592
    const int SMEM_XW1 = 2 * BUF4;   // 147456
    static int s_attr_done = 0;
    if (!s_attr_done) {
        cudaFuncSetAttribute(k_sim_mma, cudaFuncAttributeMaxDynamicSharedMemorySize,
                             SMEM_SIM);
        cudaFuncSetAttribute(k_xw1_mma, cudaFuncAttributeMaxDynamicSharedMemorySize,
                             SMEM_XW1);
        s_attr_done = 1;
    }

    k_prep<<<NN, 128>>>(X);
    k_w1t<<<(FEATN * HIDN + 255) / 256, 256>>>(W1);
    k_xw1_mma<<<dim3(HIDN / 128, NN / 128), 256, SMEM_XW1>>>();
    k_sim_mma<<<dim3(NN / 128, NN / 128), 256, SMEM_SIM>>>(pos, lamw, temp);
    k_topk<<<NN, 128>>>();
    k_zero<<<(KMN * FEATN + 255) / 256, 256>>>(oXt);
    k_deg_scatter<<<(NN * KNNN + 255) / 256, 256>>>();
    k_scan<<<1, 256>>>();
    k_dinv<<<NN / 256, 256>>>();
    k_fill<<<(NN * KNNN + 255) / 256, 256>>>();
    k_gather1<<<NN, HIDN>>>(b1);
    k_hw2<<<NN, 64>>>(W2);
    k_g2soft<<<NN, 64>>>(b2, S);
    k_adjS<<<NN, 64>>>(S);
    k_Ac<<<NN / 128, 256>>>(S);
    k_Xt<<<dim3(FEATN / 128, NN / 128), 256>>>(X, S, oXt);
    k_loss<<<NN / 8, 256>>>(S, pos);
    k_final<<<(KMN * KMN + 255) / 256, 256>>>(sw, lamw, out);
}

// round 16
// speedup vs baseline: 3.1655x; 1.1585x over previous
#include <cuda_runtime.h>
#include <cuda_fp16.h>
#include <math.h>
#include <float.h>
#include <stdint.h>

// Problem constants
#define NN    6144
#define FEATN 512
#define HIDN  256
#define KMN   50
#define KNNN  20
#define THRF  0.1f
#define INV2SD2 (1.0f/5000.0f)
#define CAPC  128
#define SSTR  72        // smem row stride in fp16 (144B) -> conflict-free
#define TILEB (128*SSTR*2)            // 18432 B per tile
#define BUFB  (3*TILEB)               // sim buffer (Ahi,Alo,Bhi)
#define BUF4  (4*TILEB)               // xw1 buffer (Ahi,Alo,Bhi,Blo)
#define NTILE (NN/128)                // 48
#define NTRI  (NTILE*(NTILE+1)/2)     // 1176

// ---------------- device scratch ----------------
__device__ __half g_fhi[NN * FEATN];
__device__ __half g_flo[NN * FEATN];
__device__ __half g_xhi[NN * FEATN];
__device__ __half g_xlo[NN * FEATN];
__device__ __half g_w1hi[HIDN * FEATN];  // W1^T hi  [n][k]
__device__ __half g_w1lo[HIDN * FEATN];  // W1^T lo
__device__ float g_adj[(size_t)NN * NN];
__device__ float g_xw1[NN * HIDN];
__device__ float g_acc[NN * HIDN];
__device__ float g_t1[NN * KMN];
__device__ float g_t2[NN * KMN];
__device__ float g_deg[NN];
__device__ float g_dinv[NN];
__device__ int   g_idx[NN * KNNN];
__device__ float g_val[NN * KNNN];
__device__ float g_Ac[KMN * KMN];
__device__ float g_loss;
__device__ float g_E;
__device__ int   g_coff[NN + 1];
__device__ int   g_ccnt[NN];
__device__ int   g_csrc[NN * KNNN];

// ---------------- PTX helpers (baseline ISA, valid on compute_103) -----
__device__ __forceinline__ void mma16816(float* d, const uint32_t* a,
                                         const uint32_t* b) {
    asm volatile(
        "mma.sync.aligned.m16n8k16.row.col.f32.f16.f16.f32 "
        "{%0,%1,%2,%3}, {%4,%5,%6,%7}, {%8,%9}, {%0,%1,%2,%3};"
        : "+f"(d[0]), "+f"(d[1]), "+f"(d[2]), "+f"(d[3])
        : "r"(a[0]), "r"(a[1]), "r"(a[2]), "r"(a[3]), "r"(b[0]), "r"(b[1]));
}
__device__ __forceinline__ uint32_t smem_u32(const void* p) {
    uint32_t a;
    asm("{ .reg .u64 t; cvta.to.shared.u64 t, %1; cvt.u32.u64 %0, t; }"
        : "=r"(a) : "l"(p));
    return a;
}
#define LDMX4(r, addr) asm volatile( \
    "ldmatrix.sync.aligned.m8n8.x4.shared.b16 {%0,%1,%2,%3}, [%4];" \
    : "=r"((r)[0]), "=r"((r)[1]), "=r"((r)[2]), "=r"((r)[3]) : "r"(addr))
#define CP16(saddr, gptr) asm volatile( \
    "cp.async.cg.shared.global [%0], [%1], 16;" :: "r"(saddr), "l"(gptr))
#define CP_COMMIT() asm volatile("cp.async.commit_group;" ::: "memory")

// ---------------- 1. normalize + fp16 splits + fused W1^T split -------
__global__ __launch_bounds__(128) void k_prep(const float* __restrict__ X,
                                              const float* __restrict__ W1) {
    int row = blockIdx.x, t = threadIdx.x;
    const float* xr = X + row * FEATN;
    float ss = 0.f;
    for (int f = t; f < FEATN; f += 128) { float v = xr[f]; ss += v * v; }
    for (int o = 16; o > 0; o >>= 1) ss += __shfl_down_sync(0xffffffffu, ss, o);
    __shared__ float red[4];
    __shared__ float sinv;
    if ((t & 31) == 0) red[t >> 5] = ss;
    __syncthreads();
    if (t == 0) {
        float s = red[0] + red[1] + red[2] + red[3];
        sinv = 1.0f / fmaxf(sqrtf(s), 1e-12f);
    }
    __syncthreads();
    float inv = sinv;
    for (int f = t; f < FEATN; f += 128) {
        float xv = xr[f];
        __half xh = __float2half_rn(xv);
        g_xhi[row * FEATN + f] = xh;
        g_xlo[row * FEATN + f] = __float2half_rn(xv - __half2float(xh));
        float v = xv * inv;
        __half h = __float2half_rn(v);
        g_fhi[row * FEATN + f] = h;
        g_flo[row * FEATN + f] = __float2half_rn(v - __half2float(h));
    }
    if (row < FEATN) {   // fused W1^T hi/lo split: k = row
        for (int n = t; n < HIDN; n += 128) {
            float v = W1[row * HIDN + n];
            __half h = __float2half_rn(v);
            g_w1hi[n * FEATN + row] = h;
            g_w1lo[n * FEATN + row] = __float2half_rn(v - __half2float(h));
        }
    }
}

// ---------------- 2. XW1 = X @ W1 via fp16 hi/lo mma (3 terms) -------------
__global__ __launch_bounds__(256) void k_xw1_mma() {
    extern __shared__ char dyn[];
    int t = threadIdx.x, w = t >> 5, lane = t & 31;
    int bi = blockIdx.y * 128, bj = blockIdx.x * 128;
    int wm = w & 3, wn = w >> 2;

    float acc[2][8][4];
#pragma unroll
    for (int mi = 0; mi < 2; mi++)
#pragma unroll
        for (int ni = 0; ni < 8; ni++)
#pragma unroll
            for (int r = 0; r < 4; r++) acc[mi][ni][r] = 0.f;

    uint32_t dynb = smem_u32(dyn);
    int lrow = t >> 1;
    int lch = (t & 1) * 4;

    const __half* Ah0 = g_xhi + (size_t)(bi + lrow) * FEATN;
    const __half* Al0 = g_xlo + (size_t)(bi + lrow) * FEATN;
    const __half* Bh0 = g_w1hi + (size_t)(bj + lrow) * FEATN;
    const __half* Bl0 = g_w1lo + (size_t)(bj + lrow) * FEATN;

    auto issue = [&](int c, int buf) {
        int kc = c * 64;
        uint32_t sb = dynb + buf * BUF4 + lrow * (SSTR * 2);
#pragma unroll
        for (int j = 0; j < 4; j++) {
            int ch = lch + j;
            uint32_t off = sb + ch * 16;
            CP16(off,             Ah0 + kc + ch * 8);
            CP16(off + TILEB,     Al0 + kc + ch * 8);
            CP16(off + 2 * TILEB, Bh0 + kc + ch * 8);
            CP16(off + 3 * TILEB, Bl0 + kc + ch * 8);
        }
        CP_COMMIT();
    };

    issue(0, 0);
#pragma unroll 1
    for (int c = 0; c < 8; c++) {
        if (c < 7) {
            issue(c + 1, (c + 1) & 1);
            asm volatile("cp.async.wait_group 1;" ::: "memory");
        } else {
            asm volatile("cp.async.wait_group 0;" ::: "memory");
        }
        __syncthreads();
        uint32_t tb = dynb + (c & 1) * BUF4;
        int m = lane >> 3, r8 = lane & 7;
#pragma unroll
        for (int k16 = 0; k16 < 4; k16++) {
            int kb = k16 * 16;
            uint32_t ah[2][4], al[2][4], bf[8][2];
#pragma unroll
            for (int mi = 0; mi < 2; mi++) {
                int R = wm * 32 + mi * 16;
                uint32_t aoff = ((R + (m & 1) * 8 + r8) * SSTR + kb + (m >> 1) * 8) * 2;
                LDMX4(ah[mi], tb + aoff);
                LDMX4(al[mi], tb + TILEB + aoff);
            }
#pragma unroll
            for (int p = 0; p < 4; p++) {
                int n0 = wn * 64 + p * 16;
                uint32_t boff = ((n0 + (m >> 1) * 8 + r8) * SSTR + kb + (m & 1) * 8) * 2;
                LDMX4(&bf[2 * p][0], tb + 2 * TILEB + boff);
            }
#pragma unroll
            for (int mi = 0; mi < 2; mi++)
#pragma unroll
                for (int ni = 0; ni < 8; ni++) {
                    mma16816(acc[mi][ni], ah[mi], bf[ni]);   // hi.hi
                    mma16816(acc[mi][ni], al[mi], bf[ni]);   // lo.hi
                }
#pragma unroll
            for (int p = 0; p < 4; p++) {
                int n0 = wn * 64 + p * 16;
                uint32_t boff = ((n0 + (m >> 1) * 8 + r8) * SSTR + kb + (m & 1) * 8) * 2;
                LDMX4(&bf[2 * p][0], tb + 3 * TILEB + boff);
            }
#pragma unroll
            for (int mi = 0; mi < 2; mi++)
#pragma unroll
                for (int ni = 0; ni < 8; ni++)
                    mma16816(acc[mi][ni], ah[mi], bf[ni]);   // hi.lo
        }
        __syncthreads();
    }

#pragma unroll
    for (int mi = 0; mi < 2; mi++)
#pragma unroll
        for (int rr = 0; rr < 2; rr++) {
            int r = wm * 32 + mi * 16 + rr * 8 + (lane >> 2);
            int go = (bi + r) * HIDN + bj;
#pragma unroll
            for (int ni = 0; ni < 8; ni++) {
                int c = wn * 64 + ni * 8 + (lane & 3) * 2;
                float2 o;
                o.x = acc[mi][ni][rr * 2 + 0];
                o.y = acc[mi][ni][rr * 2 + 1];
                *(float2*)&g_xw1[go + c] = o;
            }
        }
}

// ---------------- 3. sim: fp16 hi/lo mma, triangular 1D grid ----------
__global__ __launch_bounds__(256, 2) void k_sim_mma(const float* __restrict__ pos,
                                                    const float* __restrict__ plam,
                                                    const float* __restrict__ ptemp) {
    // decode triangular index -> (by, bx) with bx >= by
    int e = blockIdx.x;
    int by = (int)((97.0f - sqrtf(9409.0f - 8.0f * (float)e)) * 0.5f);
    while ((by + 1) * NTILE - ((by + 1) * by) / 2 <= e) by++;
    while (by * NTILE - (by * (by - 1)) / 2 > e) by--;
    int bx = by + (e - (by * NTILE - (by * (by - 1)) / 2));

    extern __shared__ char dyn[];
    __shared__ float cpx[128], cpy[128], rpx[128], rpy[128];

    int t = threadIdx.x, w = t >> 5, lane = t & 31;
    int bi = by * 128, bj = bx * 128;
    bool offdiag = (bx != by);
    int wm = w & 3, wn = w >> 2;

    if (t < 128) {
        cpx[t] = pos[2 * (bj + t)];
        cpy[t] = pos[2 * (bj + t) + 1];
    } else {
        int u = t - 128;
        rpx[u] = pos[2 * (bi + u)];
        rpy[u] = pos[2 * (bi + u) + 1];
    }

    float acc[2][8][4];
#pragma unroll
    for (int mi = 0; mi < 2; mi++)
#pragma unroll
        for (int ni = 0; ni < 8; ni++)
#pragma unroll
            for (int r = 0; r < 4; r++) acc[mi][ni][r] = 0.f;

    uint32_t dynb = smem_u32(dyn);
    int lrow = t >> 1;
    int lch = (t & 1) * 4;

    const __half* Ah0 = g_fhi + (size_t)(bi + lrow) * FEATN;
    const __half* Al0 = g_flo + (size_t)(bi + lrow) * FEATN;
    const __half* Bh0 = g_fhi + (size_t)(bj + lrow) * FEATN;

    auto issue = [&](int c, int buf) {
        int kc = c * 64;
        uint32_t sb = dynb + buf * BUFB + lrow * (SSTR * 2);
#pragma unroll
        for (int j = 0; j < 4; j++) {
            int ch = lch + j;
            uint32_t off = sb + ch * 16;
            CP16(off,             Ah0 + kc + ch * 8);
            CP16(off + TILEB,     Al0 + kc + ch * 8);
            CP16(off + 2 * TILEB, Bh0 + kc + ch * 8);
        }
        CP_COMMIT();
    };

    issue(0, 0);
#pragma unroll 1
    for (int c = 0; c < 8; c++) {
        if (c < 7) {
            issue(c + 1, (c + 1) & 1);
            asm volatile("cp.async.wait_group 1;" ::: "memory");
        } else {
            asm volatile("cp.async.wait_group 0;" ::: "memory");
        }
        __syncthreads();
        uint32_t tb = dynb + (c & 1) * BUFB;
        int m = lane >> 3, r8 = lane & 7;
#pragma unroll
        for (int k16 = 0; k16 < 4; k16++) {
            int kb = k16 * 16;
            uint32_t ah[2][4], al[2][4], bf[8][2];
#pragma unroll
            for (int mi = 0; mi < 2; mi++) {
                int R = wm * 32 + mi * 16;
                uint32_t aoff = ((R + (m & 1) * 8 + r8) * SSTR + kb + (m >> 1) * 8) * 2;
                LDMX4(ah[mi], tb + aoff);
                LDMX4(al[mi], tb + TILEB + aoff);
            }
#pragma unroll
            for (int p = 0; p < 4; p++) {
                int n0 = wn * 64 + p * 16;
                uint32_t boff = ((n0 + (m >> 1) * 8 + r8) * SSTR + kb + (m & 1) * 8) * 2;
                LDMX4(&bf[2 * p][0], tb + 2 * TILEB + boff);
            }
#pragma unroll
            for (int mi = 0; mi < 2; mi++)
#pragma unroll
                for (int ni = 0; ni < 8; ni++) {
                    mma16816(acc[mi][ni], ah[mi], bf[ni]);   // hi.hi
                    mma16816(acc[mi][ni], al[mi], bf[ni]);   // lo.hi
                }
        }
        __syncthreads();
    }

    float lam = 1.0f / (1.0f + expf(-plam[0]));
    float T = ptemp[0];
    float aC = lam * T, bC = (1.0f - lam) * T;
    float* stage = (float*)dyn;             // 128 x (stride 132) floats
#pragma unroll
    for (int mi = 0; mi < 2; mi++) {
#pragma unroll
        for (int rr = 0; rr < 2; rr++) {
            int r = wm * 32 + mi * 16 + rr * 8 + (lane >> 2);
            float xi = rpx[r], yi = rpy[r];
            float p2i = xi * xi + yi * yi;
            size_t gro = (size_t)(bi + r) * NN + bj;
#pragma unroll
            for (int ni = 0; ni < 8; ni++) {
                int c = wn * 64 + ni * 8 + (lane & 3) * 2;
                float xj0 = cpx[c], yj0 = cpy[c];
                float xj1 = cpx[c + 1], yj1 = cpy[c + 1];
                float d20 = fmaxf(p2i + xj0 * xj0 + yj0 * yj0 -
                                  2.0f * (xi * xj0 + yi * yj0), 0.0f);
                float d21 = fmaxf(p2i + xj1 * xj1 + yj1 * yj1 -
                                  2.0f * (xi * xj1 + yi * yj1), 0.0f);
                float2 o;
                o.x = aC * acc[mi][ni][rr * 2 + 0] + bC * __expf(-d20 * INV2SD2);
                o.y = aC * acc[mi][ni][rr * 2 + 1] + bC * __expf(-d21 * INV2SD2);
                *(float2*)&g_adj[gro + c] = o;
                if (offdiag) {
                    stage[c * 132 + r] = o.x;
                    stage[(c + 1) * 132 + r] = o.y;
                }
            }
        }
    }
    if (offdiag) {
        __syncthreads();
#pragma unroll
        for (int j = 0; j < 16; j++) {
            int idx4 = t + j * 256;
            int cc = idx4 >> 5, r4 = (idx4 & 31) * 4;
            float4 v = *(float4*)&stage[cc * 132 + r4];
            *(float4*)&g_adj[(size_t)(bj + cc) * NN + bi + r4] = v;
        }
    }
}

// ---------------- 4. row-wise exact top-20 (256 threads) ----
__global__ __launch_bounds__(256) void k_topk() {
    int row = blockIdx.x, t = threadIdx.x;
    const float4* r4 = (const float4*)(g_adj + (size_t)row * NN);

    float key[24];
#pragma unroll
    for (int kk = 0; kk < 6; kk++) {
        float4 v = r4[t + kk * 256];
        key[kk * 4 + 0] = v.x; key[kk * 4 + 1] = v.y;
        key[kk * 4 + 2] = v.z; key[kk * 4 + 3] = v.w;
    }

    __shared__ int scnt[8];
    __shared__ float smm[16];

    float kmin = key[0], kmax = key[0];
#pragma unroll
    for (int k = 1; k < 24; k++) {
        kmin = fminf(kmin, key[k]);
        kmax = fmaxf(kmax, key[k]);
    }
    for (int o = 16; o > 0; o >>= 1) {
        kmin = fminf(kmin, __shfl_down_sync(0xffffffffu, kmin, o));
        kmax = fmaxf(kmax, __shfl_down_sync(0xffffffffu, kmax, o));
    }
    if ((t & 31) == 0) { smm[t >> 5] = kmin; smm[8 + (t >> 5)] = kmax; }
    __syncthreads();
    float lo = smm[0], hi = smm[8];
#pragma unroll
    for (int q = 1; q < 8; q++) {
        lo = fminf(lo, smm[q]);
        hi = fmaxf(hi, smm[8 + q]);
    }
    __syncthreads();

    for (int it = 0; it < 40; it++) {
        float mid = 0.5f * (lo + hi);
        if (mid == lo || mid == hi) break;
        int c = 0;
#pragma unroll
        for (int k = 0; k < 24; k++) c += (key[k] >= mid) ? 1 : 0;
        for (int o = 16; o > 0; o >>= 1) c += __shfl_down_sync(0xffffffffu, c, o);
        if ((t & 31) == 0) scnt[t >> 5] = c;
        __syncthreads();
        int tot = scnt[0] + scnt[1] + scnt[2] + scnt[3] +
                  scnt[4] + scnt[5] + scnt[6] + scnt[7];
        __syncthreads();
        if (tot >= 20) {
            lo = mid;
            if (tot <= 96) break;
        } else {
            hi = mid;
        }
    }

    __shared__ unsigned long long cand[CAPC];
    __shared__ int cnum;
    if (t < CAPC) cand[t] = 0ull;
    if (t == 0) cnum = 0;
    __syncthreads();
#pragma unroll
    for (int k = 0; k < 24; k++) {
        if (key[k] >= lo) {
            unsigned b = __float_as_uint(key[k]);
            unsigned mk = (b & 0x80000000u) ? ~b : (b | 0x80000000u);
            int gidx = ((t + (k >> 2) * 256) << 2) + (k & 3);
            int p = atomicAdd(&cnum, 1);
            if (p < CAPC)
                cand[p] = ((unsigned long long)mk << 32) | (unsigned)(~gidx);
        }
    }
    __syncthreads();

    if (t < 32) {
        for (int it = 0; it < KNNN; it++) {
            unsigned long long best = 0ull;
            int bslot = 0;
#pragma unroll
            for (int s = 0; s < CAPC / 32; s++) {
                unsigned long long c = cand[t + s * 32];
                if (c > best) { best = c; bslot = t + s * 32; }
            }
#pragma unroll
            for (int o = 16; o > 0; o >>= 1) {
                unsigned long long b2 = __shfl_down_sync(0xffffffffu, best, o);
                int s2 = __shfl_down_sync(0xffffffffu, bslot, o);
                if (b2 > best) { best = b2; bslot = s2; }
            }
            bslot = __shfl_sync(0xffffffffu, bslot, 0);
            if (t == 0) {
                unsigned kk = (unsigned)(best >> 32);
                unsigned fb = (kk & 0x80000000u) ? (kk & 0x7fffffffu) : ~kk;
                float raw = __uint_as_float(fb);
                g_val[row * KNNN + it] = 1.0f / (1.0f + expf(-raw));
                g_idx[row * KNNN + it] = (int)(~(unsigned)(best & 0xffffffffu));
                cand[bslot] = 0ull;
            }
            __syncwarp();
        }
    }
}

// ---------------- 5. degrees + CSC build ----------------
__global__ void k_deg_scatter() {
    int e = blockIdx.x * 256 + threadIdx.x;
    if (e < NN * KNNN) {
        if (g_val[e] > THRF) atomicAdd(&g_deg[g_idx[e]], 1.0f);
    }
}
__global__ __launch_bounds__(256) void k_scan() {   // + fused dinv
    __shared__ int part[256];
    int t = threadIdx.x;
    int base = t * 24;
    int loc[24];
    int s = 0;
#pragma unroll
    for (int u = 0; u < 24; u++) {
        float d = g_deg[base + u];
        g_dinv[base + u] = rsqrtf(d);
        loc[u] = s;
        s += (int)d - 1;
    }
    part[t] = s;
    __syncthreads();
    for (int o = 1; o < 256; o <<= 1) {
        int v = (t >= o) ? part[t - o] : 0;
        __syncthreads();
        part[t] += v;
        __syncthreads();
    }
    int pre = (t == 0) ? 0 : part[t - 1];
#pragma unroll
    for (int u = 0; u < 24; u++) g_coff[base + u] = pre + loc[u];
    if (t == 255) g_coff[NN] = part[255];
}
__global__ void k_fill() {
    int e = blockIdx.x * 256 + threadIdx.x;
    if (e < NN * KNNN && g_val[e] > THRF) {
        int j = g_idx[e];
        int p = atomicAdd(&g_ccnt[j], 1);
        g_csrc[g_coff[j] + p] = e / KNNN;
    }
}

// ---------------- 6. GCN layer 1 (gather) ----------
__global__ __launch_bounds__(HIDN) void k_gather1(const float* __restrict__ b1) {
    int j = blockIdx.x, f = threadIdx.x;
    float dj = g_dinv[j];
    float s = dj * g_xw1[j * HIDN + f];
    int e0 = g_coff[j], e1 = g_coff[j + 1];
    for (int e = e0; e < e1; e++) {
        int i = g_csrc[e];
        s += g_dinv[i] * g_xw1[i * HIDN + f];
    }
    g_acc[j * HIDN + f] = fmaxf(dj * s + b1[f], 0.0f);
}

// ---------------- 7. t1 = h @ W2  (8 rows/block, W2 in smem) ---------------
__global__ __launch_bounds__(256) void k_hw2(const float* __restrict__ W2) {
    __shared__ float sW[HIDN * KMN];     // 51200 B
    __shared__ float sh[8][HIDN];        // 8192 B
    int t = threadIdx.x;
    int r0 = blockIdx.x * 8;
    for (int i = t; i < HIDN * KMN; i += 256) sW[i] = W2[i];
#pragma unroll
    for (int rr = 0; rr < 8; rr++)
        sh[rr][t] = g_acc[(r0 + rr) * HIDN + t];
    __syncthreads();
    for (int p = t; p < 8 * KMN; p += 256) {
        int rr = p / KMN, c = p % KMN;
        float s = 0.f;
#pragma unroll 8
        for (int k = 0; k < HIDN; k++) s += sh[rr][k] * sW[k * KMN + c];
        g_t1[(r0 + rr) * KMN + c] = s;
    }
}

// ---------------- 8. GCN layer 2 (gather) + softmax -> S ----------------
__global__ __launch_bounds__(64) void k_g2soft(const float* __restrict__ b2,
                                               float* __restrict__ S) {
    int j = blockIdx.x, t = threadIdx.x;
    float dj = g_dinv[j];
    float s = (t < KMN) ? dj * g_t1[j * KMN + t] : 0.f;
    int e0 = g_coff[j], e1 = g_coff[j + 1];
    for (int e = e0; e < e1; e++) {
        int i = g_csrc[e];
        if (t < KMN) s += g_dinv[i] * g_t1[i * KMN + t];
    }
    float v = (t < KMN) ? dj * s + b2[t] : -FLT_MAX;
    __shared__ float red[64];
    red[t] = v;
#pragma unroll
    for (int o = 32; o > 0; o >>= 1) {
        __syncthreads();
        if (t < o) red[t] = fmaxf(red[t], red[t + o]);
    }
    __syncthreads();
    float mx = red[0];
    __syncthreads();
    float e2 = (t < KMN) ? expf(v - mx) : 0.f;
    red[t] = e2;
#pragma unroll
    for (int o = 32; o > 0; o >>= 1) {
        __syncthreads();
        if (t < o) red[t] += red[t + o];
    }
    __syncthreads();
    float inv = 1.0f / red[0];
    if (t < KMN) S[j * KMN + t] = e2 * inv;
}

// ---------------- 9. t2 = adj @ S (sparse) ----------------
__global__ __launch_bounds__(64) void k_adjS(const float* __restrict__ S) {
    int i = blockIdx.x, t = threadIdx.x;
    __shared__ int   sj[KNNN];
    __shared__ float sw[KNNN];
    if (t < KNNN) { sj[t] = g_idx[i * KNNN + t]; sw[t] = g_val[i * KNNN + t]; }
    __syncthreads();
    if (t < KMN) {
        float a = 0.f;
#pragma unroll
        for (int k = 0; k < KNNN; k++) a += sw[k] * S[sj[k] * KMN + t];
        g_t2[i * KMN + t] = a;
    }
}

// ---------------- 10. A_coarse = S^T @ t2 (8 rows/step) ----------------
__global__ __launch_bounds__(256) void k_Ac(const float* __restrict__ S) {
    int t = threadIdx.x;
    int r0 = blockIdx.x * 128;
    __shared__ float sS8[8][52], sT8[8][52];
    float acc[10];
    int c1[10], c2[10]; bool ok[10];
#pragma unroll
    for (int p = 0; p < 10; p++) {
        int e = t + p * 256;
        ok[p] = (e < KMN * KMN);
        c1[p] = ok[p] ? e / KMN : 0;
        c2[p] = ok[p] ? e % KMN : 0;
        acc[p] = 0.f;
    }
    for (int s0 = 0; s0 < 128; s0 += 8) {
        for (int p = t; p < 8 * KMN; p += 256) {
            int rr = p / KMN, c = p % KMN;
            int i = r0 + s0 + rr;
            sS8[rr][c] = S[i * KMN + c];
            sT8[rr][c] = g_t2[i * KMN + c];
        }
        __syncthreads();
#pragma unroll
        for (int p = 0; p < 10; p++)
            if (ok[p]) {
#pragma unroll
                for (int r = 0; r < 8; r++)
                    acc[p] += sS8[r][c1[p]] * sT8[r][c2[p]];
            }
        __syncthreads();
    }
#pragma unroll
    for (int p = 0; p < 10; p++)
        if (ok[p]) atomicAdd(&g_Ac[t + p * 256], acc[p]);
}

// ---------------- 11. X_t = S^T @ X (8 rows/step) ----------------
__global__ __launch_bounds__(256) void k_Xt(const float* __restrict__ X,
                                            const float* __restrict__ S,
                                            float* __restrict__ outXt) {
    int t = threadIdx.x;
    int fc = blockIdx.x * 128;
    int r0 = blockIdx.y * 128;
    int f = t & 127, ch = t >> 7;
    __shared__ float sS8[8][52];
    __shared__ float sX8[8][128];
    float acc[25];
#pragma unroll
    for (int c = 0; c < 25; c++) acc[c] = 0.f;
    int lr = t >> 5, lc4 = (t & 31) * 4;
    for (int s0 = 0; s0 < 128; s0 += 8) {
        *(float4*)&sX8[lr][lc4] =
            *(const float4*)(X + (size_t)(r0 + s0 + lr) * FEATN + fc + lc4);
        for (int p = t; p < 8 * KMN; p += 256) {
            int rr = p / KMN, c = p % KMN;
            sS8[rr][c] = S[(r0 + s0 + rr) * KMN + c];
        }
        __syncthreads();
#pragma unroll
        for (int r = 0; r < 8; r++) {
            float xv = sX8[r][f];
#pragma unroll
            for (int c = 0; c < 25; c++) acc[c] += sS8[r][ch * 25 + c] * xv;
        }
        __syncthreads();
    }
#pragma unroll
    for (int c = 0; c < 25; c++)
        atomicAdd(&outXt[(ch * 25 + c) * FEATN + fc + f], acc[c]);
}

// ---------------- 12. spatial loss ----------------
__global__ __launch_bounds__(256) void k_loss(const float* __restrict__ S,
                                              const float* __restrict__ pos) {
    int warp = (blockIdx.x * 256 + threadIdx.x) >> 5;
    int lane = threadIdx.x & 31;
    if (warp >= NN) return;
    int i = warp;
    float s0 = (lane < KMN) ? S[i * KMN + lane] : 0.f;
    bool has2 = (lane + 32 < KMN);
    float s1 = has2 ? S[i * KMN + lane + 32] : 0.f;
    float xi = pos[2 * i], yi = pos[2 * i + 1];
    float p2i = xi * xi + yi * yi;
    float lsum = 0.f; int cnt = 0;
#pragma unroll
    for (int k = 0; k < KNNN; k++) {
        float v = g_val[i * KNNN + k];
        if (v > THRF) {
            int j = g_idx[i * KNNN + k];
            float xj = pos[2 * j], yj = pos[2 * j + 1];
            float d2 = fmaxf(p2i + xj * xj + yj * yj -
                             2.0f * (xi * xj + yi * yj), 0.0f);
            float dp = s0 * ((lane < KMN) ? S[j * KMN + lane] : 0.f);
            if (has2) dp += s1 * S[j * KMN + lane + 32];
            lsum += d2 * dp;
            cnt++;
        }
    }
#pragma unroll
    for (int o = 16; o > 0; o >>= 1) lsum += __shfl_down_sync(0xffffffffu, lsum, o);
    if (lane == 0) {
        atomicAdd(&g_loss, lsum);
        atomicAdd(&g_E, (float)cnt);
    }
}

// ---------------- zero/init + finalize ----------------
__global__ void k_zero(float* __restrict__ outXt) {
    int idx = blockIdx.x * 256 + threadIdx.x;
    if (idx < KMN * FEATN) outXt[idx] = 0.f;
    if (idx < KMN * KMN) g_Ac[idx] = 0.f;
    if (idx < NN) { g_deg[idx] = 1.0f; g_ccnt[idx] = 0; }
    if (idx == 0) { g_loss = 0.f; g_E = 0.f; }
}
__global__ void k_final(const float* __restrict__ psw,
                        const float* __restrict__ plam,
                        float* __restrict__ out) {
    int idx = blockIdx.x * 256 + threadIdx.x;
    const int offA = NN * KMN + KMN * FEATN;
    if (idx < KMN * KMN) {
        float a = g_Ac[idx];
        out[offA + idx] = (a > THRF) ? a : 0.f;
    }
    if (idx == 0) {
        out[offA + KMN * KMN] = psw[0] * g_loss / g_E;
        out[offA + KMN * KMN + 1] = 1.0f / (1.0f + expf(-plam[0]));
    }
}

// ---------------- launcher ----------------
extern "C" void kernel_launch(void* const* d_in, const int* in_sizes, int n_in,
                              void* d_out, int out_size) {
    const float* X    = (const float*)d_in[0];
    const float* pos  = (const float*)d_in[1];
    const float* lamw = (const float*)d_in[2];
    const float* temp = (const float*)d_in[3];
    const float* sw   = (const float*)d_in[4];
    const float* W1   = (const float*)d_in[5];
    const float* b1   = (const float*)d_in[6];
    const float* W2   = (const float*)d_in[7];
    const float* b2   = (const float*)d_in[8];
    float* out  = (float*)d_out;
    float* S    = out;              // [N, K]
    float* oXt  = out + NN * KMN;   // [K, FEAT]

    const int SMEM_SIM = 2 * BUFB;   // 110592
    const int SMEM_XW1 = 2 * BUF4;   // 147456
    static int s_attr_done = 0;
    if (!s_attr_done) {
        cudaFuncSetAttribute(k_sim_mma, cudaFuncAttributeMaxDynamicSharedMemorySize,
                             SMEM_SIM);
        cudaFuncSetAttribute(k_xw1_mma, cudaFuncAttributeMaxDynamicSharedMemorySize,
                             SMEM_XW1);
        s_attr_done = 1;
    }

    k_prep<<<NN, 128>>>(X, W1);
    k_xw1_mma<<<dim3(HIDN / 128, NN / 128), 256, SMEM_XW1>>>();
    k_sim_mma<<<NTRI, 256, SMEM_SIM>>>(pos, lamw, temp);
    k_topk<<<NN, 256>>>();
    k_zero<<<(KMN * FEATN + 255) / 256, 256>>>(oXt);
    k_deg_scatter<<<(NN * KNNN + 255) / 256, 256>>>();
    k_scan<<<1, 256>>>();
    k_fill<<<(NN * KNNN + 255) / 256, 256>>>();
    k_gather1<<<NN, HIDN>>>(b1);
    k_hw2<<<NN / 8, 256>>>(W2);
    k_g2soft<<<NN, 64>>>(b2, S);
    k_adjS<<<NN, 64>>>(S);
    k_Ac<<<NN / 128, 256>>>(S);
    k_Xt<<<dim3(FEATN / 128, NN / 128), 256>>>(X, S, oXt);
    k_loss<<<NN / 8, 256>>>(S, pos);
    k_final<<<(KMN * KMN + 255) / 256, 256>>>(sw, lamw, out);
}

// round 17
// speedup vs baseline: 3.7323x; 1.1791x over previous
#include <cuda_runtime.h>
#include <cuda_fp16.h>
#include <math.h>
#include <float.h>
#include <stdint.h>

// Problem constants
#define NN    6144
#define FEATN 512
#define HIDN  256
#define KMN   50
#define KNNN  20
#define THRF  0.1f
#define INV2SD2 (1.0f/5000.0f)
#define CAPC  128
#define SSTR  72        // smem row stride in fp16 (144B) -> conflict-free
#define TILEB (128*SSTR*2)            // 18432 B per tile
#define BUFB  (3*TILEB)               // sim buffer (Ahi,Alo,Bhi)
#define BUF4  (4*TILEB)               // xw1 buffer (Ahi,Alo,Bhi,Blo)
#define NTILE (NN/128)                // 48
#define NTRI  (NTILE*(NTILE+1)/2)     // 1176

// ---------------- device scratch ----------------
__device__ __half g_fhi[NN * FEATN];
__device__ __half g_flo[NN * FEATN];
__device__ __half g_xhi[NN * FEATN];
__device__ __half g_xlo[NN * FEATN];
__device__ __half g_w1hi[HIDN * FEATN];  // W1^T hi  [n][k]
__device__ __half g_w1lo[HIDN * FEATN];  // W1^T lo
__device__ float g_adj[(size_t)NN * NN];
__device__ float g_xw1[NN * HIDN];
__device__ float g_acc[NN * HIDN];
__device__ float g_t1[NN * KMN];
__device__ float g_t2[NN * KMN];
__device__ float g_deg[NN];
__device__ float g_dinv[NN];
__device__ int   g_idx[NN * KNNN];
__device__ float g_val[NN * KNNN];
__device__ float g_Ac[KMN * KMN];
__device__ float g_loss;
__device__ float g_E;
__device__ int   g_coff[NN + 1];
__device__ int   g_ccnt[NN];
__device__ int   g_csrc[NN * KNNN];

// ---------------- PTX helpers (baseline ISA, valid on compute_103) -----
__device__ __forceinline__ void mma16816(float* d, const uint32_t* a,
                                         const uint32_t* b) {
    asm volatile(
        "mma.sync.aligned.m16n8k16.row.col.f32.f16.f16.f32 "
        "{%0,%1,%2,%3}, {%4,%5,%6,%7}, {%8,%9}, {%0,%1,%2,%3};"
        : "+f"(d[0]), "+f"(d[1]), "+f"(d[2]), "+f"(d[3])
        : "r"(a[0]), "r"(a[1]), "r"(a[2]), "r"(a[3]), "r"(b[0]), "r"(b[1]));
}
__device__ __forceinline__ uint32_t smem_u32(const void* p) {
    uint32_t a;
    asm("{ .reg .u64 t; cvta.to.shared.u64 t, %1; cvt.u32.u64 %0, t; }"
        : "=r"(a) : "l"(p));
    return a;
}
#define LDMX4(r, addr) asm volatile( \
    "ldmatrix.sync.aligned.m8n8.x4.shared.b16 {%0,%1,%2,%3}, [%4];" \
    : "=r"((r)[0]), "=r"((r)[1]), "=r"((r)[2]), "=r"((r)[3]) : "r"(addr))
#define CP16(saddr, gptr) asm volatile( \
    "cp.async.cg.shared.global [%0], [%1], 16;" :: "r"(saddr), "l"(gptr))
#define CP_COMMIT() asm volatile("cp.async.commit_group;" ::: "memory")

// ---------------- 1. normalize + fp16 splits + fused W1^T split -------
__global__ __launch_bounds__(128) void k_prep(const float* __restrict__ X,
                                              const float* __restrict__ W1) {
    int row = blockIdx.x, t = threadIdx.x;
    const float* xr = X + row * FEATN;
    float ss = 0.f;
    for (int f = t; f < FEATN; f += 128) { float v = xr[f]; ss += v * v; }
    for (int o = 16; o > 0; o >>= 1) ss += __shfl_down_sync(0xffffffffu, ss, o);
    __shared__ float red[4];
    __shared__ float sinv;
    if ((t & 31) == 0) red[t >> 5] = ss;
    __syncthreads();
    if (t == 0) {
        float s = red[0] + red[1] + red[2] + red[3];
        sinv = 1.0f / fmaxf(sqrtf(s), 1e-12f);
    }
    __syncthreads();
    float inv = sinv;
    for (int f = t; f < FEATN; f += 128) {
        float xv = xr[f];
        __half xh = __float2half_rn(xv);
        g_xhi[row * FEATN + f] = xh;
        g_xlo[row * FEATN + f] = __float2half_rn(xv - __half2float(xh));
        float v = xv * inv;
        __half h = __float2half_rn(v);
        g_fhi[row * FEATN + f] = h;
        g_flo[row * FEATN + f] = __float2half_rn(v - __half2float(h));
    }
    if (row < FEATN) {
        for (int n = t; n < HIDN; n += 128) {
            float v = W1[row * HIDN + n];
            __half h = __float2half_rn(v);
            g_w1hi[n * FEATN + row] = h;
            g_w1lo[n * FEATN + row] = __float2half_rn(v - __half2float(h));
        }
    }
}

// ---------------- 2. XW1 = X @ W1 via fp16 hi/lo mma (3 terms) -------------
__global__ __launch_bounds__(256) void k_xw1_mma() {
    extern __shared__ char dyn[];
    int t = threadIdx.x, w = t >> 5, lane = t & 31;
    int bi = blockIdx.y * 128, bj = blockIdx.x * 128;
    int wm = w & 3, wn = w >> 2;

    float acc[2][8][4];
#pragma unroll
    for (int mi = 0; mi < 2; mi++)
#pragma unroll
        for (int ni = 0; ni < 8; ni++)
#pragma unroll
            for (int r = 0; r < 4; r++) acc[mi][ni][r] = 0.f;

    uint32_t dynb = smem_u32(dyn);
    int lrow = t >> 1;
    int lch = (t & 1) * 4;

    const __half* Ah0 = g_xhi + (size_t)(bi + lrow) * FEATN;
    const __half* Al0 = g_xlo + (size_t)(bi + lrow) * FEATN;
    const __half* Bh0 = g_w1hi + (size_t)(bj + lrow) * FEATN;
    const __half* Bl0 = g_w1lo + (size_t)(bj + lrow) * FEATN;

    auto issue = [&](int c, int buf) {
        int kc = c * 64;
        uint32_t sb = dynb + buf * BUF4 + lrow * (SSTR * 2);
#pragma unroll
        for (int j = 0; j < 4; j++) {
            int ch = lch + j;
            uint32_t off = sb + ch * 16;
            CP16(off,             Ah0 + kc + ch * 8);
            CP16(off + TILEB,     Al0 + kc + ch * 8);
            CP16(off + 2 * TILEB, Bh0 + kc + ch * 8);
            CP16(off + 3 * TILEB, Bl0 + kc + ch * 8);
        }
        CP_COMMIT();
    };

    issue(0, 0);
#pragma unroll 1
    for (int c = 0; c < 8; c++) {
        if (c < 7) {
            issue(c + 1, (c + 1) & 1);
            asm volatile("cp.async.wait_group 1;" ::: "memory");
        } else {
            asm volatile("cp.async.wait_group 0;" ::: "memory");
        }
        __syncthreads();
        uint32_t tb = dynb + (c & 1) * BUF4;
        int m = lane >> 3, r8 = lane & 7;
#pragma unroll
        for (int k16 = 0; k16 < 4; k16++) {
            int kb = k16 * 16;
            uint32_t ah[2][4], al[2][4], bf[8][2];
#pragma unroll
            for (int mi = 0; mi < 2; mi++) {
                int R = wm * 32 + mi * 16;
                uint32_t aoff = ((R + (m & 1) * 8 + r8) * SSTR + kb + (m >> 1) * 8) * 2;
                LDMX4(ah[mi], tb + aoff);
                LDMX4(al[mi], tb + TILEB + aoff);
            }
#pragma unroll
            for (int p = 0; p < 4; p++) {
                int n0 = wn * 64 + p * 16;
                uint32_t boff = ((n0 + (m >> 1) * 8 + r8) * SSTR + kb + (m & 1) * 8) * 2;
                LDMX4(&bf[2 * p][0], tb + 2 * TILEB + boff);
            }
#pragma unroll
            for (int mi = 0; mi < 2; mi++)
#pragma unroll
                for (int ni = 0; ni < 8; ni++) {
                    mma16816(acc[mi][ni], ah[mi], bf[ni]);   // hi.hi
                    mma16816(acc[mi][ni], al[mi], bf[ni]);   // lo.hi
                }
#pragma unroll
            for (int p = 0; p < 4; p++) {
                int n0 = wn * 64 + p * 16;
                uint32_t boff = ((n0 + (m >> 1) * 8 + r8) * SSTR + kb + (m & 1) * 8) * 2;
                LDMX4(&bf[2 * p][0], tb + 3 * TILEB + boff);
            }
#pragma unroll
            for (int mi = 0; mi < 2; mi++)
#pragma unroll
                for (int ni = 0; ni < 8; ni++)
                    mma16816(acc[mi][ni], ah[mi], bf[ni]);   // hi.lo
        }
        __syncthreads();
    }

#pragma unroll
    for (int mi = 0; mi < 2; mi++)
#pragma unroll
        for (int rr = 0; rr < 2; rr++) {
            int r = wm * 32 + mi * 16 + rr * 8 + (lane >> 2);
            int go = (bi + r) * HIDN + bj;
#pragma unroll
            for (int ni = 0; ni < 8; ni++) {
                int c = wn * 64 + ni * 8 + (lane & 3) * 2;
                float2 o;
                o.x = acc[mi][ni][rr * 2 + 0];
                o.y = acc[mi][ni][rr * 2 + 1];
                *(float2*)&g_xw1[go + c] = o;
            }
        }
}

// ---------------- 3. sim: fp16 hi/lo mma, triangular 1D grid ----------
__global__ __launch_bounds__(256, 2) void k_sim_mma(const float* __restrict__ pos,
                                                    const float* __restrict__ plam,
                                                    const float* __restrict__ ptemp) {
    int e = blockIdx.x;
    int by = (int)((97.0f - sqrtf(9409.0f - 8.0f * (float)e)) * 0.5f);
    while ((by + 1) * NTILE - ((by + 1) * by) / 2 <= e) by++;
    while (by * NTILE - (by * (by - 1)) / 2 > e) by--;
    int bx = by + (e - (by * NTILE - (by * (by - 1)) / 2));

    extern __shared__ char dyn[];
    __shared__ float cpx[128], cpy[128], rpx[128], rpy[128];

    int t = threadIdx.x, w = t >> 5, lane = t & 31;
    int bi = by * 128, bj = bx * 128;
    bool offdiag = (bx != by);
    int wm = w & 3, wn = w >> 2;

    if (t < 128) {
        cpx[t] = pos[2 * (bj + t)];
        cpy[t] = pos[2 * (bj + t) + 1];
    } else {
        int u = t - 128;
        rpx[u] = pos[2 * (bi + u)];
        rpy[u] = pos[2 * (bi + u) + 1];
    }

    float acc[2][8][4];
#pragma unroll
    for (int mi = 0; mi < 2; mi++)
#pragma unroll
        for (int ni = 0; ni < 8; ni++)
#pragma unroll
            for (int r = 0; r < 4; r++) acc[mi][ni][r] = 0.f;

    uint32_t dynb = smem_u32(dyn);
    int lrow = t >> 1;
    int lch = (t & 1) * 4;

    const __half* Ah0 = g_fhi + (size_t)(bi + lrow) * FEATN;
    const __half* Al0 = g_flo + (size_t)(bi + lrow) * FEATN;
    const __half* Bh0 = g_fhi + (size_t)(bj + lrow) * FEATN;

    auto issue = [&](int c, int buf) {
        int kc = c * 64;
        uint32_t sb = dynb + buf * BUFB + lrow * (SSTR * 2);
#pragma unroll
        for (int j = 0; j < 4; j++) {
            int ch = lch + j;
            uint32_t off = sb + ch * 16;
            CP16(off,             Ah0 + kc + ch * 8);
            CP16(off + TILEB,     Al0 + kc + ch * 8);
            CP16(off + 2 * TILEB, Bh0 + kc + ch * 8);
        }
        CP_COMMIT();
    };

    issue(0, 0);
#pragma unroll 1
    for (int c = 0; c < 8; c++) {
        if (c < 7) {
            issue(c + 1, (c + 1) & 1);
            asm volatile("cp.async.wait_group 1;" ::: "memory");
        } else {
            asm volatile("cp.async.wait_group 0;" ::: "memory");
        }
        __syncthreads();
        uint32_t tb = dynb + (c & 1) * BUFB;
        int m = lane >> 3, r8 = lane & 7;
#pragma unroll
        for (int k16 = 0; k16 < 4; k16++) {
            int kb = k16 * 16;
            uint32_t ah[2][4], al[2][4], bf[8][2];
#pragma unroll
            for (int mi = 0; mi < 2; mi++) {
                int R = wm * 32 + mi * 16;
                uint32_t aoff = ((R + (m & 1) * 8 + r8) * SSTR + kb + (m >> 1) * 8) * 2;
                LDMX4(ah[mi], tb + aoff);
                LDMX4(al[mi], tb + TILEB + aoff);
            }
#pragma unroll
            for (int p = 0; p < 4; p++) {
                int n0 = wn * 64 + p * 16;
                uint32_t boff = ((n0 + (m >> 1) * 8 + r8) * SSTR + kb + (m & 1) * 8) * 2;
                LDMX4(&bf[2 * p][0], tb + 2 * TILEB + boff);
            }
#pragma unroll
            for (int mi = 0; mi < 2; mi++)
#pragma unroll
                for (int ni = 0; ni < 8; ni++) {
                    mma16816(acc[mi][ni], ah[mi], bf[ni]);   // hi.hi
                    mma16816(acc[mi][ni], al[mi], bf[ni]);   // lo.hi
                }
        }
        __syncthreads();
    }

    float lam = 1.0f / (1.0f + expf(-plam[0]));
    float T = ptemp[0];
    float aC = lam * T, bC = (1.0f - lam) * T;
    float* stage = (float*)dyn;             // 128 x (stride 132) floats
#pragma unroll
    for (int mi = 0; mi < 2; mi++) {
#pragma unroll
        for (int rr = 0; rr < 2; rr++) {
            int r = wm * 32 + mi * 16 + rr * 8 + (lane >> 2);
            float xi = rpx[r], yi = rpy[r];
            float p2i = xi * xi + yi * yi;
            size_t gro = (size_t)(bi + r) * NN + bj;
#pragma unroll
            for (int ni = 0; ni < 8; ni++) {
                int c = wn * 64 + ni * 8 + (lane & 3) * 2;
                float xj0 = cpx[c], yj0 = cpy[c];
                float xj1 = cpx[c + 1], yj1 = cpy[c + 1];
                float d20 = fmaxf(p2i + xj0 * xj0 + yj0 * yj0 -
                                  2.0f * (xi * xj0 + yi * yj0), 0.0f);
                float d21 = fmaxf(p2i + xj1 * xj1 + yj1 * yj1 -
                                  2.0f * (xi * xj1 + yi * yj1), 0.0f);
                float2 o;
                o.x = aC * acc[mi][ni][rr * 2 + 0] + bC * __expf(-d20 * INV2SD2);
                o.y = aC * acc[mi][ni][rr * 2 + 1] + bC * __expf(-d21 * INV2SD2);
                *(float2*)&g_adj[gro + c] = o;
                if (offdiag) {
                    stage[c * 132 + r] = o.x;
                    stage[(c + 1) * 132 + r] = o.y;
                }
            }
        }
    }
    if (offdiag) {
        __syncthreads();
#pragma unroll
        for (int j = 0; j < 16; j++) {
            int idx4 = t + j * 256;
            int cc = idx4 >> 5, r4 = (idx4 & 31) * 4;
            float4 v = *(float4*)&stage[cc * 132 + r4];
            *(float4*)&g_adj[(size_t)(bj + cc) * NN + bi + r4] = v;
        }
    }
}

// ---------------- 4. row-wise exact top-20 (128 thr, float-domain) ----
__global__ __launch_bounds__(128) void k_topk() {
    int row = blockIdx.x, t = threadIdx.x;
    const float4* r4 = (const float4*)(g_adj + (size_t)row * NN);

    float key[48];
#pragma unroll
    for (int kk = 0; kk < 12; kk++) {
        float4 v = r4[t + kk * 128];
        key[kk * 4 + 0] = v.x; key[kk * 4 + 1] = v.y;
        key[kk * 4 + 2] = v.z; key[kk * 4 + 3] = v.w;
    }

    __shared__ int scnt[4];
    __shared__ float smm[8];

    float kmin = key[0], kmax = key[0];
#pragma unroll
    for (int k = 1; k < 48; k++) {
        kmin = fminf(kmin, key[k]);
        kmax = fmaxf(kmax, key[k]);
    }
    for (int o = 16; o > 0; o >>= 1) {
        kmin = fminf(kmin, __shfl_down_sync(0xffffffffu, kmin, o));
        kmax = fmaxf(kmax, __shfl_down_sync(0xffffffffu, kmax, o));
    }
    if ((t & 31) == 0) { smm[t >> 5] = kmin; smm[4 + (t >> 5)] = kmax; }
    __syncthreads();
    float lo = fminf(fminf(smm[0], smm[1]), fminf(smm[2], smm[3]));
    float hi = fmaxf(fmaxf(smm[4], smm[5]), fmaxf(smm[6], smm[7]));
    __syncthreads();

    for (int it = 0; it < 40; it++) {
        float mid = 0.5f * (lo + hi);
        if (mid == lo || mid == hi) break;
        int c = 0;
#pragma unroll
        for (int k = 0; k < 48; k++) c += (key[k] >= mid) ? 1 : 0;
        for (int o = 16; o > 0; o >>= 1) c += __shfl_down_sync(0xffffffffu, c, o);
        if ((t & 31) == 0) scnt[t >> 5] = c;
        __syncthreads();
        int tot = scnt[0] + scnt[1] + scnt[2] + scnt[3];
        __syncthreads();
        if (tot >= 20) {
            lo = mid;
            if (tot <= 96) break;
        } else {
            hi = mid;
        }
    }

    __shared__ unsigned long long cand[CAPC];
    __shared__ int cnum;
    cand[t] = 0ull;
    if (t == 0) cnum = 0;
    __syncthreads();
#pragma unroll
    for (int k = 0; k < 48; k++) {
        if (key[k] >= lo) {
            unsigned b = __float_as_uint(key[k]);
            unsigned mk = (b & 0x80000000u) ? ~b : (b | 0x80000000u);
            int gidx = ((t + (k >> 2) * 128) << 2) + (k & 3);
            int p = atomicAdd(&cnum, 1);
            if (p < CAPC)
                cand[p] = ((unsigned long long)mk << 32) | (unsigned)(~gidx);
        }
    }
    __syncthreads();

    if (t < 32) {
        for (int it = 0; it < KNNN; it++) {
            unsigned long long best = 0ull;
            int bslot = 0;
#pragma unroll
            for (int s = 0; s < CAPC / 32; s++) {
                unsigned long long c = cand[t + s * 32];
                if (c > best) { best = c; bslot = t + s * 32; }
            }
#pragma unroll
            for (int o = 16; o > 0; o >>= 1) {
                unsigned long long b2 = __shfl_down_sync(0xffffffffu, best, o);
                int s2 = __shfl_down_sync(0xffffffffu, bslot, o);
                if (b2 > best) { best = b2; bslot = s2; }
            }
            bslot = __shfl_sync(0xffffffffu, bslot, 0);
            if (t == 0) {
                unsigned kk = (unsigned)(best >> 32);
                unsigned fb = (kk & 0x80000000u) ? (kk & 0x7fffffffu) : ~kk;
                float raw = __uint_as_float(fb);
                g_val[row * KNNN + it] = 1.0f / (1.0f + expf(-raw));
                g_idx[row * KNNN + it] = (int)(~(unsigned)(best & 0xffffffffu));
                cand[bslot] = 0ull;
            }
            __syncwarp();
        }
    }
}

// ---------------- 5. degrees + CSC build ----------------
__global__ void k_deg_scatter() {
    int e = blockIdx.x * 256 + threadIdx.x;
    if (e < NN * KNNN) {
        if (g_val[e] > THRF) atomicAdd(&g_deg[g_idx[e]], 1.0f);
    }
}
__global__ __launch_bounds__(256) void k_scan() {   // + fused dinv
    __shared__ int part[256];
    int t = threadIdx.x;
    int base = t * 24;
    int loc[24];
    int s = 0;
#pragma unroll
    for (int u = 0; u < 24; u++) {
        float d = g_deg[base + u];
        g_dinv[base + u] = rsqrtf(d);
        loc[u] = s;
        s += (int)d - 1;
    }
    part[t] = s;
    __syncthreads();
    for (int o = 1; o < 256; o <<= 1) {
        int v = (t >= o) ? part[t - o] : 0;
        __syncthreads();
        part[t] += v;
        __syncthreads();
    }
    int pre = (t == 0) ? 0 : part[t - 1];
#pragma unroll
    for (int u = 0; u < 24; u++) g_coff[base + u] = pre + loc[u];
    if (t == 255) g_coff[NN] = part[255];
}
__global__ void k_fill() {
    int e = blockIdx.x * 256 + threadIdx.x;
    if (e < NN * KNNN && g_val[e] > THRF) {
        int j = g_idx[e];
        int p = atomicAdd(&g_ccnt[j], 1);
        g_csrc[g_coff[j] + p] = e / KNNN;
    }
}

// ---------------- 6. GCN layer 1 (gather) ----------
__global__ __launch_bounds__(HIDN) void k_gather1(const float* __restrict__ b1) {
    int j = blockIdx.x, f = threadIdx.x;
    float dj = g_dinv[j];
    float s = dj * g_xw1[j * HIDN + f];
    int e0 = g_coff[j], e1 = g_coff[j + 1];
    for (int e = e0; e < e1; e++) {
        int i = g_csrc[e];
        s += g_dinv[i] * g_xw1[i * HIDN + f];
    }
    g_acc[j * HIDN + f] = fmaxf(dj * s + b1[f], 0.0f);
}

// ---------------- 7. t1 = h @ W2  (8 rows/block, W2 in smem) ---------------
__global__ __launch_bounds__(256) void k_hw2(const float* __restrict__ W2) {
    __shared__ float sW[HIDN * KMN];
    __shared__ float sh[8][HIDN];
    int t = threadIdx.x;
    int r0 = blockIdx.x * 8;
    for (int i = t; i < HIDN * KMN; i += 256) sW[i] = W2[i];
#pragma unroll
    for (int rr = 0; rr < 8; rr++)
        sh[rr][t] = g_acc[(r0 + rr) * HIDN + t];
    __syncthreads();
    for (int p = t; p < 8 * KMN; p += 256) {
        int rr = p / KMN, c = p % KMN;
        float s = 0.f;
#pragma unroll 8
        for (int k = 0; k < HIDN; k++) s += sh[rr][k] * sW[k * KMN + c];
        g_t1[(r0 + rr) * KMN + c] = s;
    }
}

// ---------------- 8. GCN layer 2 (gather) + softmax -> S ----------------
__global__ __launch_bounds__(64) void k_g2soft(const float* __restrict__ b2,
                                               float* __restrict__ S) {
    int j = blockIdx.x, t = threadIdx.x;
    float dj = g_dinv[j];
    float s = (t < KMN) ? dj * g_t1[j * KMN + t] : 0.f;
    int e0 = g_coff[j], e1 = g_coff[j + 1];
    for (int e = e0; e < e1; e++) {
        int i = g_csrc[e];
        if (t < KMN) s += g_dinv[i] * g_t1[i * KMN + t];
    }
    float v = (t < KMN) ? dj * s + b2[t] : -FLT_MAX;
    __shared__ float red[64];
    red[t] = v;
#pragma unroll
    for (int o = 32; o > 0; o >>= 1) {
        __syncthreads();
        if (t < o) red[t] = fmaxf(red[t], red[t + o]);
    }
    __syncthreads();
    float mx = red[0];
    __syncthreads();
    float e2 = (t < KMN) ? expf(v - mx) : 0.f;
    red[t] = e2;
#pragma unroll
    for (int o = 32; o > 0; o >>= 1) {
        __syncthreads();
        if (t < o) red[t] += red[t + o];
    }
    __syncthreads();
    float inv = 1.0f / red[0];
    if (t < KMN) S[j * KMN + t] = e2 * inv;
}

// ---------------- 9. t2 = adj @ S (sparse) ----------------
__global__ __launch_bounds__(64) void k_adjS(const float* __restrict__ S) {
    int i = blockIdx.x, t = threadIdx.x;
    __shared__ int   sj[KNNN];
    __shared__ float sw[KNNN];
    if (t < KNNN) { sj[t] = g_idx[i * KNNN + t]; sw[t] = g_val[i * KNNN + t]; }
    __syncthreads();
    if (t < KMN) {
        float a = 0.f;
#pragma unroll
        for (int k = 0; k < KNNN; k++) a += sw[k] * S[sj[k] * KMN + t];
        g_t2[i * KMN + t] = a;
    }
}

// ---------------- 10. A_coarse = S^T @ t2 (8 rows/step) ----------------
__global__ __launch_bounds__(256) void k_Ac(const float* __restrict__ S) {
    int t = threadIdx.x;
    int r0 = blockIdx.x * 128;
    __shared__ float sS8[8][52], sT8[8][52];
    float acc[10];
    int c1[10], c2[10]; bool ok[10];
#pragma unroll
    for (int p = 0; p < 10; p++) {
        int e = t + p * 256;
        ok[p] = (e < KMN * KMN);
        c1[p] = ok[p] ? e / KMN : 0;
        c2[p] = ok[p] ? e % KMN : 0;
        acc[p] = 0.f;
    }
    for (int s0 = 0; s0 < 128; s0 += 8) {
        for (int p = t; p < 8 * KMN; p += 256) {
            int rr = p / KMN, c = p % KMN;
            int i = r0 + s0 + rr;
            sS8[rr][c] = S[i * KMN + c];
            sT8[rr][c] = g_t2[i * KMN + c];
        }
        __syncthreads();
#pragma unroll
        for (int p = 0; p < 10; p++)
            if (ok[p]) {
#pragma unroll
                for (int r = 0; r < 8; r++)
                    acc[p] += sS8[r][c1[p]] * sT8[r][c2[p]];
            }
        __syncthreads();
    }
#pragma unroll
    for (int p = 0; p < 10; p++)
        if (ok[p]) atomicAdd(&g_Ac[t + p * 256], acc[p]);
}

// ---------------- 11. X_t = S^T @ X (8 rows/step) ----------------
__global__ __launch_bounds__(256) void k_Xt(const float* __restrict__ X,
                                            const float* __restrict__ S,
                                            float* __restrict__ outXt) {
    int t = threadIdx.x;
    int fc = blockIdx.x * 128;
    int r0 = blockIdx.y * 128;
    int f = t & 127, ch = t >> 7;
    __shared__ float sS8[8][52];
    __shared__ float sX8[8][128];
    float acc[25];
#pragma unroll
    for (int c = 0; c < 25; c++) acc[c] = 0.f;
    int lr = t >> 5, lc4 = (t & 31) * 4;
    for (int s0 = 0; s0 < 128; s0 += 8) {
        *(float4*)&sX8[lr][lc4] =
            *(const float4*)(X + (size_t)(r0 + s0 + lr) * FEATN + fc + lc4);
        for (int p = t; p < 8 * KMN; p += 256) {
            int rr = p / KMN, c = p % KMN;
            sS8[rr][c] = S[(r0 + s0 + rr) * KMN + c];
        }
        __syncthreads();
#pragma unroll
        for (int r = 0; r < 8; r++) {
            float xv = sX8[r][f];
#pragma unroll
            for (int c = 0; c < 25; c++) acc[c] += sS8[r][ch * 25 + c] * xv;
        }
        __syncthreads();
    }
#pragma unroll
    for (int c = 0; c < 25; c++)
        atomicAdd(&outXt[(ch * 25 + c) * FEATN + fc + f], acc[c]);
}

// ---------------- 12. spatial loss ----------------
__global__ __launch_bounds__(256) void k_loss(const float* __restrict__ S,
                                              const float* __restrict__ pos) {
    int warp = (blockIdx.x * 256 + threadIdx.x) >> 5;
    int lane = threadIdx.x & 31;
    if (warp >= NN) return;
    int i = warp;
    float s0 = (lane < KMN) ? S[i * KMN + lane] : 0.f;
    bool has2 = (lane + 32 < KMN);
    float s1 = has2 ? S[i * KMN + lane + 32] : 0.f;
    float xi = pos[2 * i], yi = pos[2 * i + 1];
    float p2i = xi * xi + yi * yi;
    float lsum = 0.f; int cnt = 0;
#pragma unroll
    for (int k = 0; k < KNNN; k++) {
        float v = g_val[i * KNNN + k];
        if (v > THRF) {
            int j = g_idx[i * KNNN + k];
            float xj = pos[2 * j], yj = pos[2 * j + 1];
            float d2 = fmaxf(p2i + xj * xj + yj * yj -
                             2.0f * (xi * xj + yi * yj), 0.0f);
            float dp = s0 * ((lane < KMN) ? S[j * KMN + lane] : 0.f);
            if (has2) dp += s1 * S[j * KMN + lane + 32];
            lsum += d2 * dp;
            cnt++;
        }
    }
#pragma unroll
    for (int o = 16; o > 0; o >>= 1) lsum += __shfl_down_sync(0xffffffffu, lsum, o);
    if (lane == 0) {
        atomicAdd(&g_loss, lsum);
        atomicAdd(&g_E, (float)cnt);
    }
}

// ---------------- zero/init + finalize ----------------
__global__ void k_zero(float* __restrict__ outXt) {
    int idx = blockIdx.x * 256 + threadIdx.x;
    if (idx < KMN * FEATN) outXt[idx] = 0.f;
    if (idx < KMN * KMN) g_Ac[idx] = 0.f;
    if (idx < NN) { g_deg[idx] = 1.0f; g_ccnt[idx] = 0; }
    if (idx == 0) { g_loss = 0.f; g_E = 0.f; }
}
__global__ void k_final(const float* __restrict__ psw,
                        const float* __restrict__ plam,
                        float* __restrict__ out) {
    int idx = blockIdx.x * 256 + threadIdx.x;
    const int offA = NN * KMN + KMN * FEATN;
    if (idx < KMN * KMN) {
        float a = g_Ac[idx];
        out[offA + idx] = (a > THRF) ? a : 0.f;
    }
    if (idx == 0) {
        out[offA + KMN * KMN] = psw[0] * g_loss / g_E;
        out[offA + KMN * KMN + 1] = 1.0f / (1.0f + expf(-plam[0]));
    }
}

// ---------------- launcher (multi-stream fork/join, capture-legal) ---------
extern "C" void kernel_launch(void* const* d_in, const int* in_sizes, int n_in,
                              void* d_out, int out_size) {
    const float* X    = (const float*)d_in[0];
    const float* pos  = (const float*)d_in[1];
    const float* lamw = (const float*)d_in[2];
    const float* temp = (const float*)d_in[3];
    const float* sw   = (const float*)d_in[4];
    const float* W1   = (const float*)d_in[5];
    const float* b1   = (const float*)d_in[6];
    const float* W2   = (const float*)d_in[7];
    const float* b2   = (const float*)d_in[8];
    float* out  = (float*)d_out;
    float* S    = out;              // [N, K]
    float* oXt  = out + NN * KMN;   // [K, FEAT]

    const int SMEM_SIM = 2 * BUFB;   // 110592
    const int SMEM_XW1 = 2 * BUF4;   // 147456
    static int s_init = 0;
    static cudaStream_t s1, s2;
    static cudaEvent_t evP, evX, evZ, evS, evXt, evL;
    if (!s_init) {
        cudaFuncSetAttribute(k_sim_mma, cudaFuncAttributeMaxDynamicSharedMemorySize,
                             SMEM_SIM);
        cudaFuncSetAttribute(k_xw1_mma, cudaFuncAttributeMaxDynamicSharedMemorySize,
                             SMEM_XW1);
        cudaStreamCreateWithFlags(&s1, cudaStreamNonBlocking);
        cudaStreamCreateWithFlags(&s2, cudaStreamNonBlocking);
        cudaEventCreateWithFlags(&evP, cudaEventDisableTiming);
        cudaEventCreateWithFlags(&evX, cudaEventDisableTiming);
        cudaEventCreateWithFlags(&evZ, cudaEventDisableTiming);
        cudaEventCreateWithFlags(&evS, cudaEventDisableTiming);
        cudaEventCreateWithFlags(&evXt, cudaEventDisableTiming);
        cudaEventCreateWithFlags(&evL, cudaEventDisableTiming);
        s_init = 1;
    }

    // main stream (0): prep -> sim -> topk -> CSC -> GCN chain
    k_prep<<<NN, 128>>>(X, W1);
    cudaEventRecord(evP, 0);

    // side stream s1: zero + xw1 (hidden under sim)
    cudaStreamWaitEvent(s1, evP, 0);
    k_zero<<<(KMN * FEATN + 255) / 256, 256, 0, s1>>>(oXt);
    cudaEventRecord(evZ, s1);
    k_xw1_mma<<<dim3(HIDN / 128, NN / 128), 256, SMEM_XW1, s1>>>();
    cudaEventRecord(evX, s1);

    k_sim_mma<<<NTRI, 256, SMEM_SIM>>>(pos, lamw, temp);
    k_topk<<<NN, 128>>>();
    cudaStreamWaitEvent(0, evZ, 0);          // deg/ccnt init done
    k_deg_scatter<<<(NN * KNNN + 255) / 256, 256>>>();
    k_scan<<<1, 256>>>();
    k_fill<<<(NN * KNNN + 255) / 256, 256>>>();
    cudaStreamWaitEvent(0, evX, 0);          // xw1 ready
    k_gather1<<<NN, HIDN>>>(b1);
    k_hw2<<<NN / 8, 256>>>(W2);
    k_g2soft<<<NN, 64>>>(b2, S);
    cudaEventRecord(evS, 0);

    // S consumers in parallel
    cudaStreamWaitEvent(s1, evS, 0);
    k_Xt<<<dim3(FEATN / 128, NN / 128), 256, 0, s1>>>(X, S, oXt);
    cudaEventRecord(evXt, s1);
    cudaStreamWaitEvent(s2, evS, 0);
    k_loss<<<NN / 8, 256, 0, s2>>>(S, pos);
    cudaEventRecord(evL, s2);

    k_adjS<<<NN, 64>>>(S);
    k_Ac<<<NN / 128, 256>>>(S);
    cudaStreamWaitEvent(0, evXt, 0);
    cudaStreamWaitEvent(0, evL, 0);
    k_final<<<(KMN * KMN + 255) / 256, 256>>>(sw, lamw, out);
}